// round 1
// baseline (speedup 1.0000x reference)
#include <cuda_runtime.h>
#include <math.h>

#define NN   2048
#define DM   256
#define HH   4
#define HDM  64
#define NP1  2049
#define NORMC   (-8.317766166719343f)   /* -ln(4096) */
#define LOGN    (7.624618986159398f)    /*  ln(2048) */
#define LOG4096 (8.317766166719343f)

// ---------------- scratch (static device memory; no allocations) ----------------
__device__ float g_dA0[DM*NN];
__device__ float g_dB0[DM*NN];
__device__ float g_dA1[DM*NN];
__device__ float g_dB1[DM*NN];
__device__ float g_q  [DM*NN];
__device__ float g_k  [DM*NN];
__device__ float g_v  [DM*NN];
__device__ float g_ao [DM*NN];
__device__ float g_y  [2*DM*NN];
__device__ float g_h  [2*DM*NN];
__device__ float g_prob[(size_t)HH*NN*NN];   // 64 MB attention probs
__device__ float g_cos0[NN*32];
__device__ float g_sin0[NN*32];
__device__ float g_cos1[NN*32];
__device__ float g_sin1[NN*32];
__device__ float g_u [NP1];
__device__ float g_vv[NP1];
__device__ float g_pm[16*NP1];
__device__ float g_ps[16*NP1];

// ---------------- positional encoding ----------------
__global__ void posenc_kernel(const float* __restrict__ kpts, const float* __restrict__ Wr,
                              float* __restrict__ cosv, float* __restrict__ sinv) {
    int idx = blockIdx.x*blockDim.x + threadIdx.x;
    if (idx >= NN*32) return;
    int p = idx & 31;
    int n = idx >> 5;
    float kx = (kpts[2*n+0] - 512.0f) * (1.0f/716.8f);
    float ky = (kpts[2*n+1] - 384.0f) * (1.0f/716.8f);
    float pr = kx*Wr[2*p+0] + ky*Wr[2*p+1];
    cosv[idx] = cosf(pr);
    sinv[idx] = sinf(pr);
}

// ---------------- conv1 GEMM: out[o,n] = sum_c W[o,c] X[c,n] + bias[o] (+res) ----------------
__global__ void __launch_bounds__(256)
sgemm_bias_kernel(const float* __restrict__ W, const float* __restrict__ X,
                  const float* __restrict__ bias, const float* __restrict__ res,
                  float* __restrict__ out, int M, int K) {
    __shared__ float As[16][65];
    __shared__ float Bs[16][64];
    int tid = threadIdx.x;
    int tx = tid & 15, ty = tid >> 4;
    int n0 = blockIdx.x * 64, o0 = blockIdx.y * 64;
    int a_k = tid & 15, a_o = tid >> 4;     // 16k x 16o per pass, 4 passes
    int b_n = tid & 63, b_k = tid >> 6;     // 64n x 4k  per pass, 4 passes
    float acc[4][4] = {};
    for (int k0 = 0; k0 < K; k0 += 16) {
        #pragma unroll
        for (int r = 0; r < 4; r++)
            As[a_k][a_o + r*16] = W[(size_t)(o0 + a_o + r*16)*K + k0 + a_k];
        #pragma unroll
        for (int r = 0; r < 4; r++)
            Bs[b_k + r*4][b_n] = X[(size_t)(k0 + b_k + r*4)*NN + n0 + b_n];
        __syncthreads();
        #pragma unroll
        for (int kk = 0; kk < 16; kk++) {
            float a[4], b[4];
            #pragma unroll
            for (int j = 0; j < 4; j++) a[j] = As[kk][ty*4+j];
            #pragma unroll
            for (int j = 0; j < 4; j++) b[j] = Bs[kk][tx*4+j];
            #pragma unroll
            for (int ii = 0; ii < 4; ii++)
                #pragma unroll
                for (int jj = 0; jj < 4; jj++)
                    acc[ii][jj] += a[ii]*b[jj];
        }
        __syncthreads();
    }
    #pragma unroll
    for (int ii = 0; ii < 4; ii++) {
        int o = o0 + ty*4 + ii;
        float bv = bias[o];
        #pragma unroll
        for (int jj = 0; jj < 4; jj++) {
            int n = n0 + tx*4 + jj;
            float v = acc[ii][jj] + bv;
            if (res) v += res[(size_t)o*NN + n];
            out[(size_t)o*NN + n] = v;
        }
    }
}

// ---------------- RoPE (layout (HD,H,N): channel d = hd*4 + h) ----------------
__global__ void rope_kernel(float* __restrict__ t, const float* __restrict__ cosv,
                            const float* __restrict__ sinv) {
    int idx = blockIdx.x*blockDim.x + threadIdx.x;   // 32*4*2048
    int n = idx & (NN-1);
    int r = idx >> 11;
    int h = r & 3;
    int p = r >> 2;                                  // pair index 0..31
    float c = cosv[n*32+p];
    float s = sinv[n*32+p];
    int i0 = ((2*p)*HH + h)*NN + n;
    int i1 = i0 + HH*NN;
    float a = t[i0], b = t[i1];
    t[i0] = a*c - b*s;
    t[i1] = b*c + a*s;
}

// ---------------- scores: S[h,n,m] = scale * sum_c q[(c*cs+h),n] k[(c*cs+h),m] ----------------
__global__ void __launch_bounds__(256)
scores_kernel(const float* __restrict__ q, const float* __restrict__ k,
              float* __restrict__ S, int Kc, int cstride,
              long long batchStride, int ldS, float scale) {
    __shared__ float qs[64][65];
    __shared__ float ks[64][65];
    int h  = blockIdx.z;
    int m0 = blockIdx.x*64, n0 = blockIdx.y*64;
    int tid = threadIdx.x;
    int tx = tid & 15, ty = tid >> 4;
    int ln = tid & 63, lc = tid >> 6;
    float acc[4][4] = {};
    for (int c0 = 0; c0 < Kc; c0 += 64) {
        #pragma unroll
        for (int r = 0; r < 16; r++) {
            int cl = lc + r*4;
            int ch = (c0 + cl)*cstride + h;
            qs[cl][ln] = q[(size_t)ch*NN + n0 + ln];
            ks[cl][ln] = k[(size_t)ch*NN + m0 + ln];
        }
        __syncthreads();
        #pragma unroll
        for (int kk = 0; kk < 64; kk++) {
            float a[4], b[4];
            #pragma unroll
            for (int j = 0; j < 4; j++) a[j] = qs[kk][ty*4+j];
            #pragma unroll
            for (int j = 0; j < 4; j++) b[j] = ks[kk][tx*4+j];
            #pragma unroll
            for (int ii = 0; ii < 4; ii++)
                #pragma unroll
                for (int jj = 0; jj < 4; jj++)
                    acc[ii][jj] += a[ii]*b[jj];
        }
        __syncthreads();
    }
    float* Sb = S + (size_t)h*batchStride;
    #pragma unroll
    for (int ii = 0; ii < 4; ii++)
        #pragma unroll
        for (int jj = 0; jj < 4; jj++)
            Sb[(size_t)(n0+ty*4+ii)*ldS + m0 + tx*4 + jj] = acc[ii][jj]*scale;
}

// ---------------- row softmax over 2048 cols ----------------
__global__ void __launch_bounds__(256)
softmax_kernel(float* __restrict__ P) {
    __shared__ float sm[8];
    int row = blockIdx.x;
    float* p = P + (size_t)row*NN;
    int t = threadIdx.x;
    float vals[8];
    float mx = -1e30f;
    #pragma unroll
    for (int r = 0; r < 8; r++) { vals[r] = p[t + r*256]; mx = fmaxf(mx, vals[r]); }
    #pragma unroll
    for (int o = 16; o > 0; o >>= 1) mx = fmaxf(mx, __shfl_xor_sync(0xffffffffu, mx, o));
    if ((t & 31) == 0) sm[t >> 5] = mx;
    __syncthreads();
    mx = sm[0];
    #pragma unroll
    for (int i = 1; i < 8; i++) mx = fmaxf(mx, sm[i]);
    float s = 0.f;
    #pragma unroll
    for (int r = 0; r < 8; r++) { vals[r] = __expf(vals[r]-mx); s += vals[r]; }
    #pragma unroll
    for (int o = 16; o > 0; o >>= 1) s += __shfl_xor_sync(0xffffffffu, s, o);
    __syncthreads();
    if ((t & 31) == 0) sm[t >> 5] = s;
    __syncthreads();
    s = 0.f;
    #pragma unroll
    for (int i = 0; i < 8; i++) s += sm[i];
    float inv = 1.0f/s;
    #pragma unroll
    for (int r = 0; r < 8; r++) p[t + r*256] = vals[r]*inv;
}

// ---------------- out[(hd*4+h),n] = sum_m P[h,n,m] v[(hd*4+h),m] ----------------
__global__ void __launch_bounds__(256)
attn_out_kernel(const float* __restrict__ P, const float* __restrict__ v,
                float* __restrict__ out) {
    __shared__ float Ps[64][65];   // [m][n]
    __shared__ float Vs[64][65];   // [m][hd]
    int h  = blockIdx.z;
    int n0 = blockIdx.x*64;
    const float* Pb = P + (size_t)h*NN*NN;
    int tid = threadIdx.x;
    int tx = tid & 15, ty = tid >> 4;
    int lm = tid & 63, lr = tid >> 6;
    float acc[4][4] = {};
    for (int m0 = 0; m0 < NN; m0 += 64) {
        #pragma unroll
        for (int r = 0; r < 16; r++) {
            int rr = lr + r*4;
            Ps[lm][rr] = Pb[(size_t)(n0+rr)*NN + m0 + lm];
            Vs[lm][rr] = v[(size_t)(rr*HH + h)*NN + m0 + lm];
        }
        __syncthreads();
        #pragma unroll
        for (int kk = 0; kk < 64; kk++) {
            float a[4], b[4];
            #pragma unroll
            for (int j = 0; j < 4; j++) a[j] = Vs[kk][ty*4+j];
            #pragma unroll
            for (int j = 0; j < 4; j++) b[j] = Ps[kk][tx*4+j];
            #pragma unroll
            for (int ii = 0; ii < 4; ii++)
                #pragma unroll
                for (int jj = 0; jj < 4; jj++)
                    acc[ii][jj] += a[ii]*b[jj];
        }
        __syncthreads();
    }
    #pragma unroll
    for (int ii = 0; ii < 4; ii++)
        #pragma unroll
        for (int jj = 0; jj < 4; jj++)
            out[(size_t)((ty*4+ii)*HH + h)*NN + n0 + tx*4 + jj] = acc[ii][jj];
}

// ---------------- fused batchnorm (over n) + relu, per channel ----------------
__global__ void __launch_bounds__(256)
bn_relu_kernel(float* __restrict__ h, const float* __restrict__ g, const float* __restrict__ b) {
    __shared__ float sm1[8], sm2[8];
    int c = blockIdx.x;
    float* row = h + (size_t)c*NN;
    int t = threadIdx.x;
    float vals[8];
    float s = 0.f, sq = 0.f;
    #pragma unroll
    for (int r = 0; r < 8; r++) { float x = row[t + r*256]; vals[r] = x; s += x; sq += x*x; }
    #pragma unroll
    for (int o = 16; o > 0; o >>= 1) {
        s  += __shfl_xor_sync(0xffffffffu, s,  o);
        sq += __shfl_xor_sync(0xffffffffu, sq, o);
    }
    if ((t & 31) == 0) { sm1[t>>5] = s; sm2[t>>5] = sq; }
    __syncthreads();
    s = 0.f; sq = 0.f;
    #pragma unroll
    for (int i = 0; i < 8; i++) { s += sm1[i]; sq += sm2[i]; }
    float mean = s * (1.0f/NN);
    float var  = sq * (1.0f/NN) - mean*mean;
    float sc = g[c]*rsqrtf(var + 1e-5f);
    float sh = b[c] - mean*sc;
    #pragma unroll
    for (int r = 0; r < 8; r++) row[t + r*256] = fmaxf(vals[r]*sc + sh, 0.0f);
}

// ---------------- Sinkhorn pieces ----------------
__global__ void bins_kernel(float* __restrict__ C, const float* __restrict__ alpha) {
    int i = blockIdx.x*blockDim.x + threadIdx.x;
    if (i >= NP1) return;
    float a = alpha[0];
    C[(size_t)i*NP1 + NN] = a;
    C[(size_t)NN*NP1 + i] = a;
}

__global__ void zero_kernel(float* __restrict__ p, int n) {
    int i = blockIdx.x*blockDim.x + threadIdx.x;
    if (i < n) p[i] = 0.0f;
}

__global__ void __launch_bounds__(256)
u_update_kernel(const float* __restrict__ C, const float* __restrict__ vv,
                float* __restrict__ u) {
    __shared__ float sm[8];
    int i = blockIdx.x;
    const float* row = C + (size_t)i*NP1;
    int t = threadIdx.x;
    float mx = -1e30f;
    for (int j = t; j < NP1; j += 256) mx = fmaxf(mx, row[j] + vv[j]);
    #pragma unroll
    for (int o = 16; o > 0; o >>= 1) mx = fmaxf(mx, __shfl_xor_sync(0xffffffffu, mx, o));
    if ((t & 31) == 0) sm[t>>5] = mx;
    __syncthreads();
    mx = sm[0];
    #pragma unroll
    for (int w = 1; w < 8; w++) mx = fmaxf(mx, sm[w]);
    float s = 0.f;
    for (int j = t; j < NP1; j += 256) s += __expf(row[j] + vv[j] - mx);
    #pragma unroll
    for (int o = 16; o > 0; o >>= 1) s += __shfl_xor_sync(0xffffffffu, s, o);
    __syncthreads();
    if ((t & 31) == 0) sm[t>>5] = s;
    __syncthreads();
    s = 0.f;
    #pragma unroll
    for (int w = 0; w < 8; w++) s += sm[w];
    if (t == 0) {
        float lm = (i < NN) ? NORMC : (LOGN + NORMC);
        u[i] = lm - (mx + logf(s));
    }
}

// column LSE, split over 16 row-chunks for occupancy (coalesced along columns)
__global__ void v_part_kernel(const float* __restrict__ C, const float* __restrict__ u,
                              float* __restrict__ pm, float* __restrict__ ps) {
    int j = blockIdx.x*256 + threadIdx.x;
    if (j >= NP1) return;
    int rc = blockIdx.y;
    int i0 = rc*129;
    int i1 = min(i0 + 129, NP1);
    float m = -1e30f, s = 0.f;
    for (int i = i0; i < i1; i++) {
        float x = C[(size_t)i*NP1 + j] + u[i];
        if (x > m) { s = s*__expf(m - x) + 1.f; m = x; }
        else       { s += __expf(x - m); }
    }
    pm[rc*NP1 + j] = m;
    ps[rc*NP1 + j] = s;
}

__global__ void v_combine_kernel(const float* __restrict__ pm, const float* __restrict__ ps,
                                 float* __restrict__ vv) {
    int j = blockIdx.x*256 + threadIdx.x;
    if (j >= NP1) return;
    float M = -1e30f;
    #pragma unroll
    for (int rc = 0; rc < 16; rc++) M = fmaxf(M, pm[rc*NP1 + j]);
    float S = 0.f;
    #pragma unroll
    for (int rc = 0; rc < 16; rc++) S += ps[rc*NP1 + j]*__expf(pm[rc*NP1 + j] - M);
    float ln_ = (j < NN) ? NORMC : (LOGN + NORMC);
    vv[j] = ln_ - (M + logf(S));
}

__global__ void final_add_kernel(float* __restrict__ C, const float* __restrict__ u,
                                 const float* __restrict__ vv) {
    int idx = blockIdx.x*blockDim.x + threadIdx.x;
    if (idx >= NP1*NP1) return;
    int i = idx / NP1, j = idx % NP1;
    C[idx] += u[i] + vv[j] + LOG4096;
}

// ---------------- host orchestration ----------------
static inline void gemm(const float* W, const float* X, const float* bias,
                        const float* res, float* out, int M, int K) {
    dim3 grid(NN/64, M/64);
    sgemm_bias_kernel<<<grid, 256>>>(W, X, bias, res, out, M, K);
}

static void run_attn(const float* x, const float* src,
                     const float* cosv, const float* sinv, float* out,
                     const float* pw, const float* pb,
                     const float* mw, const float* mb,
                     const float* w1, const float* b1,
                     const float* gg, const float* gb,
                     const float* w2, const float* b2,
                     float* pq, float* pk, float* pv, float* pao,
                     float* py, float* ph, float* pprob) {
    gemm(pw,            x,   pb,        nullptr, pq, DM, DM);
    gemm(pw +   DM*DM,  src, pb +   DM, nullptr, pk, DM, DM);
    gemm(pw + 2*DM*DM,  src, pb + 2*DM, nullptr, pv, DM, DM);
    if (cosv) {
        rope_kernel<<<(32*HH*NN)/256, 256>>>(pq, cosv, sinv);
        rope_kernel<<<(32*HH*NN)/256, 256>>>(pk, cosv, sinv);
    }
    scores_kernel<<<dim3(NN/64, NN/64, HH), 256>>>(pq, pk, pprob, HDM, HH,
                                                   (long long)NN*NN, NN, 0.125f);
    softmax_kernel<<<HH*NN, 256>>>(pprob);
    attn_out_kernel<<<dim3(NN/64, 1, HH), 256>>>(pprob, pv, pao);
    cudaMemcpyAsync(py, x, (size_t)DM*NN*sizeof(float), cudaMemcpyDeviceToDevice);
    gemm(mw, pao, mb, nullptr, py + (size_t)DM*NN, DM, DM);   // message into y[256:]
    gemm(w1, py, b1, nullptr, ph, 2*DM, 2*DM);
    bn_relu_kernel<<<2*DM, 256>>>(ph, gg, gb);
    gemm(w2, ph, b2, x, out, DM, 2*DM);                       // fused residual
}

extern "C" void kernel_launch(void* const* d_in, const int* in_sizes, int n_in,
                              void* d_out, int out_size) {
    (void)in_sizes; (void)n_in; (void)out_size;
    const float* desc0   = (const float*)d_in[0];
    const float* desc1   = (const float*)d_in[1];
    const float* kpts0   = (const float*)d_in[2];
    const float* kpts1   = (const float*)d_in[3];
    const float* Wr      = (const float*)d_in[4];
    const float* proj_w  = (const float*)d_in[5];
    const float* proj_b  = (const float*)d_in[6];
    const float* merge_w = (const float*)d_in[7];
    const float* merge_b = (const float*)d_in[8];
    const float* mlp_w1  = (const float*)d_in[9];
    const float* mlp_b1  = (const float*)d_in[10];
    const float* bn_g    = (const float*)d_in[11];
    const float* bn_b    = (const float*)d_in[12];
    const float* mlp_w2  = (const float*)d_in[13];
    const float* mlp_b2  = (const float*)d_in[14];
    const float* fp_w    = (const float*)d_in[15];
    const float* fp_b    = (const float*)d_in[16];
    const float* binsc   = (const float*)d_in[17];
    float* C = (float*)d_out;

    float *pA0,*pB0,*pA1,*pB1,*pq,*pk,*pv,*pao,*py,*ph,*pprob;
    float *pc0,*psn0,*pc1,*psn1,*pu,*pvv,*ppm,*pps;
    cudaGetSymbolAddress((void**)&pA0, g_dA0);
    cudaGetSymbolAddress((void**)&pB0, g_dB0);
    cudaGetSymbolAddress((void**)&pA1, g_dA1);
    cudaGetSymbolAddress((void**)&pB1, g_dB1);
    cudaGetSymbolAddress((void**)&pq,  g_q);
    cudaGetSymbolAddress((void**)&pk,  g_k);
    cudaGetSymbolAddress((void**)&pv,  g_v);
    cudaGetSymbolAddress((void**)&pao, g_ao);
    cudaGetSymbolAddress((void**)&py,  g_y);
    cudaGetSymbolAddress((void**)&ph,  g_h);
    cudaGetSymbolAddress((void**)&pprob, g_prob);
    cudaGetSymbolAddress((void**)&pc0,  g_cos0);
    cudaGetSymbolAddress((void**)&psn0, g_sin0);
    cudaGetSymbolAddress((void**)&pc1,  g_cos1);
    cudaGetSymbolAddress((void**)&psn1, g_sin1);
    cudaGetSymbolAddress((void**)&pu,  g_u);
    cudaGetSymbolAddress((void**)&pvv, g_vv);
    cudaGetSymbolAddress((void**)&ppm, g_pm);
    cudaGetSymbolAddress((void**)&pps, g_ps);

    posenc_kernel<<<(NN*32)/256, 256>>>(kpts0, Wr, pc0, psn0);
    posenc_kernel<<<(NN*32)/256, 256>>>(kpts1, Wr, pc1, psn1);

    const float* d0 = desc0;
    const float* d1 = desc1;
    float* outs0[2] = {pA0, pB0};
    float* outs1[2] = {pA1, pB1};
    for (int i = 0; i < 10; i++) {
        const float* pw = proj_w  + (size_t)i*3*DM*DM;
        const float* pb = proj_b  + (size_t)i*3*DM;
        const float* mw = merge_w + (size_t)i*DM*DM;
        const float* mb = merge_b + (size_t)i*DM;
        const float* w1 = mlp_w1  + (size_t)i*2*DM*2*DM;
        const float* b1 = mlp_b1  + (size_t)i*2*DM;
        const float* gg = bn_g    + (size_t)i*2*DM;
        const float* gb = bn_b    + (size_t)i*2*DM;
        const float* w2 = mlp_w2  + (size_t)i*DM*2*DM;
        const float* b2 = mlp_b2  + (size_t)i*DM;
        bool even = ((i & 1) == 0);
        float* o0 = outs0[i & 1];
        float* o1 = outs1[i & 1];
        run_attn(d0, even ? d0 : d1, even ? pc0 : nullptr, even ? psn0 : nullptr, o0,
                 pw, pb, mw, mb, w1, b1, gg, gb, w2, b2,
                 pq, pk, pv, pao, py, ph, pprob);
        run_attn(d1, even ? d1 : d0, even ? pc1 : nullptr, even ? psn1 : nullptr, o1,
                 pw, pb, mw, mb, w1, b1, gg, gb, w2, b2,
                 pq, pk, pv, pao, py, ph, pprob);
        d0 = o0; d1 = o1;
    }

    // final projection + match scores into d_out interior (ld = 2049)
    gemm(fp_w, d0, fp_b, nullptr, pq, DM, DM);
    gemm(fp_w, d1, fp_b, nullptr, pk, DM, DM);
    scores_kernel<<<dim3(NN/64, NN/64, 1), 256>>>(pq, pk, C, DM, 1, 0LL, NP1, 0.0625f);
    bins_kernel<<<(NP1+255)/256, 256>>>(C, binsc);

    // Sinkhorn (log-space), 20 iterations
    zero_kernel<<<(NP1+255)/256, 256>>>(pvv, NP1);
    for (int t = 0; t < 20; t++) {
        u_update_kernel<<<NP1, 256>>>(C, pvv, pu);
        v_part_kernel<<<dim3((NP1+255)/256, 16), 256>>>(C, pu, ppm, pps);
        v_combine_kernel<<<(NP1+255)/256, 256>>>(ppm, pps, pvv);
    }
    final_add_kernel<<<(NP1*NP1+255)/256, 256>>>(C, pu, pvv);
}

// round 2
// speedup vs baseline: 1.2411x; 1.2411x over previous
#include <cuda_runtime.h>
#include <math.h>

#define NN   2048
#define DM   256
#define HH   4
#define HDM  64
#define NP1  2049
#define NORMC   (-8.317766166719343f)   /* -ln(4096) */
#define LOGN    (7.624618986159398f)    /*  ln(2048) */
#define LOG4096 (8.317766166719343f)

#define SOFF ((size_t)DM*NN)        /* per-stream offset for q/k/v/ao  */
#define YOFF ((size_t)2*DM*NN)      /* per-stream offset for y/h       */

// ---------------- scratch (static device memory; no allocations) ----------------
__device__ float g_dA0[DM*NN];
__device__ float g_dB0[DM*NN];
__device__ float g_dA1[DM*NN];
__device__ float g_dB1[DM*NN];
__device__ float g_q  [2*DM*NN];
__device__ float g_k  [2*DM*NN];
__device__ float g_v  [2*DM*NN];
__device__ float g_ao [2*DM*NN];
__device__ float g_y  [2*2*DM*NN];
__device__ float g_h  [2*2*DM*NN];
__device__ float g_prob[(size_t)2*HH*NN*NN];   // 128 MB: both streams' attention probs
__device__ float g_cos0[NN*32];
__device__ float g_sin0[NN*32];
__device__ float g_cos1[NN*32];
__device__ float g_sin1[NN*32];
__device__ float g_u [NP1];
__device__ float g_vv[NP1];
__device__ float g_pm[16*NP1];
__device__ float g_ps[16*NP1];

// ---------------- arg structs (batched launches via grid.z) ----------------
struct GemmArgs  { const float* W[8]; const float* X[8]; const float* b[8];
                   const float* r[8]; float* o[8]; };
struct ScoreArgs { const float* q[8]; const float* k[8]; float* S[8]; };
struct AOArgs    { const float* P[8]; const float* v[8]; float* o[8]; };
struct RopeArgs  { float* t[4]; const float* c[4]; const float* s[4]; };

// ---------------- positional encoding ----------------
__global__ void posenc_kernel(const float* __restrict__ kpts, const float* __restrict__ Wr,
                              float* __restrict__ cosv, float* __restrict__ sinv) {
    int idx = blockIdx.x*blockDim.x + threadIdx.x;
    if (idx >= NN*32) return;
    int p = idx & 31;
    int n = idx >> 5;
    float kx = (kpts[2*n+0] - 512.0f) * (1.0f/716.8f);
    float ky = (kpts[2*n+1] - 384.0f) * (1.0f/716.8f);
    float pr = kx*Wr[2*p+0] + ky*Wr[2*p+1];
    cosv[idx] = cosf(pr);
    sinv[idx] = sinf(pr);
}

// ---------------- GEMM v2: out[o,n] = sum_c W[o,c] X[c,n] + bias (+res) -------
// tile 64(M) x 128(N), K-tile 16, 4x8 microtile, double-buffered SMEM
__global__ void __launch_bounds__(256,3)
sgemm_v2(GemmArgs g, int K) {
    __shared__ float As[2][16][68];
    __shared__ float Bs[2][16][128];
    int z = blockIdx.z;
    const float* W    = g.W[z];
    const float* X    = g.X[z];
    const float* bias = g.b[z];
    const float* res  = g.r[z];
    float*       out  = g.o[z];
    int t  = threadIdx.x;
    int n0 = blockIdx.x*128, o0 = blockIdx.y*64;
    int wo = t >> 2, wk = (t & 3) << 2;
    int xk = t >> 5, xn = (t & 31) << 2;
    int tx = t & 15, ty = t >> 4;
    const float* Wp = W + (size_t)(o0 + wo)*K + wk;
    const float* Xp = X + (size_t)xk*NN + n0 + xn;

    float4 wv = *(const float4*)Wp;
    float4 x0 = *(const float4*)Xp;
    float4 x1 = *(const float4*)(Xp + 8*NN);
    As[0][wk+0][wo]=wv.x; As[0][wk+1][wo]=wv.y; As[0][wk+2][wo]=wv.z; As[0][wk+3][wo]=wv.w;
    *(float4*)&Bs[0][xk  ][xn] = x0;
    *(float4*)&Bs[0][xk+8][xn] = x1;
    __syncthreads();

    float acc[4][8] = {};
    int nkt = K >> 4;
    for (int kt = 0; kt < nkt; kt++) {
        int buf = kt & 1;
        bool pf = (kt + 1 < nkt);
        if (pf) {
            wv = *(const float4*)(Wp + (kt+1)*16);
            x0 = *(const float4*)(Xp + (size_t)((kt+1)*16    )*NN);
            x1 = *(const float4*)(Xp + (size_t)((kt+1)*16 + 8)*NN);
        }
        #pragma unroll
        for (int kk = 0; kk < 16; kk++) {
            float a[4], b[8];
            *(float4*)a     = *(const float4*)&As[buf][kk][ty*4];
            *(float4*)b     = *(const float4*)&Bs[buf][kk][tx*8];
            *(float4*)(b+4) = *(const float4*)&Bs[buf][kk][tx*8+4];
            #pragma unroll
            for (int ii = 0; ii < 4; ii++)
                #pragma unroll
                for (int jj = 0; jj < 8; jj++)
                    acc[ii][jj] += a[ii]*b[jj];
        }
        if (pf) {
            int nb = buf ^ 1;
            As[nb][wk+0][wo]=wv.x; As[nb][wk+1][wo]=wv.y;
            As[nb][wk+2][wo]=wv.z; As[nb][wk+3][wo]=wv.w;
            *(float4*)&Bs[nb][xk  ][xn] = x0;
            *(float4*)&Bs[nb][xk+8][xn] = x1;
        }
        __syncthreads();
    }
    #pragma unroll
    for (int ii = 0; ii < 4; ii++) {
        int o = o0 + ty*4 + ii;
        float bv = bias[o];
        #pragma unroll
        for (int jj = 0; jj < 8; jj++) {
            int n = n0 + tx*8 + jj;
            float v = acc[ii][jj] + bv;
            if (res) v += res[(size_t)o*NN + n];
            out[(size_t)o*NN + n] = v;
        }
    }
}

// ---------------- RoPE, batched over {q0,k0,q1,k1} via grid.y ----------------
__global__ void rope_v2(RopeArgs a) {
    int z = blockIdx.y;
    float* t_ = a.t[z];
    const float* cosv = a.c[z];
    const float* sinv = a.s[z];
    int idx = blockIdx.x*blockDim.x + threadIdx.x;   // 32*4*2048
    int n = idx & (NN-1);
    int r = idx >> 11;
    int h = r & 3;
    int p = r >> 2;
    float c = cosv[n*32+p];
    float s = sinv[n*32+p];
    int i0 = ((2*p)*HH + h)*NN + n;
    int i1 = i0 + HH*NN;
    float va = t_[i0], vb = t_[i1];
    t_[i0] = va*c - vb*s;
    t_[i1] = vb*c + va*s;
}

// ---------------- scores v2: S[n,m] = scale * sum_c q[c,n] k[c,m] ----------------
// tile 64(n) x 128(m), K-tile 16, 4x8 microtile, double-buffered
__global__ void __launch_bounds__(256,3)
scores_v2(ScoreArgs a, int Kc, int cstride, int ldS, float scale) {
    __shared__ float Qs[2][16][68];
    __shared__ float Ks[2][16][128];
    int z = blockIdx.z;
    const float* q = a.q[z];
    const float* k = a.k[z];
    float*       S = a.S[z];
    int t  = threadIdx.x;
    int m0 = blockIdx.x*128, n0 = blockIdx.y*64;
    int qc = t >> 4, qn = (t & 15) << 2;
    int kc = t >> 5, km = (t & 31) << 2;
    int tx = t & 15, ty = t >> 4;
    size_t crow = (size_t)cstride*NN;
    const float* qp = q + (size_t)qc*crow + n0 + qn;
    const float* kp = k + (size_t)kc*crow + m0 + km;

    float4 qv = *(const float4*)qp;
    float4 k0v = *(const float4*)kp;
    float4 k1v = *(const float4*)(kp + 8*crow);
    *(float4*)&Qs[0][qc][qn]    = qv;
    *(float4*)&Ks[0][kc][km]    = k0v;
    *(float4*)&Ks[0][kc+8][km]  = k1v;
    __syncthreads();

    float acc[4][8] = {};
    int nkt = Kc >> 4;
    for (int kt = 0; kt < nkt; kt++) {
        int buf = kt & 1;
        bool pf = (kt + 1 < nkt);
        if (pf) {
            size_t off = (size_t)(kt+1)*16*crow;
            qv  = *(const float4*)(qp + off);
            k0v = *(const float4*)(kp + off);
            k1v = *(const float4*)(kp + off + 8*crow);
        }
        #pragma unroll
        for (int kk = 0; kk < 16; kk++) {
            float av[4], bv[8];
            *(float4*)av     = *(const float4*)&Qs[buf][kk][ty*4];
            *(float4*)bv     = *(const float4*)&Ks[buf][kk][tx*8];
            *(float4*)(bv+4) = *(const float4*)&Ks[buf][kk][tx*8+4];
            #pragma unroll
            for (int ii = 0; ii < 4; ii++)
                #pragma unroll
                for (int jj = 0; jj < 8; jj++)
                    acc[ii][jj] += av[ii]*bv[jj];
        }
        if (pf) {
            int nb = buf ^ 1;
            *(float4*)&Qs[nb][qc][qn]   = qv;
            *(float4*)&Ks[nb][kc][km]   = k0v;
            *(float4*)&Ks[nb][kc+8][km] = k1v;
        }
        __syncthreads();
    }
    #pragma unroll
    for (int ii = 0; ii < 4; ii++)
        #pragma unroll
        for (int jj = 0; jj < 8; jj++)
            S[(size_t)(n0+ty*4+ii)*ldS + m0 + tx*8 + jj] = acc[ii][jj]*scale;
}

// ---------------- row softmax over 2048 cols ----------------
__global__ void __launch_bounds__(256)
softmax_kernel(float* __restrict__ P) {
    __shared__ float sm[8];
    size_t row = blockIdx.x;
    float* p = P + row*NN;
    int t = threadIdx.x;
    float vals[8];
    float mx = -1e30f;
    #pragma unroll
    for (int r = 0; r < 8; r++) { vals[r] = p[t + r*256]; mx = fmaxf(mx, vals[r]); }
    #pragma unroll
    for (int o = 16; o > 0; o >>= 1) mx = fmaxf(mx, __shfl_xor_sync(0xffffffffu, mx, o));
    if ((t & 31) == 0) sm[t >> 5] = mx;
    __syncthreads();
    mx = sm[0];
    #pragma unroll
    for (int i = 1; i < 8; i++) mx = fmaxf(mx, sm[i]);
    float s = 0.f;
    #pragma unroll
    for (int r = 0; r < 8; r++) { vals[r] = __expf(vals[r]-mx); s += vals[r]; }
    #pragma unroll
    for (int o = 16; o > 0; o >>= 1) s += __shfl_xor_sync(0xffffffffu, s, o);
    __syncthreads();
    if ((t & 31) == 0) sm[t >> 5] = s;
    __syncthreads();
    s = 0.f;
    #pragma unroll
    for (int i = 0; i < 8; i++) s += sm[i];
    float inv = 1.0f/s;
    #pragma unroll
    for (int r = 0; r < 8; r++) p[t + r*256] = vals[r]*inv;
}

// ---------------- attn_out v2: out[hd,n] = sum_m V[hd,m] P[n,m] ----------------
// tile 64(hd) x 64(n), K-tile 16, 4x4 microtile, double-buffered
__global__ void __launch_bounds__(256,3)
attn_out_v2(AOArgs g) {
    __shared__ float Vs[2][16][68];
    __shared__ float Ps[2][16][68];
    int z = blockIdx.z;
    const float* P   = g.P[z];
    const float* v   = g.v[z];
    float*       out = g.o[z];
    int t  = threadIdx.x;
    int n0 = blockIdx.x*64;
    int rh = t >> 2, mk = (t & 3) << 2;
    int tx = t & 15, ty = t >> 4;
    const float* vp = v + (size_t)rh*4*NN + mk;       // row hd=rh, stride 4*NN
    const float* pp = P + (size_t)(n0 + rh)*NN + mk;  // row n, stride NN

    float4 vv = *(const float4*)vp;
    float4 pv = *(const float4*)pp;
    Vs[0][mk+0][rh]=vv.x; Vs[0][mk+1][rh]=vv.y; Vs[0][mk+2][rh]=vv.z; Vs[0][mk+3][rh]=vv.w;
    Ps[0][mk+0][rh]=pv.x; Ps[0][mk+1][rh]=pv.y; Ps[0][mk+2][rh]=pv.z; Ps[0][mk+3][rh]=pv.w;
    __syncthreads();

    float acc[4][4] = {};
    for (int kt = 0; kt < NN/16; kt++) {
        int buf = kt & 1;
        bool pf = (kt + 1 < NN/16);
        if (pf) {
            vv = *(const float4*)(vp + (kt+1)*16);
            pv = *(const float4*)(pp + (kt+1)*16);
        }
        #pragma unroll
        for (int kk = 0; kk < 16; kk++) {
            float av[4], bv[4];
            *(float4*)av = *(const float4*)&Vs[buf][kk][ty*4];
            *(float4*)bv = *(const float4*)&Ps[buf][kk][tx*4];
            #pragma unroll
            for (int ii = 0; ii < 4; ii++)
                #pragma unroll
                for (int jj = 0; jj < 4; jj++)
                    acc[ii][jj] += av[ii]*bv[jj];
        }
        if (pf) {
            int nb = buf ^ 1;
            Vs[nb][mk+0][rh]=vv.x; Vs[nb][mk+1][rh]=vv.y; Vs[nb][mk+2][rh]=vv.z; Vs[nb][mk+3][rh]=vv.w;
            Ps[nb][mk+0][rh]=pv.x; Ps[nb][mk+1][rh]=pv.y; Ps[nb][mk+2][rh]=pv.z; Ps[nb][mk+3][rh]=pv.w;
        }
        __syncthreads();
    }
    #pragma unroll
    for (int ii = 0; ii < 4; ii++)
        #pragma unroll
        for (int jj = 0; jj < 4; jj++)
            out[(size_t)(ty*4+ii)*4*NN + n0 + tx*4 + jj] = acc[ii][jj];
}

// ---------------- fused batchnorm + relu, 2 streams via block index ----------------
__global__ void __launch_bounds__(256)
bn_relu_v2(float* __restrict__ hbase, const float* __restrict__ g, const float* __restrict__ b) {
    __shared__ float sm1[8], sm2[8];
    int blk = blockIdx.x;
    int s = blk >> 9;
    int c = blk & 511;
    float* row = hbase + (size_t)s*YOFF + (size_t)c*NN;
    int t = threadIdx.x;
    float vals[8];
    float su = 0.f, sq = 0.f;
    #pragma unroll
    for (int r = 0; r < 8; r++) { float x = row[t + r*256]; vals[r] = x; su += x; sq += x*x; }
    #pragma unroll
    for (int o = 16; o > 0; o >>= 1) {
        su += __shfl_xor_sync(0xffffffffu, su, o);
        sq += __shfl_xor_sync(0xffffffffu, sq, o);
    }
    if ((t & 31) == 0) { sm1[t>>5] = su; sm2[t>>5] = sq; }
    __syncthreads();
    su = 0.f; sq = 0.f;
    #pragma unroll
    for (int i = 0; i < 8; i++) { su += sm1[i]; sq += sm2[i]; }
    float mean = su * (1.0f/NN);
    float var  = sq * (1.0f/NN) - mean*mean;
    float sc = g[c]*rsqrtf(var + 1e-5f);
    float sh = b[c] - mean*sc;
    #pragma unroll
    for (int r = 0; r < 8; r++) row[t + r*256] = fmaxf(vals[r]*sc + sh, 0.0f);
}

// ---------------- Sinkhorn pieces ----------------
__global__ void bins_kernel(float* __restrict__ C, const float* __restrict__ alpha) {
    int i = blockIdx.x*blockDim.x + threadIdx.x;
    if (i >= NP1) return;
    float a = alpha[0];
    C[(size_t)i*NP1 + NN] = a;
    C[(size_t)NN*NP1 + i] = a;
}

__global__ void zero_kernel(float* __restrict__ p, int n) {
    int i = blockIdx.x*blockDim.x + threadIdx.x;
    if (i < n) p[i] = 0.0f;
}

__global__ void __launch_bounds__(256)
u_update_kernel(const float* __restrict__ C, const float* __restrict__ vv,
                float* __restrict__ u) {
    __shared__ float sm[8];
    int i = blockIdx.x;
    const float* row = C + (size_t)i*NP1;
    int t = threadIdx.x;
    float mx = -1e30f;
    for (int j = t; j < NP1; j += 256) mx = fmaxf(mx, row[j] + vv[j]);
    #pragma unroll
    for (int o = 16; o > 0; o >>= 1) mx = fmaxf(mx, __shfl_xor_sync(0xffffffffu, mx, o));
    if ((t & 31) == 0) sm[t>>5] = mx;
    __syncthreads();
    mx = sm[0];
    #pragma unroll
    for (int w = 1; w < 8; w++) mx = fmaxf(mx, sm[w]);
    float s = 0.f;
    for (int j = t; j < NP1; j += 256) s += __expf(row[j] + vv[j] - mx);
    #pragma unroll
    for (int o = 16; o > 0; o >>= 1) s += __shfl_xor_sync(0xffffffffu, s, o);
    __syncthreads();
    if ((t & 31) == 0) sm[t>>5] = s;
    __syncthreads();
    s = 0.f;
    #pragma unroll
    for (int w = 0; w < 8; w++) s += sm[w];
    if (t == 0) {
        float lm = (i < NN) ? NORMC : (LOGN + NORMC);
        u[i] = lm - (mx + logf(s));
    }
}

__global__ void v_part_kernel(const float* __restrict__ C, const float* __restrict__ u,
                              float* __restrict__ pm, float* __restrict__ ps) {
    int j = blockIdx.x*256 + threadIdx.x;
    if (j >= NP1) return;
    int rc = blockIdx.y;
    int i0 = rc*129;
    int i1 = min(i0 + 129, NP1);
    float m = -1e30f, s = 0.f;
    for (int i = i0; i < i1; i++) {
        float x = C[(size_t)i*NP1 + j] + u[i];
        if (x > m) { s = s*__expf(m - x) + 1.f; m = x; }
        else       { s += __expf(x - m); }
    }
    pm[rc*NP1 + j] = m;
    ps[rc*NP1 + j] = s;
}

__global__ void v_combine_kernel(const float* __restrict__ pm, const float* __restrict__ ps,
                                 float* __restrict__ vv) {
    int j = blockIdx.x*256 + threadIdx.x;
    if (j >= NP1) return;
    float M = -1e30f;
    #pragma unroll
    for (int rc = 0; rc < 16; rc++) M = fmaxf(M, pm[rc*NP1 + j]);
    float S = 0.f;
    #pragma unroll
    for (int rc = 0; rc < 16; rc++) S += ps[rc*NP1 + j]*__expf(pm[rc*NP1 + j] - M);
    float ln_ = (j < NN) ? NORMC : (LOGN + NORMC);
    vv[j] = ln_ - (M + logf(S));
}

__global__ void final_add_kernel(float* __restrict__ C, const float* __restrict__ u,
                                 const float* __restrict__ vv) {
    int idx = blockIdx.x*blockDim.x + threadIdx.x;
    if (idx >= NP1*NP1) return;
    int i = idx / NP1, j = idx % NP1;
    C[idx] += u[i] + vv[j] + LOG4096;
}

// ---------------- host orchestration ----------------
extern "C" void kernel_launch(void* const* d_in, const int* in_sizes, int n_in,
                              void* d_out, int out_size) {
    (void)in_sizes; (void)n_in; (void)out_size;
    const float* desc0   = (const float*)d_in[0];
    const float* desc1   = (const float*)d_in[1];
    const float* kpts0   = (const float*)d_in[2];
    const float* kpts1   = (const float*)d_in[3];
    const float* Wr      = (const float*)d_in[4];
    const float* proj_w  = (const float*)d_in[5];
    const float* proj_b  = (const float*)d_in[6];
    const float* merge_w = (const float*)d_in[7];
    const float* merge_b = (const float*)d_in[8];
    const float* mlp_w1  = (const float*)d_in[9];
    const float* mlp_b1  = (const float*)d_in[10];
    const float* bn_g    = (const float*)d_in[11];
    const float* bn_b    = (const float*)d_in[12];
    const float* mlp_w2  = (const float*)d_in[13];
    const float* mlp_b2  = (const float*)d_in[14];
    const float* fp_w    = (const float*)d_in[15];
    const float* fp_b    = (const float*)d_in[16];
    const float* binsc   = (const float*)d_in[17];
    float* C = (float*)d_out;

    float *pA0,*pB0,*pA1,*pB1,*pq,*pk,*pv,*pao,*py,*ph,*pprob;
    float *pc0,*psn0,*pc1,*psn1,*pu,*pvv,*ppm,*pps;
    cudaGetSymbolAddress((void**)&pA0, g_dA0);
    cudaGetSymbolAddress((void**)&pB0, g_dB0);
    cudaGetSymbolAddress((void**)&pA1, g_dA1);
    cudaGetSymbolAddress((void**)&pB1, g_dB1);
    cudaGetSymbolAddress((void**)&pq,  g_q);
    cudaGetSymbolAddress((void**)&pk,  g_k);
    cudaGetSymbolAddress((void**)&pv,  g_v);
    cudaGetSymbolAddress((void**)&pao, g_ao);
    cudaGetSymbolAddress((void**)&py,  g_y);
    cudaGetSymbolAddress((void**)&ph,  g_h);
    cudaGetSymbolAddress((void**)&pprob, g_prob);
    cudaGetSymbolAddress((void**)&pc0,  g_cos0);
    cudaGetSymbolAddress((void**)&psn0, g_sin0);
    cudaGetSymbolAddress((void**)&pc1,  g_cos1);
    cudaGetSymbolAddress((void**)&psn1, g_sin1);
    cudaGetSymbolAddress((void**)&pu,  g_u);
    cudaGetSymbolAddress((void**)&pvv, g_vv);
    cudaGetSymbolAddress((void**)&ppm, g_pm);
    cudaGetSymbolAddress((void**)&pps, g_ps);

    posenc_kernel<<<(NN*32)/256, 256>>>(kpts0, Wr, pc0, psn0);
    posenc_kernel<<<(NN*32)/256, 256>>>(kpts1, Wr, pc1, psn1);

    const float* d0 = desc0;
    const float* d1 = desc1;
    float* outs0[2] = {pA0, pB0};
    float* outs1[2] = {pA1, pB1};
    for (int i = 0; i < 10; i++) {
        const float* pw = proj_w  + (size_t)i*3*DM*DM;
        const float* pb = proj_b  + (size_t)i*3*DM;
        const float* mw = merge_w + (size_t)i*DM*DM;
        const float* mb = merge_b + (size_t)i*DM;
        const float* w1 = mlp_w1  + (size_t)i*2*DM*2*DM;
        const float* b1 = mlp_b1  + (size_t)i*2*DM;
        const float* gg = bn_g    + (size_t)i*2*DM;
        const float* gb = bn_b    + (size_t)i*2*DM;
        const float* w2 = mlp_w2  + (size_t)i*DM*2*DM;
        const float* b2 = mlp_b2  + (size_t)i*DM;
        bool even = ((i & 1) == 0);
        const float* xs[2]  = {d0, d1};
        const float* srs[2] = {even ? d0 : d1, even ? d1 : d0};
        float* os[2] = {outs0[i & 1], outs1[i & 1]};

        // --- q/k/v projections: 6 sub-GEMMs in one launch ---
        GemmArgs pa;
        for (int s = 0; s < 2; s++) {
            pa.W[s*3+0] = pw;            pa.X[s*3+0] = xs[s];  pa.b[s*3+0] = pb;
            pa.r[s*3+0] = nullptr;       pa.o[s*3+0] = pq + s*SOFF;
            pa.W[s*3+1] = pw + DM*DM;    pa.X[s*3+1] = srs[s]; pa.b[s*3+1] = pb + DM;
            pa.r[s*3+1] = nullptr;       pa.o[s*3+1] = pk + s*SOFF;
            pa.W[s*3+2] = pw + 2*DM*DM;  pa.X[s*3+2] = srs[s]; pa.b[s*3+2] = pb + 2*DM;
            pa.r[s*3+2] = nullptr;       pa.o[s*3+2] = pv + s*SOFF;
        }
        sgemm_v2<<<dim3(16, 4, 6), 256>>>(pa, DM);

        if (even) {
            RopeArgs ra;
            ra.t[0] = pq;        ra.c[0] = pc0; ra.s[0] = psn0;
            ra.t[1] = pk;        ra.c[1] = pc0; ra.s[1] = psn0;
            ra.t[2] = pq + SOFF; ra.c[2] = pc1; ra.s[2] = psn1;
            ra.t[3] = pk + SOFF; ra.c[3] = pc1; ra.s[3] = psn1;
            rope_v2<<<dim3(1024, 4), 256>>>(ra);
        }

        // --- scores: 8 head-stream slices in one launch ---
        ScoreArgs sa;
        for (int s = 0; s < 2; s++)
            for (int h = 0; h < HH; h++) {
                int z = s*HH + h;
                sa.q[z] = pq + s*SOFF + (size_t)h*NN;
                sa.k[z] = pk + s*SOFF + (size_t)h*NN;
                sa.S[z] = pprob + (size_t)z*NN*NN;
            }
        scores_v2<<<dim3(16, 32, 8), 256>>>(sa, HDM, HH, NN, 0.125f);
        softmax_kernel<<<2*HH*NN, 256>>>(pprob);

        AOArgs aa;
        for (int s = 0; s < 2; s++)
            for (int h = 0; h < HH; h++) {
                int z = s*HH + h;
                aa.P[z] = pprob + (size_t)z*NN*NN;
                aa.v[z] = pv + s*SOFF + (size_t)h*NN;
                aa.o[z] = pao + s*SOFF + (size_t)h*NN;
            }
        attn_out_v2<<<dim3(32, 1, 8), 256>>>(aa);

        // --- y = [x ; merge(ao)] ---
        cudaMemcpyAsync(py,        d0, SOFF*sizeof(float), cudaMemcpyDeviceToDevice);
        cudaMemcpyAsync(py + YOFF, d1, SOFF*sizeof(float), cudaMemcpyDeviceToDevice);
        GemmArgs ma;
        for (int s = 0; s < 2; s++) {
            ma.W[s] = mw; ma.X[s] = pao + s*SOFF; ma.b[s] = mb;
            ma.r[s] = nullptr; ma.o[s] = py + s*YOFF + SOFF;
        }
        sgemm_v2<<<dim3(16, 4, 2), 256>>>(ma, DM);

        // --- mlp1 + bn/relu + mlp2 (residual fused) ---
        GemmArgs m1;
        for (int s = 0; s < 2; s++) {
            m1.W[s] = w1; m1.X[s] = py + s*YOFF; m1.b[s] = b1;
            m1.r[s] = nullptr; m1.o[s] = ph + s*YOFF;
        }
        sgemm_v2<<<dim3(16, 8, 2), 256>>>(m1, 2*DM);
        bn_relu_v2<<<1024, 256>>>(ph, gg, gb);
        GemmArgs m2;
        for (int s = 0; s < 2; s++) {
            m2.W[s] = w2; m2.X[s] = ph + s*YOFF; m2.b[s] = b2;
            m2.r[s] = xs[s]; m2.o[s] = os[s];
        }
        sgemm_v2<<<dim3(16, 4, 2), 256>>>(m2, 2*DM);

        d0 = os[0]; d1 = os[1];
    }

    // final projection (both streams) + match scores into d_out (ld = 2049)
    GemmArgs fa;
    fa.W[0] = fp_w; fa.X[0] = d0; fa.b[0] = fp_b; fa.r[0] = nullptr; fa.o[0] = pq;
    fa.W[1] = fp_w; fa.X[1] = d1; fa.b[1] = fp_b; fa.r[1] = nullptr; fa.o[1] = pk;
    sgemm_v2<<<dim3(16, 4, 2), 256>>>(fa, DM);
    ScoreArgs fs;
    fs.q[0] = pq; fs.k[0] = pk; fs.S[0] = C;
    scores_v2<<<dim3(16, 32, 1), 256>>>(fs, DM, 1, NP1, 0.0625f);
    bins_kernel<<<(NP1+255)/256, 256>>>(C, binsc);

    // Sinkhorn (log-space), 20 iterations
    zero_kernel<<<(NP1+255)/256, 256>>>(pvv, NP1);
    for (int t = 0; t < 20; t++) {
        u_update_kernel<<<NP1, 256>>>(C, pvv, pu);
        v_part_kernel<<<dim3((NP1+255)/256, 16), 256>>>(C, pu, ppm, pps);
        v_combine_kernel<<<(NP1+255)/256, 256>>>(ppm, pps, pvv);
    }
    final_add_kernel<<<(NP1*NP1+255)/256, 256>>>(C, pu, pvv);
}

// round 3
// speedup vs baseline: 1.2429x; 1.0015x over previous
#include <cuda_runtime.h>
#include <math.h>

#define NN   2048
#define DM   256
#define HH   4
#define HDM  64
#define NP1  2049
#define NORMC   (-8.317766166719343f)   /* -ln(4096) */
#define LOGN    (7.624618986159398f)    /*  ln(2048) */
#define LOG4096 (8.317766166719343f)

#define SOFF ((size_t)DM*NN)        /* per-stream offset for q/k/v/ao  */
#define YOFF ((size_t)2*DM*NN)      /* per-stream offset for y/h       */

// ---------------- scratch (static device memory; no allocations) ----------------
__device__ float g_dA0[DM*NN];
__device__ float g_dB0[DM*NN];
__device__ float g_dA1[DM*NN];
__device__ float g_dB1[DM*NN];
__device__ float g_q  [2*DM*NN];
__device__ float g_k  [2*DM*NN];
__device__ float g_v  [2*DM*NN];
__device__ float g_ao [2*DM*NN];
__device__ float g_y  [2*2*DM*NN];
__device__ float g_h  [2*2*DM*NN];
__device__ float g_prob[(size_t)2*HH*NN*NN];   // 128 MB: both streams' attention probs
__device__ float g_cos0[NN*32];
__device__ float g_sin0[NN*32];
__device__ float g_cos1[NN*32];
__device__ float g_sin1[NN*32];
__device__ float g_u [NP1];
__device__ float g_vv[NP1];
__device__ float g_pm[16*NP1];
__device__ float g_ps[16*NP1];

// ---------------- arg structs (batched launches via grid.z) ----------------
struct GemmArgs  { const float* W[8]; const float* X[8]; const float* b[8];
                   const float* r[8]; float* o[8]; };
struct ScoreArgs { const float* q[8]; const float* k[8]; float* S[8]; };
struct AOArgs    { const float* P[8]; const float* v[8]; float* o[8]; };
struct RopeArgs  { float* t[4]; const float* c[4]; const float* s[4]; };

// ---------------- positional encoding ----------------
__global__ void posenc_kernel(const float* __restrict__ kpts, const float* __restrict__ Wr,
                              float* __restrict__ cosv, float* __restrict__ sinv) {
    int idx = blockIdx.x*blockDim.x + threadIdx.x;
    if (idx >= NN*32) return;
    int p = idx & 31;
    int n = idx >> 5;
    float kx = (kpts[2*n+0] - 512.0f) * (1.0f/716.8f);
    float ky = (kpts[2*n+1] - 384.0f) * (1.0f/716.8f);
    float pr = kx*Wr[2*p+0] + ky*Wr[2*p+1];
    cosv[idx] = cosf(pr);
    sinv[idx] = sinf(pr);
}

// ---------------- GEMM v2: out[o,n] = sum_c W[o,c] X[c,n] + bias (+res) -------
// tile 64(M) x 128(N), K-tile 16, 4x8 microtile, double-buffered SMEM
__global__ void __launch_bounds__(256,3)
sgemm_v2(GemmArgs g, int K) {
    __shared__ float As[2][16][68];
    __shared__ float Bs[2][16][128];
    int z = blockIdx.z;
    const float* W    = g.W[z];
    const float* X    = g.X[z];
    const float* bias = g.b[z];
    const float* res  = g.r[z];
    float*       out  = g.o[z];
    int t  = threadIdx.x;
    int n0 = blockIdx.x*128, o0 = blockIdx.y*64;
    int wo = t >> 2, wk = (t & 3) << 2;
    int xk = t >> 5, xn = (t & 31) << 2;
    int tx = t & 15, ty = t >> 4;
    const float* Wp = W + (size_t)(o0 + wo)*K + wk;
    const float* Xp = X + (size_t)xk*NN + n0 + xn;

    float4 wv = *(const float4*)Wp;
    float4 x0 = *(const float4*)Xp;
    float4 x1 = *(const float4*)(Xp + 8*NN);
    As[0][wk+0][wo]=wv.x; As[0][wk+1][wo]=wv.y; As[0][wk+2][wo]=wv.z; As[0][wk+3][wo]=wv.w;
    *(float4*)&Bs[0][xk  ][xn] = x0;
    *(float4*)&Bs[0][xk+8][xn] = x1;
    __syncthreads();

    float acc[4][8] = {};
    int nkt = K >> 4;
    for (int kt = 0; kt < nkt; kt++) {
        int buf = kt & 1;
        bool pf = (kt + 1 < nkt);
        if (pf) {
            wv = *(const float4*)(Wp + (kt+1)*16);
            x0 = *(const float4*)(Xp + (size_t)((kt+1)*16    )*NN);
            x1 = *(const float4*)(Xp + (size_t)((kt+1)*16 + 8)*NN);
        }
        #pragma unroll
        for (int kk = 0; kk < 16; kk++) {
            float a[4], b[8];
            *(float4*)a     = *(const float4*)&As[buf][kk][ty*4];
            *(float4*)b     = *(const float4*)&Bs[buf][kk][tx*8];
            *(float4*)(b+4) = *(const float4*)&Bs[buf][kk][tx*8+4];
            #pragma unroll
            for (int ii = 0; ii < 4; ii++)
                #pragma unroll
                for (int jj = 0; jj < 8; jj++)
                    acc[ii][jj] += a[ii]*b[jj];
        }
        if (pf) {
            int nb = buf ^ 1;
            As[nb][wk+0][wo]=wv.x; As[nb][wk+1][wo]=wv.y;
            As[nb][wk+2][wo]=wv.z; As[nb][wk+3][wo]=wv.w;
            *(float4*)&Bs[nb][xk  ][xn] = x0;
            *(float4*)&Bs[nb][xk+8][xn] = x1;
        }
        __syncthreads();
    }
    #pragma unroll
    for (int ii = 0; ii < 4; ii++) {
        int o = o0 + ty*4 + ii;
        float bv = bias[o];
        #pragma unroll
        for (int jj = 0; jj < 8; jj++) {
            int n = n0 + tx*8 + jj;
            float v = acc[ii][jj] + bv;
            if (res) v += res[(size_t)o*NN + n];
            out[(size_t)o*NN + n] = v;
        }
    }
}

// ---------------- RoPE, batched over {q0,k0,q1,k1} via grid.y ----------------
__global__ void rope_v2(RopeArgs a) {
    int z = blockIdx.y;
    float* t_ = a.t[z];
    const float* cosv = a.c[z];
    const float* sinv = a.s[z];
    int idx = blockIdx.x*blockDim.x + threadIdx.x;   // 32*4*2048
    int n = idx & (NN-1);
    int r = idx >> 11;
    int h = r & 3;
    int p = r >> 2;
    float c = cosv[n*32+p];
    float s = sinv[n*32+p];
    int i0 = ((2*p)*HH + h)*NN + n;
    int i1 = i0 + HH*NN;
    float va = t_[i0], vb = t_[i1];
    t_[i0] = va*c - vb*s;
    t_[i1] = vb*c + va*s;
}

// ---------------- scores v2: S[n,m] = scale * sum_c q[c,n] k[c,m] ----------------
// tile 64(n) x 128(m), K-tile 16, 4x8 microtile, double-buffered
__global__ void __launch_bounds__(256,3)
scores_v2(ScoreArgs a, int Kc, int cstride, int ldS, float scale) {
    __shared__ float Qs[2][16][68];
    __shared__ float Ks[2][16][128];
    int z = blockIdx.z;
    const float* q = a.q[z];
    const float* k = a.k[z];
    float*       S = a.S[z];
    int t  = threadIdx.x;
    int m0 = blockIdx.x*128, n0 = blockIdx.y*64;
    int qc = t >> 4, qn = (t & 15) << 2;
    int kc = t >> 5, km = (t & 31) << 2;
    int tx = t & 15, ty = t >> 4;
    size_t crow = (size_t)cstride*NN;
    const float* qp = q + (size_t)qc*crow + n0 + qn;
    const float* kp = k + (size_t)kc*crow + m0 + km;

    float4 qv = *(const float4*)qp;
    float4 k0v = *(const float4*)kp;
    float4 k1v = *(const float4*)(kp + 8*crow);
    *(float4*)&Qs[0][qc][qn]    = qv;
    *(float4*)&Ks[0][kc][km]    = k0v;
    *(float4*)&Ks[0][kc+8][km]  = k1v;
    __syncthreads();

    float acc[4][8] = {};
    int nkt = Kc >> 4;
    for (int kt = 0; kt < nkt; kt++) {
        int buf = kt & 1;
        bool pf = (kt + 1 < nkt);
        if (pf) {
            size_t off = (size_t)(kt+1)*16*crow;
            qv  = *(const float4*)(qp + off);
            k0v = *(const float4*)(kp + off);
            k1v = *(const float4*)(kp + off + 8*crow);
        }
        #pragma unroll
        for (int kk = 0; kk < 16; kk++) {
            float av[4], bv[8];
            *(float4*)av     = *(const float4*)&Qs[buf][kk][ty*4];
            *(float4*)bv     = *(const float4*)&Ks[buf][kk][tx*8];
            *(float4*)(bv+4) = *(const float4*)&Ks[buf][kk][tx*8+4];
            #pragma unroll
            for (int ii = 0; ii < 4; ii++)
                #pragma unroll
                for (int jj = 0; jj < 8; jj++)
                    acc[ii][jj] += av[ii]*bv[jj];
        }
        if (pf) {
            int nb = buf ^ 1;
            *(float4*)&Qs[nb][qc][qn]   = qv;
            *(float4*)&Ks[nb][kc][km]   = k0v;
            *(float4*)&Ks[nb][kc+8][km] = k1v;
        }
        __syncthreads();
    }
    #pragma unroll
    for (int ii = 0; ii < 4; ii++)
        #pragma unroll
        for (int jj = 0; jj < 8; jj++)
            S[(size_t)(n0+ty*4+ii)*ldS + m0 + tx*8 + jj] = acc[ii][jj]*scale;
}

// ---------------- row softmax over 2048 cols ----------------
__global__ void __launch_bounds__(256)
softmax_kernel(float* __restrict__ P) {
    __shared__ float sm[8];
    size_t row = blockIdx.x;
    float* p = P + row*NN;
    int t = threadIdx.x;
    float vals[8];
    float mx = -1e30f;
    #pragma unroll
    for (int r = 0; r < 8; r++) { vals[r] = p[t + r*256]; mx = fmaxf(mx, vals[r]); }
    #pragma unroll
    for (int o = 16; o > 0; o >>= 1) mx = fmaxf(mx, __shfl_xor_sync(0xffffffffu, mx, o));
    if ((t & 31) == 0) sm[t >> 5] = mx;
    __syncthreads();
    mx = sm[0];
    #pragma unroll
    for (int i = 1; i < 8; i++) mx = fmaxf(mx, sm[i]);
    float s = 0.f;
    #pragma unroll
    for (int r = 0; r < 8; r++) { vals[r] = __expf(vals[r]-mx); s += vals[r]; }
    #pragma unroll
    for (int o = 16; o > 0; o >>= 1) s += __shfl_xor_sync(0xffffffffu, s, o);
    __syncthreads();
    if ((t & 31) == 0) sm[t >> 5] = s;
    __syncthreads();
    s = 0.f;
    #pragma unroll
    for (int i = 0; i < 8; i++) s += sm[i];
    float inv = 1.0f/s;
    #pragma unroll
    for (int r = 0; r < 8; r++) p[t + r*256] = vals[r]*inv;
}

// ---------------- attn_out v2: out[hd,n] = sum_m V[hd,m] P[n,m] ----------------
// tile 64(hd) x 64(n), K-tile 16, 4x4 microtile, double-buffered
__global__ void __launch_bounds__(256,3)
attn_out_v2(AOArgs g) {
    __shared__ float Vs[2][16][68];
    __shared__ float Ps[2][16][68];
    int z = blockIdx.z;
    const float* P   = g.P[z];
    const float* v   = g.v[z];
    float*       out = g.o[z];
    int t  = threadIdx.x;
    int n0 = blockIdx.x*64;
    int rh = t >> 2, mk = (t & 3) << 2;
    int tx = t & 15, ty = t >> 4;
    const float* vp = v + (size_t)rh*4*NN + mk;       // row hd=rh, stride 4*NN
    const float* pp = P + (size_t)(n0 + rh)*NN + mk;  // row n, stride NN

    float4 vv = *(const float4*)vp;
    float4 pv = *(const float4*)pp;
    Vs[0][mk+0][rh]=vv.x; Vs[0][mk+1][rh]=vv.y; Vs[0][mk+2][rh]=vv.z; Vs[0][mk+3][rh]=vv.w;
    Ps[0][mk+0][rh]=pv.x; Ps[0][mk+1][rh]=pv.y; Ps[0][mk+2][rh]=pv.z; Ps[0][mk+3][rh]=pv.w;
    __syncthreads();

    float acc[4][4] = {};
    for (int kt = 0; kt < NN/16; kt++) {
        int buf = kt & 1;
        bool pf = (kt + 1 < NN/16);
        if (pf) {
            vv = *(const float4*)(vp + (kt+1)*16);
            pv = *(const float4*)(pp + (kt+1)*16);
        }
        #pragma unroll
        for (int kk = 0; kk < 16; kk++) {
            float av[4], bv[4];
            *(float4*)av = *(const float4*)&Vs[buf][kk][ty*4];
            *(float4*)bv = *(const float4*)&Ps[buf][kk][tx*4];
            #pragma unroll
            for (int ii = 0; ii < 4; ii++)
                #pragma unroll
                for (int jj = 0; jj < 4; jj++)
                    acc[ii][jj] += av[ii]*bv[jj];
        }
        if (pf) {
            int nb = buf ^ 1;
            Vs[nb][mk+0][rh]=vv.x; Vs[nb][mk+1][rh]=vv.y; Vs[nb][mk+2][rh]=vv.z; Vs[nb][mk+3][rh]=vv.w;
            Ps[nb][mk+0][rh]=pv.x; Ps[nb][mk+1][rh]=pv.y; Ps[nb][mk+2][rh]=pv.z; Ps[nb][mk+3][rh]=pv.w;
        }
        __syncthreads();
    }
    #pragma unroll
    for (int ii = 0; ii < 4; ii++)
        #pragma unroll
        for (int jj = 0; jj < 4; jj++)
            out[(size_t)(ty*4+ii)*4*NN + n0 + tx*4 + jj] = acc[ii][jj];
}

// ---------------- fused batchnorm + relu, 2 streams via block index ----------------
__global__ void __launch_bounds__(256)
bn_relu_v2(float* __restrict__ hbase, const float* __restrict__ g, const float* __restrict__ b) {
    __shared__ float sm1[8], sm2[8];
    int blk = blockIdx.x;
    int s = blk >> 9;
    int c = blk & 511;
    float* row = hbase + (size_t)s*YOFF + (size_t)c*NN;
    int t = threadIdx.x;
    float vals[8];
    float su = 0.f, sq = 0.f;
    #pragma unroll
    for (int r = 0; r < 8; r++) { float x = row[t + r*256]; vals[r] = x; su += x; sq += x*x; }
    #pragma unroll
    for (int o = 16; o > 0; o >>= 1) {
        su += __shfl_xor_sync(0xffffffffu, su, o);
        sq += __shfl_xor_sync(0xffffffffu, sq, o);
    }
    if ((t & 31) == 0) { sm1[t>>5] = su; sm2[t>>5] = sq; }
    __syncthreads();
    su = 0.f; sq = 0.f;
    #pragma unroll
    for (int i = 0; i < 8; i++) { su += sm1[i]; sq += sm2[i]; }
    float mean = su * (1.0f/NN);
    float var  = sq * (1.0f/NN) - mean*mean;
    float sc = g[c]*rsqrtf(var + 1e-5f);
    float sh = b[c] - mean*sc;
    #pragma unroll
    for (int r = 0; r < 8; r++) row[t + r*256] = fmaxf(vals[r]*sc + sh, 0.0f);
}

// ---------------- Sinkhorn pieces ----------------
__global__ void bins_kernel(float* __restrict__ C, const float* __restrict__ alpha) {
    int i = blockIdx.x*blockDim.x + threadIdx.x;
    if (i >= NP1) return;
    float a = alpha[0];
    C[(size_t)i*NP1 + NN] = a;
    C[(size_t)NN*NP1 + i] = a;
}

__global__ void zero_kernel(float* __restrict__ p, int n) {
    int i = blockIdx.x*blockDim.x + threadIdx.x;
    if (i < n) p[i] = 0.0f;
}

__global__ void __launch_bounds__(256)
u_update_kernel(const float* __restrict__ C, const float* __restrict__ vv,
                float* __restrict__ u) {
    __shared__ float sm[8];
    int i = blockIdx.x;
    const float* row = C + (size_t)i*NP1;
    int t = threadIdx.x;
    float mx = -1e30f;
    for (int j = t; j < NP1; j += 256) mx = fmaxf(mx, row[j] + vv[j]);
    #pragma unroll
    for (int o = 16; o > 0; o >>= 1) mx = fmaxf(mx, __shfl_xor_sync(0xffffffffu, mx, o));
    if ((t & 31) == 0) sm[t>>5] = mx;
    __syncthreads();
    mx = sm[0];
    #pragma unroll
    for (int w = 1; w < 8; w++) mx = fmaxf(mx, sm[w]);
    float s = 0.f;
    for (int j = t; j < NP1; j += 256) s += __expf(row[j] + vv[j] - mx);
    #pragma unroll
    for (int o = 16; o > 0; o >>= 1) s += __shfl_xor_sync(0xffffffffu, s, o);
    __syncthreads();
    if ((t & 31) == 0) sm[t>>5] = s;
    __syncthreads();
    s = 0.f;
    #pragma unroll
    for (int w = 0; w < 8; w++) s += sm[w];
    if (t == 0) {
        float lm = (i < NN) ? NORMC : (LOGN + NORMC);
        u[i] = lm - (mx + logf(s));
    }
}

__global__ void v_part_kernel(const float* __restrict__ C, const float* __restrict__ u,
                              float* __restrict__ pm, float* __restrict__ ps) {
    int j = blockIdx.x*256 + threadIdx.x;
    if (j >= NP1) return;
    int rc = blockIdx.y;
    int i0 = rc*129;
    int i1 = min(i0 + 129, NP1);
    float m = -1e30f, s = 0.f;
    for (int i = i0; i < i1; i++) {
        float x = C[(size_t)i*NP1 + j] + u[i];
        if (x > m) { s = s*__expf(m - x) + 1.f; m = x; }
        else       { s += __expf(x - m); }
    }
    pm[rc*NP1 + j] = m;
    ps[rc*NP1 + j] = s;
}

__global__ void v_combine_kernel(const float* __restrict__ pm, const float* __restrict__ ps,
                                 float* __restrict__ vv) {
    int j = blockIdx.x*256 + threadIdx.x;
    if (j >= NP1) return;
    float M = -1e30f;
    #pragma unroll
    for (int rc = 0; rc < 16; rc++) M = fmaxf(M, pm[rc*NP1 + j]);
    float S = 0.f;
    #pragma unroll
    for (int rc = 0; rc < 16; rc++) S += ps[rc*NP1 + j]*__expf(pm[rc*NP1 + j] - M);
    float ln_ = (j < NN) ? NORMC : (LOGN + NORMC);
    vv[j] = ln_ - (M + logf(S));
}

__global__ void final_add_kernel(float* __restrict__ C, const float* __restrict__ u,
                                 const float* __restrict__ vv) {
    int idx = blockIdx.x*blockDim.x + threadIdx.x;
    if (idx >= NP1*NP1) return;
    int i = idx / NP1, j = idx % NP1;
    C[idx] += u[i] + vv[j] + LOG4096;
}

// ---------------- host orchestration ----------------
extern "C" void kernel_launch(void* const* d_in, const int* in_sizes, int n_in,
                              void* d_out, int out_size) {
    (void)in_sizes; (void)n_in; (void)out_size;
    const float* desc0   = (const float*)d_in[0];
    const float* desc1   = (const float*)d_in[1];
    const float* kpts0   = (const float*)d_in[2];
    const float* kpts1   = (const float*)d_in[3];
    const float* Wr      = (const float*)d_in[4];
    const float* proj_w  = (const float*)d_in[5];
    const float* proj_b  = (const float*)d_in[6];
    const float* merge_w = (const float*)d_in[7];
    const float* merge_b = (const float*)d_in[8];
    const float* mlp_w1  = (const float*)d_in[9];
    const float* mlp_b1  = (const float*)d_in[10];
    const float* bn_g    = (const float*)d_in[11];
    const float* bn_b    = (const float*)d_in[12];
    const float* mlp_w2  = (const float*)d_in[13];
    const float* mlp_b2  = (const float*)d_in[14];
    const float* fp_w    = (const float*)d_in[15];
    const float* fp_b    = (const float*)d_in[16];
    const float* binsc   = (const float*)d_in[17];
    float* C = (float*)d_out;

    float *pA0,*pB0,*pA1,*pB1,*pq,*pk,*pv,*pao,*py,*ph,*pprob;
    float *pc0,*psn0,*pc1,*psn1,*pu,*pvv,*ppm,*pps;
    cudaGetSymbolAddress((void**)&pA0, g_dA0);
    cudaGetSymbolAddress((void**)&pB0, g_dB0);
    cudaGetSymbolAddress((void**)&pA1, g_dA1);
    cudaGetSymbolAddress((void**)&pB1, g_dB1);
    cudaGetSymbolAddress((void**)&pq,  g_q);
    cudaGetSymbolAddress((void**)&pk,  g_k);
    cudaGetSymbolAddress((void**)&pv,  g_v);
    cudaGetSymbolAddress((void**)&pao, g_ao);
    cudaGetSymbolAddress((void**)&py,  g_y);
    cudaGetSymbolAddress((void**)&ph,  g_h);
    cudaGetSymbolAddress((void**)&pprob, g_prob);
    cudaGetSymbolAddress((void**)&pc0,  g_cos0);
    cudaGetSymbolAddress((void**)&psn0, g_sin0);
    cudaGetSymbolAddress((void**)&pc1,  g_cos1);
    cudaGetSymbolAddress((void**)&psn1, g_sin1);
    cudaGetSymbolAddress((void**)&pu,  g_u);
    cudaGetSymbolAddress((void**)&pvv, g_vv);
    cudaGetSymbolAddress((void**)&ppm, g_pm);
    cudaGetSymbolAddress((void**)&pps, g_ps);

    posenc_kernel<<<(NN*32)/256, 256>>>(kpts0, Wr, pc0, psn0);
    posenc_kernel<<<(NN*32)/256, 256>>>(kpts1, Wr, pc1, psn1);

    const float* d0 = desc0;
    const float* d1 = desc1;
    float* outs0[2] = {pA0, pB0};
    float* outs1[2] = {pA1, pB1};
    for (int i = 0; i < 10; i++) {
        const float* pw = proj_w  + (size_t)i*3*DM*DM;
        const float* pb = proj_b  + (size_t)i*3*DM;
        const float* mw = merge_w + (size_t)i*DM*DM;
        const float* mb = merge_b + (size_t)i*DM;
        const float* w1 = mlp_w1  + (size_t)i*2*DM*2*DM;
        const float* b1 = mlp_b1  + (size_t)i*2*DM;
        const float* gg = bn_g    + (size_t)i*2*DM;
        const float* gb = bn_b    + (size_t)i*2*DM;
        const float* w2 = mlp_w2  + (size_t)i*DM*2*DM;
        const float* b2 = mlp_b2  + (size_t)i*DM;
        bool even = ((i & 1) == 0);
        const float* xs[2]  = {d0, d1};
        const float* srs[2] = {even ? d0 : d1, even ? d1 : d0};
        float* os[2] = {outs0[i & 1], outs1[i & 1]};

        // --- q/k/v projections: 6 sub-GEMMs in one launch ---
        GemmArgs pa;
        for (int s = 0; s < 2; s++) {
            pa.W[s*3+0] = pw;            pa.X[s*3+0] = xs[s];  pa.b[s*3+0] = pb;
            pa.r[s*3+0] = nullptr;       pa.o[s*3+0] = pq + s*SOFF;
            pa.W[s*3+1] = pw + DM*DM;    pa.X[s*3+1] = srs[s]; pa.b[s*3+1] = pb + DM;
            pa.r[s*3+1] = nullptr;       pa.o[s*3+1] = pk + s*SOFF;
            pa.W[s*3+2] = pw + 2*DM*DM;  pa.X[s*3+2] = srs[s]; pa.b[s*3+2] = pb + 2*DM;
            pa.r[s*3+2] = nullptr;       pa.o[s*3+2] = pv + s*SOFF;
        }
        sgemm_v2<<<dim3(16, 4, 6), 256>>>(pa, DM);

        if (even) {
            RopeArgs ra;
            ra.t[0] = pq;        ra.c[0] = pc0; ra.s[0] = psn0;
            ra.t[1] = pk;        ra.c[1] = pc0; ra.s[1] = psn0;
            ra.t[2] = pq + SOFF; ra.c[2] = pc1; ra.s[2] = psn1;
            ra.t[3] = pk + SOFF; ra.c[3] = pc1; ra.s[3] = psn1;
            rope_v2<<<dim3(1024, 4), 256>>>(ra);
        }

        // --- scores: 8 head-stream slices in one launch ---
        ScoreArgs sa;
        for (int s = 0; s < 2; s++)
            for (int h = 0; h < HH; h++) {
                int z = s*HH + h;
                sa.q[z] = pq + s*SOFF + (size_t)h*NN;
                sa.k[z] = pk + s*SOFF + (size_t)h*NN;
                sa.S[z] = pprob + (size_t)z*NN*NN;
            }
        scores_v2<<<dim3(16, 32, 8), 256>>>(sa, HDM, HH, NN, 0.125f);
        softmax_kernel<<<2*HH*NN, 256>>>(pprob);

        AOArgs aa;
        for (int s = 0; s < 2; s++)
            for (int h = 0; h < HH; h++) {
                int z = s*HH + h;
                aa.P[z] = pprob + (size_t)z*NN*NN;
                aa.v[z] = pv + s*SOFF + (size_t)h*NN;
                aa.o[z] = pao + s*SOFF + (size_t)h*NN;
            }
        attn_out_v2<<<dim3(32, 1, 8), 256>>>(aa);

        // --- y = [x ; merge(ao)] ---
        cudaMemcpyAsync(py,        d0, SOFF*sizeof(float), cudaMemcpyDeviceToDevice);
        cudaMemcpyAsync(py + YOFF, d1, SOFF*sizeof(float), cudaMemcpyDeviceToDevice);
        GemmArgs ma;
        for (int s = 0; s < 2; s++) {
            ma.W[s] = mw; ma.X[s] = pao + s*SOFF; ma.b[s] = mb;
            ma.r[s] = nullptr; ma.o[s] = py + s*YOFF + SOFF;
        }
        sgemm_v2<<<dim3(16, 4, 2), 256>>>(ma, DM);

        // --- mlp1 + bn/relu + mlp2 (residual fused) ---
        GemmArgs m1;
        for (int s = 0; s < 2; s++) {
            m1.W[s] = w1; m1.X[s] = py + s*YOFF; m1.b[s] = b1;
            m1.r[s] = nullptr; m1.o[s] = ph + s*YOFF;
        }
        sgemm_v2<<<dim3(16, 8, 2), 256>>>(m1, 2*DM);
        bn_relu_v2<<<1024, 256>>>(ph, gg, gb);
        GemmArgs m2;
        for (int s = 0; s < 2; s++) {
            m2.W[s] = w2; m2.X[s] = ph + s*YOFF; m2.b[s] = b2;
            m2.r[s] = xs[s]; m2.o[s] = os[s];
        }
        sgemm_v2<<<dim3(16, 4, 2), 256>>>(m2, 2*DM);

        d0 = os[0]; d1 = os[1];
    }

    // final projection (both streams) + match scores into d_out (ld = 2049)
    GemmArgs fa;
    fa.W[0] = fp_w; fa.X[0] = d0; fa.b[0] = fp_b; fa.r[0] = nullptr; fa.o[0] = pq;
    fa.W[1] = fp_w; fa.X[1] = d1; fa.b[1] = fp_b; fa.r[1] = nullptr; fa.o[1] = pk;
    sgemm_v2<<<dim3(16, 4, 2), 256>>>(fa, DM);
    ScoreArgs fs;
    fs.q[0] = pq; fs.k[0] = pk; fs.S[0] = C;
    scores_v2<<<dim3(16, 32, 1), 256>>>(fs, DM, 1, NP1, 0.0625f);
    bins_kernel<<<(NP1+255)/256, 256>>>(C, binsc);

    // Sinkhorn (log-space), 20 iterations
    zero_kernel<<<(NP1+255)/256, 256>>>(pvv, NP1);
    for (int t = 0; t < 20; t++) {
        u_update_kernel<<<NP1, 256>>>(C, pvv, pu);
        v_part_kernel<<<dim3((NP1+255)/256, 16), 256>>>(C, pu, ppm, pps);
        v_combine_kernel<<<(NP1+255)/256, 256>>>(ppm, pps, pvv);
    }
    final_add_kernel<<<(NP1*NP1+255)/256, 256>>>(C, pu, pvv);
}

// round 5
// speedup vs baseline: 1.4631x; 1.1771x over previous
#include <cuda_runtime.h>
#include <cuda_bf16.h>
#include <math.h>
#include <stdint.h>

#define NN 2048
#define DM 256
#define NP1 2049
#define NORMC (-8.317766166719343f)
#define LOGN (7.624618986159398f)
#define LOG4096 (8.317766166719343f)
#define SZ ((size_t)NN*DM)
#define HSZ ((size_t)NN*512)
#define PSZ ((size_t)NN*NN)
typedef __nv_bfloat16 bf;

// ---------- static scratch ----------
__device__ float g_xF[2*SZ], g_qf[2*SZ], g_kf[2*SZ], g_hf[2*HSZ];
__device__ bf g_yh[2*HSZ], g_yl[2*HSZ];
__device__ bf g_qh[2*SZ], g_ql[2*SZ], g_kh[2*SZ], g_kl[2*SZ];
__device__ bf g_vh[2*SZ], g_vl[2*SZ], g_aoh[2*SZ], g_aol[2*SZ];
__device__ bf g_hh[2*HSZ], g_hl[2*HSZ];
__device__ float g_S[8*PSZ];
__device__ bf g_ph[8*PSZ], g_pl[8*PSZ];
__device__ bf g_wqh[30*65536], g_wql[30*65536], g_wmh[10*65536], g_wml[10*65536];
__device__ bf g_w1h[10*262144], g_w1l[10*262144], g_w2h[10*131072], g_w2l[10*131072];
__device__ bf g_fph[65536], g_fpl[65536];
__device__ float g_pbp[30*256];
__device__ float g_cs[4*NN*32];
__device__ float g_u[NP1], g_vv[NP1], g_pm[16*NP1], g_ps[16*NP1];

// ---------- HMMA m16n8k16 bf16 ----------
__device__ __forceinline__ void mma16816(float* c, const uint32_t* a, const uint32_t* b) {
    asm volatile("mma.sync.aligned.m16n8k16.row.col.f32.bf16.bf16.f32 "
        "{%0,%1,%2,%3}, {%4,%5,%6,%7}, {%8,%9}, {%0,%1,%2,%3};"
        : "+f"(c[0]), "+f"(c[1]), "+f"(c[2]), "+f"(c[3])
        : "r"(a[0]), "r"(a[1]), "r"(a[2]), "r"(a[3]), "r"(b[0]), "r"(b[1]));
}

// ---------- generic split-bf16 HMMA GEMM ----------
// D[row][col] = scale * sum_k A[row][k]*B[col][k]  (+bias +res), A/B hi+lo split
struct MZ { const bf *Ah,*Al,*Bh,*Bl; const float *bias,*res; float *outF; bf *oh,*ol; };
struct MArgs { MZ z[8]; int lda,ldb,ldo,ldh,K,Nc,bias_rows; float scale; };

#define APAD 72
#define SMEMB (4*128*APAD*2)   /* 73728 bytes */

__global__ void __launch_bounds__(256) mma_gemm(MArgs a) {
    extern __shared__ bf smem[];
    bf* Ash = smem;
    bf* Asl = smem + 128*APAD;
    bf* Bsh = smem + 2*128*APAD;
    bf* Bsl = smem + 3*128*APAD;
    MZ z = a.z[blockIdx.z];
    int t = threadIdx.x, w = t>>5, lane = t&31;
    int wm = w & 1, wn = w >> 1;
    int row0 = blockIdx.x*128, col0 = blockIdx.y*128;
    float acc[4][4][4];
    #pragma unroll
    for (int i=0;i<4;i++)
        #pragma unroll
        for (int j=0;j<4;j++)
            #pragma unroll
            for (int e=0;e<4;e++) acc[i][j][e]=0.f;

    int lr = t >> 3, lc = (t & 7) * 8;   // 32 rows per pass, 8B-col chunk
    for (int ch = 0; ch < a.K; ch += 64) {
        __syncthreads();
        #pragma unroll
        for (int it = 0; it < 4; it++) {
            int r = lr + it*32;
            size_t ga = (size_t)(row0 + r)*a.lda + ch + lc;
            *(uint4*)&Ash[r*APAD + lc] = *(const uint4*)(z.Ah + ga);
            *(uint4*)&Asl[r*APAD + lc] = *(const uint4*)(z.Al + ga);
            if (col0 + r < a.Nc) {
                size_t gb = (size_t)(col0 + r)*a.ldb + ch + lc;
                *(uint4*)&Bsh[r*APAD + lc] = *(const uint4*)(z.Bh + gb);
                *(uint4*)&Bsl[r*APAD + lc] = *(const uint4*)(z.Bl + gb);
            }
        }
        __syncthreads();
        #pragma unroll
        for (int ks = 0; ks < 4; ks++) {
            int ak = ks*16 + (lane & 3)*2;
            uint32_t Afh[4][4], Afl[4][4], Bfh[4][2], Bfl[4][2];
            int ar = wm*64 + (lane >> 2);
            #pragma unroll
            for (int i = 0; i < 4; i++) {
                int base = (ar + i*16)*APAD + ak;
                Afh[i][0] = *(const uint32_t*)&Ash[base];
                Afh[i][1] = *(const uint32_t*)&Ash[base + 8*APAD];
                Afh[i][2] = *(const uint32_t*)&Ash[base + 8];
                Afh[i][3] = *(const uint32_t*)&Ash[base + 8*APAD + 8];
                Afl[i][0] = *(const uint32_t*)&Asl[base];
                Afl[i][1] = *(const uint32_t*)&Asl[base + 8*APAD];
                Afl[i][2] = *(const uint32_t*)&Asl[base + 8];
                Afl[i][3] = *(const uint32_t*)&Asl[base + 8*APAD + 8];
            }
            int bc = wn*32 + (lane >> 2);
            #pragma unroll
            for (int j = 0; j < 4; j++) {
                int base = (bc + j*8)*APAD + ak;
                Bfh[j][0] = *(const uint32_t*)&Bsh[base];
                Bfh[j][1] = *(const uint32_t*)&Bsh[base + 8];
                Bfl[j][0] = *(const uint32_t*)&Bsl[base];
                Bfl[j][1] = *(const uint32_t*)&Bsl[base + 8];
            }
            #pragma unroll
            for (int i = 0; i < 4; i++)
                #pragma unroll
                for (int j = 0; j < 4; j++) {
                    mma16816(acc[i][j], Afh[i], Bfh[j]);
                    mma16816(acc[i][j], Afh[i], Bfl[j]);
                    mma16816(acc[i][j], Afl[i], Bfh[j]);
                }
        }
    }
    // epilogue
    #pragma unroll
    for (int i = 0; i < 4; i++) {
        #pragma unroll
        for (int j = 0; j < 4; j++) {
            int gr0 = row0 + wm*64 + i*16 + (lane >> 2);
            int gc  = col0 + wn*32 + j*8 + (lane & 3)*2;
            if (gc >= a.Nc) continue;
            #pragma unroll
            for (int h2 = 0; h2 < 2; h2++) {
                int gr = gr0 + h2*8;
                float v0 = acc[i][j][h2*2+0]*a.scale;
                float v1 = acc[i][j][h2*2+1]*a.scale;
                if (z.bias) {
                    if (a.bias_rows) { float bb=z.bias[gr]; v0+=bb; v1+=bb; }
                    else { v0+=z.bias[gc]; v1+=z.bias[gc+1]; }
                }
                if (z.res) {
                    v0 += z.res[(size_t)gr*a.ldo + gc];
                    v1 += z.res[(size_t)gr*a.ldo + gc + 1];
                }
                if (z.outF) {
                    z.outF[(size_t)gr*a.ldo + gc]   = v0;
                    z.outF[(size_t)gr*a.ldo + gc+1] = v1;
                }
                if (z.oh) {
                    bf h0=__float2bfloat16(v0), h1=__float2bfloat16(v1);
                    size_t o = (size_t)gr*a.ldh + gc;
                    z.oh[o]=h0;   z.oh[o+1]=h1;
                    z.ol[o]  =__float2bfloat16(v0-__bfloat162float(h0));
                    z.ol[o+1]=__float2bfloat16(v1-__bfloat162float(h1));
                }
            }
        }
    }
}

// ---------- conversions ----------
__global__ void wconv(const float* __restrict__ w, bf* __restrict__ oh, bf* __restrict__ ol,
                      int mode, size_t total) {
    size_t idx = (size_t)blockIdx.x*256 + threadIdx.x;
    if (idx >= total) return;
    size_t src = idx;
    if (mode==1) { int op=(idx>>8)&255; int o=(op&63)*4+(op>>6); src = (idx & ~(size_t)0xFF00) | ((size_t)o<<8); }
    else if (mode==2) { int cp=idx&255; int c=(cp&63)*4+(cp>>6); src = (idx & ~(size_t)0xFF) | (size_t)c; }
    float v = w[src];
    bf h = __float2bfloat16(v);
    oh[idx]=h; ol[idx]=__float2bfloat16(v-__bfloat162float(h));
}
__global__ void bias_perm(const float* __restrict__ pb, float* __restrict__ out) {
    int idx = blockIdx.x*256 + threadIdx.x;
    int op = idx & 255;
    out[idx] = pb[(idx & ~255) | ((op&63)*4 + (op>>6))];
}
struct TArgs { const float* in[2]; float* xF[2]; bf *yh[2], *yl[2]; };
__global__ void transpose_split(TArgs a) {
    __shared__ float tl[32][33];
    int zz = blockIdx.z, n0 = blockIdx.x*32, c0 = blockIdx.y*32;
    int tx = threadIdx.x&31, ty = threadIdx.x>>5;
    const float* in = a.in[zz];
    #pragma unroll
    for (int r=0;r<4;r++) tl[ty+r*8][tx] = in[(size_t)(c0+ty+r*8)*NN + n0+tx];
    __syncthreads();
    #pragma unroll
    for (int r=0;r<4;r++) {
        int n=n0+ty+r*8, c=c0+tx;
        float v = tl[tx][ty+r*8];
        a.xF[zz][(size_t)n*256+c]=v;
        bf h=__float2bfloat16(v);
        a.yh[zz][(size_t)n*512+c]=h;
        a.yl[zz][(size_t)n*512+c]=__float2bfloat16(v-__bfloat162float(h));
    }
}
__global__ void posenc_kernel(const float* __restrict__ kpts, const float* __restrict__ Wr,
                              float* __restrict__ cosv, float* __restrict__ sinv) {
    int idx = blockIdx.x*256 + threadIdx.x;
    if (idx >= NN*32) return;
    int p = idx & 31, n = idx >> 5;
    float kx = (kpts[2*n+0]-512.0f)*(1.0f/716.8f);
    float ky = (kpts[2*n+1]-384.0f)*(1.0f/716.8f);
    float pr = kx*Wr[2*p+0] + ky*Wr[2*p+1];
    cosv[idx] = cosf(pr); sinv[idx] = sinf(pr);
}
struct RArgs { const float* f[4]; bf *oh[4], *ol[4]; const float *cs[4], *sn[4]; };
__global__ void rope_split(RArgs a, int dorope) {
    int zz = blockIdx.y;
    int idx = blockIdx.x*256 + threadIdx.x;
    int pair = idx & 127, n = idx >> 7;
    int c = (pair>>5)*64 + 2*(pair&31);
    const float* f = a.f[zz];
    float x0 = f[(size_t)n*256+c], x1 = f[(size_t)n*256+c+1];
    if (dorope) {
        int p = pair&31;
        float cv = a.cs[zz][n*32+p], sv = a.sn[zz][n*32+p];
        float r0 = x0*cv - x1*sv, r1 = x1*cv + x0*sv;
        x0=r0; x1=r1;
    }
    bf h0=__float2bfloat16(x0), h1=__float2bfloat16(x1);
    a.oh[zz][(size_t)n*256+c]=h0;   a.oh[zz][(size_t)n*256+c+1]=h1;
    a.ol[zz][(size_t)n*256+c]=__float2bfloat16(x0-__bfloat162float(h0));
    a.ol[zz][(size_t)n*256+c+1]=__float2bfloat16(x1-__bfloat162float(h1));
}
__global__ void __launch_bounds__(256)
softmax_split(const float* __restrict__ S, bf* __restrict__ ph, bf* __restrict__ pl) {
    __shared__ float sm[8];
    size_t row = blockIdx.x;
    const float* p = S + row*NN;
    int t = threadIdx.x;
    float vals[8], mx=-1e30f;
    #pragma unroll
    for (int r=0;r<8;r++){ vals[r]=p[t+r*256]; mx=fmaxf(mx,vals[r]); }
    #pragma unroll
    for (int o=16;o>0;o>>=1) mx=fmaxf(mx,__shfl_xor_sync(0xffffffffu,mx,o));
    if ((t&31)==0) sm[t>>5]=mx;
    __syncthreads();
    mx=sm[0];
    #pragma unroll
    for (int i=1;i<8;i++) mx=fmaxf(mx,sm[i]);
    float s=0.f;
    #pragma unroll
    for (int r=0;r<8;r++){ vals[r]=__expf(vals[r]-mx); s+=vals[r]; }
    #pragma unroll
    for (int o=16;o>0;o>>=1) s+=__shfl_xor_sync(0xffffffffu,s,o);
    __syncthreads();
    if ((t&31)==0) sm[t>>5]=s;
    __syncthreads();
    s=0.f;
    #pragma unroll
    for (int i=0;i<8;i++) s+=sm[i];
    float inv=1.0f/s;
    #pragma unroll
    for (int r=0;r<8;r++) {
        float pv = vals[r]*inv;
        bf h=__float2bfloat16(pv);
        ph[row*NN+t+r*256]=h;
        pl[row*NN+t+r*256]=__float2bfloat16(pv-__bfloat162float(h));
    }
}
__global__ void __launch_bounds__(256)
bn_split(const float* __restrict__ hf, const float* __restrict__ g, const float* __restrict__ b,
         bf* __restrict__ oh, bf* __restrict__ ol) {
    __shared__ float ssum[4][64], ssq[4][64], sc[64], sh[64];
    size_t base = (size_t)blockIdx.y * HSZ;
    int l = threadIdx.x & 63, r0 = threadIdx.x >> 6;
    int c = blockIdx.x*64 + l;
    float su=0.f, sq=0.f;
    for (int n=r0; n<NN; n+=4) { float x = hf[base+(size_t)n*512+c]; su+=x; sq+=x*x; }
    ssum[r0][l]=su; ssq[r0][l]=sq;
    __syncthreads();
    if (r0==0) {
        float S=0,Q=0;
        #pragma unroll
        for (int i=0;i<4;i++){ S+=ssum[i][l]; Q+=ssq[i][l]; }
        float mean=S*(1.0f/NN), var=Q*(1.0f/NN)-mean*mean;
        float s1=g[c]*rsqrtf(var+1e-5f);
        sc[l]=s1; sh[l]=b[c]-mean*s1;
    }
    __syncthreads();
    float s1=sc[l], s2=sh[l];
    for (int n=r0; n<NN; n+=4) {
        float v=fmaxf(hf[base+(size_t)n*512+c]*s1+s2, 0.0f);
        bf h=__float2bfloat16(v);
        oh[base+(size_t)n*512+c]=h;
        ol[base+(size_t)n*512+c]=__float2bfloat16(v-__bfloat162float(h));
    }
}
// ---------- Sinkhorn ----------
__global__ void bins_kernel(float* __restrict__ C, const float* __restrict__ a) {
    int i = blockIdx.x*256 + threadIdx.x;
    if (i >= NP1) return;
    float v = a[0];
    C[(size_t)i*NP1 + NN] = v;
    C[(size_t)NN*NP1 + i] = v;
}
__global__ void zero_kernel(float* p, int n) { int i=blockIdx.x*256+threadIdx.x; if(i<n) p[i]=0.f; }
__global__ void __launch_bounds__(256)
u_update_kernel(const float* __restrict__ C, const float* __restrict__ vv, float* __restrict__ u) {
    __shared__ float sm[8];
    int i = blockIdx.x;
    const float* row = C + (size_t)i*NP1;
    int t = threadIdx.x;
    float mx = -1e30f;
    for (int j=t; j<NP1; j+=256) mx = fmaxf(mx, row[j]+vv[j]);
    #pragma unroll
    for (int o=16;o>0;o>>=1) mx=fmaxf(mx,__shfl_xor_sync(0xffffffffu,mx,o));
    if ((t&31)==0) sm[t>>5]=mx;
    __syncthreads();
    mx=sm[0];
    #pragma unroll
    for (int w=1;w<8;w++) mx=fmaxf(mx,sm[w]);
    float s=0.f;
    for (int j=t; j<NP1; j+=256) s += __expf(row[j]+vv[j]-mx);
    #pragma unroll
    for (int o=16;o>0;o>>=1) s+=__shfl_xor_sync(0xffffffffu,s,o);
    __syncthreads();
    if ((t&31)==0) sm[t>>5]=s;
    __syncthreads();
    s=0.f;
    #pragma unroll
    for (int w=0;w<8;w++) s+=sm[w];
    if (t==0) u[i] = ((i<NN)?NORMC:(LOGN+NORMC)) - (mx + logf(s));
}
__global__ void v_part_kernel(const float* __restrict__ C, const float* __restrict__ u,
                              float* __restrict__ pm, float* __restrict__ ps) {
    int j = blockIdx.x*256 + threadIdx.x;
    if (j >= NP1) return;
    int rc = blockIdx.y, i0 = rc*129, i1 = min(i0+129, NP1);
    float m=-1e30f, s=0.f;
    for (int i=i0; i<i1; i++) {
        float x = C[(size_t)i*NP1+j] + u[i];
        if (x>m) { s=s*__expf(m-x)+1.f; m=x; } else s+=__expf(x-m);
    }
    pm[rc*NP1+j]=m; ps[rc*NP1+j]=s;
}
__global__ void v_combine_kernel(const float* __restrict__ pm, const float* __restrict__ ps,
                                 float* __restrict__ vv) {
    int j = blockIdx.x*256 + threadIdx.x;
    if (j >= NP1) return;
    float M=-1e30f;
    #pragma unroll
    for (int rc=0;rc<16;rc++) M=fmaxf(M, pm[rc*NP1+j]);
    float S=0.f;
    #pragma unroll
    for (int rc=0;rc<16;rc++) S+=ps[rc*NP1+j]*__expf(pm[rc*NP1+j]-M);
    vv[j] = ((j<NN)?NORMC:(LOGN+NORMC)) - (M + logf(S));
}
__global__ void final_add_kernel(float* __restrict__ C, const float* __restrict__ u,
                                 const float* __restrict__ vv) {
    int idx = blockIdx.x*256 + threadIdx.x;
    if (idx >= NP1*NP1) return;
    C[idx] += u[idx/NP1] + vv[idx%NP1] + LOG4096;
}

// ---------- host ----------
#define GSA(p,s) cudaGetSymbolAddress((void**)&(p), s)
extern "C" void kernel_launch(void* const* d_in, const int* in_sizes, int n_in,
                              void* d_out, int out_size) {
    (void)in_sizes; (void)n_in; (void)out_size;
    const float *desc0=(const float*)d_in[0], *desc1=(const float*)d_in[1];
    const float *kpts0=(const float*)d_in[2], *kpts1=(const float*)d_in[3];
    const float *Wr=(const float*)d_in[4], *proj_w=(const float*)d_in[5];
    const float *proj_b=(const float*)d_in[6];
    const float *merge_w=(const float*)d_in[7], *merge_b=(const float*)d_in[8];
    const float *mlp_w1=(const float*)d_in[9], *mlp_b1=(const float*)d_in[10];
    const float *bn_g=(const float*)d_in[11], *bn_b=(const float*)d_in[12];
    const float *mlp_w2=(const float*)d_in[13], *mlp_b2=(const float*)d_in[14];
    const float *fp_w=(const float*)d_in[15], *fp_b=(const float*)d_in[16];
    const float *binsc=(const float*)d_in[17];
    float* C = (float*)d_out;

    cudaFuncSetAttribute(mma_gemm, cudaFuncAttributeMaxDynamicSharedMemorySize, SMEMB);

    float *xF,*qf,*kf,*hf,*pbp,*cs,*pu,*pvv,*ppm,*pps,*S;
    bf *yh,*yl,*qh,*ql,*kh,*kl,*vh,*vl,*aoh,*aol,*hh,*hl,*ph,*pl;
    bf *wqh,*wql,*wmh,*wml,*w1h,*w1l,*w2h,*w2l,*fph,*fpl;
    GSA(xF,g_xF); GSA(qf,g_qf); GSA(kf,g_kf); GSA(hf,g_hf);
    GSA(yh,g_yh); GSA(yl,g_yl); GSA(qh,g_qh); GSA(ql,g_ql);
    GSA(kh,g_kh); GSA(kl,g_kl); GSA(vh,g_vh); GSA(vl,g_vl);
    GSA(aoh,g_aoh); GSA(aol,g_aol); GSA(hh,g_hh); GSA(hl,g_hl);
    GSA(S,g_S); GSA(ph,g_ph); GSA(pl,g_pl);
    GSA(wqh,g_wqh); GSA(wql,g_wql); GSA(wmh,g_wmh); GSA(wml,g_wml);
    GSA(w1h,g_w1h); GSA(w1l,g_w1l); GSA(w2h,g_w2h); GSA(w2l,g_w2l);
    GSA(fph,g_fph); GSA(fpl,g_fpl); GSA(pbp,g_pbp); GSA(cs,g_cs);
    GSA(pu,g_u); GSA(pvv,g_vv); GSA(ppm,g_pm); GSA(pps,g_ps);
    float *c0=cs, *s0=cs+NN*32, *c1=cs+2*NN*32, *s1=cs+3*NN*32;

    wconv<<<30*65536/256,256>>>(proj_w, wqh, wql, 1, (size_t)30*65536);
    wconv<<<10*65536/256,256>>>(merge_w, wmh, wml, 2, (size_t)10*65536);
    wconv<<<10*262144/256,256>>>(mlp_w1, w1h, w1l, 0, (size_t)10*262144);
    wconv<<<10*131072/256,256>>>(mlp_w2, w2h, w2l, 0, (size_t)10*131072);
    wconv<<<65536/256,256>>>(fp_w, fph, fpl, 0, 65536);
    bias_perm<<<30,256>>>(proj_b, pbp);
    posenc_kernel<<<NN*32/256,256>>>(kpts0, Wr, c0, s0);
    posenc_kernel<<<NN*32/256,256>>>(kpts1, Wr, c1, s1);
    TArgs ta;
    ta.in[0]=desc0; ta.in[1]=desc1;
    for (int s=0;s<2;s++){ ta.xF[s]=xF+s*SZ; ta.yh[s]=yh+s*HSZ; ta.yl[s]=yl+s*HSZ; }
    transpose_split<<<dim3(64,8,2),256>>>(ta);

    for (int l=0; l<10; l++) {
        int even = !(l&1);
        int src[2] = { even?0:1, even?1:0 };
        const float* mb  = merge_b + l*256;
        const float* b1  = mlp_b1 + l*512;
        const float* b2  = mlp_b2 + l*256;

        // q,k projections (fp32 out for RoPE): z={q0,k0,q1,k1}
        MArgs mq = {};
        mq.lda=512; mq.ldb=256; mq.ldo=256; mq.ldh=256; mq.K=256; mq.Nc=256; mq.scale=1.f;
        for (int s=0;s<2;s++) {
            MZ* zq=&mq.z[s*2], *zk=&mq.z[s*2+1];
            zq->Ah=yh+s*HSZ; zq->Al=yl+s*HSZ;
            zq->Bh=wqh+(size_t)(l*3)*65536; zq->Bl=wql+(size_t)(l*3)*65536;
            zq->bias=pbp+(l*3)*256; zq->outF=qf+s*SZ;
            zk->Ah=yh+src[s]*HSZ; zk->Al=yl+src[s]*HSZ;
            zk->Bh=wqh+(size_t)(l*3+1)*65536; zk->Bl=wql+(size_t)(l*3+1)*65536;
            zk->bias=pbp+(l*3+1)*256; zk->outF=kf+s*SZ;
        }
        mma_gemm<<<dim3(16,2,4),256,SMEMB>>>(mq);

        // v projection, output transposed [c][m] as hi/lo
        MArgs mv = {};
        mv.lda=256; mv.ldb=512; mv.ldo=2048; mv.ldh=2048; mv.K=256; mv.Nc=2048;
        mv.scale=1.f; mv.bias_rows=1;
        for (int s=0;s<2;s++) {
            MZ* zv=&mv.z[s];
            zv->Ah=wqh+(size_t)(l*3+2)*65536; zv->Al=wql+(size_t)(l*3+2)*65536;
            zv->Bh=yh+src[s]*HSZ; zv->Bl=yl+src[s]*HSZ;
            zv->bias=pbp+(l*3+2)*256; zv->oh=vh+s*SZ; zv->ol=vl+s*SZ;
        }
        mma_gemm<<<dim3(2,16,2),256,SMEMB>>>(mv);

        // rope (even) or plain split (odd)
        RArgs ra;
        ra.f[0]=qf; ra.f[1]=kf; ra.f[2]=qf+SZ; ra.f[3]=kf+SZ;
        ra.oh[0]=qh; ra.ol[0]=ql; ra.oh[1]=kh; ra.ol[1]=kl;
        ra.oh[2]=qh+SZ; ra.ol[2]=ql+SZ; ra.oh[3]=kh+SZ; ra.ol[3]=kl+SZ;
        ra.cs[0]=c0; ra.sn[0]=s0; ra.cs[1]=c0; ra.sn[1]=s0;
        ra.cs[2]=c1; ra.sn[2]=s1; ra.cs[3]=c1; ra.sn[3]=s1;
        rope_split<<<dim3(1024,4),256>>>(ra, even);

        // scores (per head-stream slice)
        MArgs ms = {};
        ms.lda=256; ms.ldb=256; ms.ldo=2048; ms.K=64; ms.Nc=2048; ms.scale=0.125f;
        for (int s=0;s<2;s++) for (int h=0;h<4;h++) {
            MZ* zz=&ms.z[s*4+h];
            zz->Ah=qh+s*SZ+h*64; zz->Al=ql+s*SZ+h*64;
            zz->Bh=kh+s*SZ+h*64; zz->Bl=kl+s*SZ+h*64;
            zz->outF=S+(size_t)(s*4+h)*PSZ;
        }
        mma_gemm<<<dim3(16,16,8),256,SMEMB>>>(ms);
        softmax_split<<<8*NN,256>>>(S, ph, pl);

        // attn out: rows n, cols hd (64), K=2048
        MArgs mo = {};
        mo.lda=2048; mo.ldb=2048; mo.ldh=256; mo.K=2048; mo.Nc=64; mo.scale=1.f;
        for (int s=0;s<2;s++) for (int h=0;h<4;h++) {
            MZ* zz=&mo.z[s*4+h];
            zz->Ah=ph+(size_t)(s*4+h)*PSZ; zz->Al=pl+(size_t)(s*4+h)*PSZ;
            zz->Bh=vh+s*SZ+(size_t)(h*64)*2048; zz->Bl=vl+s*SZ+(size_t)(h*64)*2048;
            zz->oh=aoh+s*SZ+h*64; zz->ol=aol+s*SZ+h*64;
        }
        mma_gemm<<<dim3(16,1,8),256,SMEMB>>>(mo);

        // merge -> y cols 256:511
        MArgs mm = {};
        mm.lda=256; mm.ldb=256; mm.ldh=512; mm.K=256; mm.Nc=256; mm.scale=1.f;
        for (int s=0;s<2;s++) {
            MZ* zz=&mm.z[s];
            zz->Ah=aoh+s*SZ; zz->Al=aol+s*SZ;
            zz->Bh=wmh+(size_t)l*65536; zz->Bl=wml+(size_t)l*65536;
            zz->bias=mb; zz->oh=yh+s*HSZ+256; zz->ol=yl+s*HSZ+256;
        }
        mma_gemm<<<dim3(16,2,2),256,SMEMB>>>(mm);

        // mlp1 -> h fp32
        MArgs m1 = {};
        m1.lda=512; m1.ldb=512; m1.ldo=512; m1.K=512; m1.Nc=512; m1.scale=1.f;
        for (int s=0;s<2;s++) {
            MZ* zz=&m1.z[s];
            zz->Ah=yh+s*HSZ; zz->Al=yl+s*HSZ;
            zz->Bh=w1h+(size_t)l*262144; zz->Bl=w1l+(size_t)l*262144;
            zz->bias=b1; zz->outF=hf+s*HSZ;
        }
        mma_gemm<<<dim3(16,4,2),256,SMEMB>>>(m1);
        bn_split<<<dim3(8,2),256>>>(hf, bn_g+l*512, bn_b+l*512, hh, hl);

        // mlp2 + residual -> xF + y cols 0:255
        MArgs m2 = {};
        m2.lda=512; m2.ldb=512; m2.ldo=256; m2.ldh=512; m2.K=512; m2.Nc=256; m2.scale=1.f;
        for (int s=0;s<2;s++) {
            MZ* zz=&m2.z[s];
            zz->Ah=hh+s*HSZ; zz->Al=hl+s*HSZ;
            zz->Bh=w2h+(size_t)l*131072; zz->Bl=w2l+(size_t)l*131072;
            zz->bias=b2; zz->res=xF+s*SZ; zz->outF=xF+s*SZ;
            zz->oh=yh+s*HSZ; zz->ol=yl+s*HSZ;
        }
        mma_gemm<<<dim3(16,2,2),256,SMEMB>>>(m2);
    }

    // final projection
    MArgs mf = {};
    mf.lda=512; mf.ldb=256; mf.ldh=256; mf.K=256; mf.Nc=256; mf.scale=1.f;
    for (int s=0;s<2;s++) {
        MZ* zz=&mf.z[s];
        zz->Ah=yh+s*HSZ; zz->Al=yl+s*HSZ;
        zz->Bh=fph; zz->Bl=fpl;
        zz->bias=fp_b; zz->oh=qh+s*SZ; zz->ol=ql+s*SZ;
    }
    mma_gemm<<<dim3(16,2,2),256,SMEMB>>>(mf);

    // final match scores into C (ld 2049)
    MArgs mc = {};
    mc.lda=256; mc.ldb=256; mc.ldo=NP1; mc.K=256; mc.Nc=2048; mc.scale=0.0625f;
    mc.z[0].Ah=qh; mc.z[0].Al=ql; mc.z[0].Bh=qh+SZ; mc.z[0].Bl=ql+SZ;
    mc.z[0].outF=C;
    mma_gemm<<<dim3(16,16,1),256,SMEMB>>>(mc);
    bins_kernel<<<(NP1+255)/256,256>>>(C, binsc);

    zero_kernel<<<(NP1+255)/256,256>>>(pvv, NP1);
    for (int t=0; t<20; t++) {
        u_update_kernel<<<NP1,256>>>(C, pvv, pu);
        v_part_kernel<<<dim3((NP1+255)/256,16),256>>>(C, pu, ppm, pps);
        v_combine_kernel<<<(NP1+255)/256,256>>>(ppm, pps, pvv);
    }
    final_add_kernel<<<(NP1*NP1+255)/256,256>>>(C, pu, pvv);
}

// round 6
// speedup vs baseline: 1.9680x; 1.3451x over previous
#include <cuda_runtime.h>
#include <cuda_bf16.h>
#include <math.h>
#include <stdint.h>

#define NN 2048
#define DM 256
#define NP1 2049
#define NORMC (-8.317766166719343f)
#define LOGN (7.624618986159398f)
#define LOG4096 (8.317766166719343f)
#define SZ ((size_t)NN*DM)
#define HSZ ((size_t)NN*512)
#define PSZ ((size_t)NN*NN)
typedef __nv_bfloat16 bf;

// ---------- static scratch ----------
__device__ float g_xF[2*SZ], g_qf[2*SZ], g_kf[2*SZ], g_hf[2*HSZ];
__device__ bf g_yh[2*HSZ], g_yl[2*HSZ];
__device__ bf g_qh[2*SZ], g_ql[2*SZ], g_kh[2*SZ], g_kl[2*SZ];
__device__ bf g_vh[2*SZ], g_vl[2*SZ], g_aoh[2*SZ], g_aol[2*SZ];
__device__ bf g_hh[2*HSZ], g_hl[2*HSZ];
__device__ float g_S[8*PSZ];
__device__ bf g_ph[8*PSZ], g_pl[8*PSZ];
__device__ bf g_wqh[30*65536], g_wql[30*65536], g_wmh[10*65536], g_wml[10*65536];
__device__ bf g_w1h[10*262144], g_w1l[10*262144], g_w2h[10*131072], g_w2l[10*131072];
__device__ bf g_fph[65536], g_fpl[65536];
__device__ float g_pbp[30*256];
__device__ float g_cs[4*NN*32];
__device__ float g_u[NP1], g_vv[NP1], g_pm[16*NP1], g_ps[16*NP1];

// ---------- HMMA m16n8k16 bf16 ----------
__device__ __forceinline__ void mma16816(float* c, const uint32_t* a, const uint32_t* b) {
    asm volatile("mma.sync.aligned.m16n8k16.row.col.f32.bf16.bf16.f32 "
        "{%0,%1,%2,%3}, {%4,%5,%6,%7}, {%8,%9}, {%0,%1,%2,%3};"
        : "+f"(c[0]), "+f"(c[1]), "+f"(c[2]), "+f"(c[3])
        : "r"(a[0]), "r"(a[1]), "r"(a[2]), "r"(a[3]), "r"(b[0]), "r"(b[1]));
}
#define CP16(dst, src) asm volatile("cp.async.ca.shared.global [%0], [%1], 16;" :: "r"(dst), "l"(src))

// ---------- generic split-bf16 HMMA GEMM, cp.async double-buffered ----------
// D[row][col] = scale * sum_k A[row][k]*B[col][k]  (+bias +res), A/B hi+lo split
struct MZ { const bf *Ah,*Al,*Bh,*Bl; const float *bias,*res; float *outF; bf *oh,*ol; };
struct MArgs { MZ z[8]; int lda,ldb,ldo,ldh,K,Nc,bias_rows; float scale; };

#define APAD 72
#define AST (128*APAD)

template<int JT>   // j-tiles (8 cols) per warp; CTA tile = 128 rows x 32*JT cols
__global__ void __launch_bounds__(256) mma_gemm(MArgs a) {
    constexpr int CTAC = 32*JT;
    constexpr int BST = CTAC*APAD;
    constexpr int STAGE = 2*AST + 2*BST;
    extern __shared__ bf smem[];
    MZ z = a.z[blockIdx.z];
    int t = threadIdx.x, w = t>>5, lane = t&31;
    int wm = w & 1, wn = w >> 1;
    int row0 = blockIdx.x*128, col0 = blockIdx.y*CTAC;
    uint32_t smb = (uint32_t)__cvta_generic_to_shared(smem);
    int lr = t >> 3, lc = (t & 7) * 8;
    int nch = a.K >> 6;

    auto issue = [&](int ch, int st) {
        uint32_t base = smb + (uint32_t)(st*STAGE*2);
        const bf* Agh = z.Ah + (size_t)(row0+lr)*a.lda + ch*64 + lc;
        const bf* Agl = z.Al + (size_t)(row0+lr)*a.lda + ch*64 + lc;
        #pragma unroll
        for (int it=0; it<4; it++) {
            uint32_t d = base + (uint32_t)(((lr+it*32)*APAD + lc)*2);
            CP16(d,           Agh + (size_t)it*32*a.lda);
            CP16(d + AST*2,   Agl + (size_t)it*32*a.lda);
        }
        uint32_t bb = base + 2*AST*2;
        #pragma unroll
        for (int it=0; it<JT; it++) {
            int r = lr + it*32;
            if (col0 + r < a.Nc) {
                uint32_t d = bb + (uint32_t)((r*APAD + lc)*2);
                CP16(d,         z.Bh + (size_t)(col0+r)*a.ldb + ch*64 + lc);
                CP16(d + BST*2, z.Bl + (size_t)(col0+r)*a.ldb + ch*64 + lc);
            }
        }
        asm volatile("cp.async.commit_group;");
    };

    float acc[4][JT][4] = {};
    issue(0, 0);
    for (int ch = 0; ch < nch; ch++) {
        int st = ch & 1;
        if (ch + 1 < nch) {
            issue(ch+1, st^1);
            asm volatile("cp.async.wait_group 1;");
        } else {
            asm volatile("cp.async.wait_group 0;");
        }
        __syncthreads();
        bf* Ash = smem + st*STAGE;
        bf* Asl = Ash + AST;
        bf* Bsh = Asl + AST;
        bf* Bsl = Bsh + BST;
        #pragma unroll
        for (int ks = 0; ks < 4; ks++) {
            int ak = ks*16 + (lane & 3)*2;
            int ar = wm*64 + (lane >> 2);
            uint32_t Afh[4][4], Afl[4][4], Bfh[JT][2], Bfl[JT][2];
            #pragma unroll
            for (int i = 0; i < 4; i++) {
                int base = (ar + i*16)*APAD + ak;
                Afh[i][0] = *(const uint32_t*)&Ash[base];
                Afh[i][1] = *(const uint32_t*)&Ash[base + 8*APAD];
                Afh[i][2] = *(const uint32_t*)&Ash[base + 8];
                Afh[i][3] = *(const uint32_t*)&Ash[base + 8*APAD + 8];
                Afl[i][0] = *(const uint32_t*)&Asl[base];
                Afl[i][1] = *(const uint32_t*)&Asl[base + 8*APAD];
                Afl[i][2] = *(const uint32_t*)&Asl[base + 8];
                Afl[i][3] = *(const uint32_t*)&Asl[base + 8*APAD + 8];
            }
            int bc = wn*8*JT + (lane >> 2);
            #pragma unroll
            for (int j = 0; j < JT; j++) {
                int base = (bc + j*8)*APAD + ak;
                Bfh[j][0] = *(const uint32_t*)&Bsh[base];
                Bfh[j][1] = *(const uint32_t*)&Bsh[base + 8];
                Bfl[j][0] = *(const uint32_t*)&Bsl[base];
                Bfl[j][1] = *(const uint32_t*)&Bsl[base + 8];
            }
            #pragma unroll
            for (int i = 0; i < 4; i++)
                #pragma unroll
                for (int j = 0; j < JT; j++) {
                    mma16816(acc[i][j], Afh[i], Bfh[j]);
                    mma16816(acc[i][j], Afh[i], Bfl[j]);
                    mma16816(acc[i][j], Afl[i], Bfh[j]);
                }
        }
        __syncthreads();
    }
    // epilogue
    #pragma unroll
    for (int i = 0; i < 4; i++) {
        #pragma unroll
        for (int j = 0; j < JT; j++) {
            int gr0 = row0 + wm*64 + i*16 + (lane >> 2);
            int gc  = col0 + wn*8*JT + j*8 + (lane & 3)*2;
            if (gc >= a.Nc) continue;
            #pragma unroll
            for (int h2 = 0; h2 < 2; h2++) {
                int gr = gr0 + h2*8;
                float v0 = acc[i][j][h2*2+0]*a.scale;
                float v1 = acc[i][j][h2*2+1]*a.scale;
                if (z.bias) {
                    if (a.bias_rows) { float bb=z.bias[gr]; v0+=bb; v1+=bb; }
                    else { v0+=z.bias[gc]; v1+=z.bias[gc+1]; }
                }
                if (z.res) {
                    v0 += z.res[(size_t)gr*a.ldo + gc];
                    v1 += z.res[(size_t)gr*a.ldo + gc + 1];
                }
                if (z.outF) {
                    z.outF[(size_t)gr*a.ldo + gc]   = v0;
                    z.outF[(size_t)gr*a.ldo + gc+1] = v1;
                }
                if (z.oh) {
                    bf h0=__float2bfloat16(v0), h1=__float2bfloat16(v1);
                    size_t o = (size_t)gr*a.ldh + gc;
                    z.oh[o]=h0;   z.oh[o+1]=h1;
                    z.ol[o]  =__float2bfloat16(v0-__bfloat162float(h0));
                    z.ol[o+1]=__float2bfloat16(v1-__bfloat162float(h1));
                }
            }
        }
    }
}
#define SMEMB4 ((2*(2*AST+2*128*APAD))*2)
#define SMEMB2 ((2*(2*AST+2*64*APAD))*2)

// ---------- conversions ----------
__global__ void wconv(const float* __restrict__ w, bf* __restrict__ oh, bf* __restrict__ ol,
                      int mode, size_t total) {
    size_t idx = (size_t)blockIdx.x*256 + threadIdx.x;
    if (idx >= total) return;
    size_t src = idx;
    if (mode==1) { int op=(idx>>8)&255; int o=(op&63)*4+(op>>6); src = (idx & ~(size_t)0xFF00) | ((size_t)o<<8); }
    else if (mode==2) { int cp=idx&255; int c=(cp&63)*4+(cp>>6); src = (idx & ~(size_t)0xFF) | (size_t)c; }
    float v = w[src];
    bf h = __float2bfloat16(v);
    oh[idx]=h; ol[idx]=__float2bfloat16(v-__bfloat162float(h));
}
__global__ void bias_perm(const float* __restrict__ pb, float* __restrict__ out) {
    int idx = blockIdx.x*256 + threadIdx.x;
    int op = idx & 255;
    out[idx] = pb[(idx & ~255) | ((op&63)*4 + (op>>6))];
}
struct TArgs { const float* in[2]; float* xF[2]; bf *yh[2], *yl[2]; };
__global__ void transpose_split(TArgs a) {
    __shared__ float tl[32][33];
    int zz = blockIdx.z, n0 = blockIdx.x*32, c0 = blockIdx.y*32;
    int tx = threadIdx.x&31, ty = threadIdx.x>>5;
    const float* in = a.in[zz];
    #pragma unroll
    for (int r=0;r<4;r++) tl[ty+r*8][tx] = in[(size_t)(c0+ty+r*8)*NN + n0+tx];
    __syncthreads();
    #pragma unroll
    for (int r=0;r<4;r++) {
        int n=n0+ty+r*8, c=c0+tx;
        float v = tl[tx][ty+r*8];
        a.xF[zz][(size_t)n*256+c]=v;
        bf h=__float2bfloat16(v);
        a.yh[zz][(size_t)n*512+c]=h;
        a.yl[zz][(size_t)n*512+c]=__float2bfloat16(v-__bfloat162float(h));
    }
}
__global__ void posenc_kernel(const float* __restrict__ kpts, const float* __restrict__ Wr,
                              float* __restrict__ cosv, float* __restrict__ sinv) {
    int idx = blockIdx.x*256 + threadIdx.x;
    if (idx >= NN*32) return;
    int p = idx & 31, n = idx >> 5;
    float kx = (kpts[2*n+0]-512.0f)*(1.0f/716.8f);
    float ky = (kpts[2*n+1]-384.0f)*(1.0f/716.8f);
    float pr = kx*Wr[2*p+0] + ky*Wr[2*p+1];
    cosv[idx] = cosf(pr); sinv[idx] = sinf(pr);
}
struct RArgs { const float* f[4]; bf *oh[4], *ol[4]; const float *cs[4], *sn[4]; };
__global__ void rope_split(RArgs a, int dorope) {
    int zz = blockIdx.y;
    int idx = blockIdx.x*256 + threadIdx.x;
    int pair = idx & 127, n = idx >> 7;
    int c = (pair>>5)*64 + 2*(pair&31);
    const float* f = a.f[zz];
    float x0 = f[(size_t)n*256+c], x1 = f[(size_t)n*256+c+1];
    if (dorope) {
        int p = pair&31;
        float cv = a.cs[zz][n*32+p], sv = a.sn[zz][n*32+p];
        float r0 = x0*cv - x1*sv, r1 = x1*cv + x0*sv;
        x0=r0; x1=r1;
    }
    bf h0=__float2bfloat16(x0), h1=__float2bfloat16(x1);
    a.oh[zz][(size_t)n*256+c]=h0;   a.oh[zz][(size_t)n*256+c+1]=h1;
    a.ol[zz][(size_t)n*256+c]=__float2bfloat16(x0-__bfloat162float(h0));
    a.ol[zz][(size_t)n*256+c+1]=__float2bfloat16(x1-__bfloat162float(h1));
}
__global__ void __launch_bounds__(256)
softmax_split(const float* __restrict__ S, bf* __restrict__ ph, bf* __restrict__ pl) {
    __shared__ float sm[8];
    size_t row = blockIdx.x;
    const float* p = S + row*NN;
    int t = threadIdx.x;
    float vals[8], mx=-1e30f;
    #pragma unroll
    for (int r=0;r<8;r++){ vals[r]=p[t+r*256]; mx=fmaxf(mx,vals[r]); }
    #pragma unroll
    for (int o=16;o>0;o>>=1) mx=fmaxf(mx,__shfl_xor_sync(0xffffffffu,mx,o));
    if ((t&31)==0) sm[t>>5]=mx;
    __syncthreads();
    mx=sm[0];
    #pragma unroll
    for (int i=1;i<8;i++) mx=fmaxf(mx,sm[i]);
    float s=0.f;
    #pragma unroll
    for (int r=0;r<8;r++){ vals[r]=__expf(vals[r]-mx); s+=vals[r]; }
    #pragma unroll
    for (int o=16;o>0;o>>=1) s+=__shfl_xor_sync(0xffffffffu,s,o);
    __syncthreads();
    if ((t&31)==0) sm[t>>5]=s;
    __syncthreads();
    s=0.f;
    #pragma unroll
    for (int i=0;i<8;i++) s+=sm[i];
    float inv=1.0f/s;
    #pragma unroll
    for (int r=0;r<8;r++) {
        float pv = vals[r]*inv;
        bf h=__float2bfloat16(pv);
        ph[row*NN+t+r*256]=h;
        pl[row*NN+t+r*256]=__float2bfloat16(pv-__bfloat162float(h));
    }
}
__global__ void __launch_bounds__(256)
bn_split(const float* __restrict__ hf, const float* __restrict__ g, const float* __restrict__ b,
         bf* __restrict__ oh, bf* __restrict__ ol) {
    __shared__ float ssum[4][64], ssq[4][64], sc[64], sh[64];
    size_t base = (size_t)blockIdx.y * HSZ;
    int l = threadIdx.x & 63, r0 = threadIdx.x >> 6;
    int c = blockIdx.x*64 + l;
    float su=0.f, sq=0.f;
    for (int n=r0; n<NN; n+=4) { float x = hf[base+(size_t)n*512+c]; su+=x; sq+=x*x; }
    ssum[r0][l]=su; ssq[r0][l]=sq;
    __syncthreads();
    if (r0==0) {
        float S=0,Q=0;
        #pragma unroll
        for (int i=0;i<4;i++){ S+=ssum[i][l]; Q+=ssq[i][l]; }
        float mean=S*(1.0f/NN), var=Q*(1.0f/NN)-mean*mean;
        float s1=g[c]*rsqrtf(var+1e-5f);
        sc[l]=s1; sh[l]=b[c]-mean*s1;
    }
    __syncthreads();
    float s1=sc[l], s2=sh[l];
    for (int n=r0; n<NN; n+=4) {
        float v=fmaxf(hf[base+(size_t)n*512+c]*s1+s2, 0.0f);
        bf h=__float2bfloat16(v);
        oh[base+(size_t)n*512+c]=h;
        ol[base+(size_t)n*512+c]=__float2bfloat16(v-__bfloat162float(h));
    }
}
// ---------- Sinkhorn ----------
__global__ void bins_kernel(float* __restrict__ C, const float* __restrict__ a) {
    int i = blockIdx.x*256 + threadIdx.x;
    if (i >= NP1) return;
    float v = a[0];
    C[(size_t)i*NP1 + NN] = v;
    C[(size_t)NN*NP1 + i] = v;
}
__global__ void zero_kernel(float* p, int n) { int i=blockIdx.x*256+threadIdx.x; if(i<n) p[i]=0.f; }
__global__ void __launch_bounds__(256)
u_update_kernel(const float* __restrict__ C, const float* __restrict__ vv, float* __restrict__ u) {
    __shared__ float sm[8];
    int i = blockIdx.x;
    const float* row = C + (size_t)i*NP1;
    int t = threadIdx.x;
    float mx = -1e30f;
    for (int j=t; j<NP1; j+=256) mx = fmaxf(mx, row[j]+vv[j]);
    #pragma unroll
    for (int o=16;o>0;o>>=1) mx=fmaxf(mx,__shfl_xor_sync(0xffffffffu,mx,o));
    if ((t&31)==0) sm[t>>5]=mx;
    __syncthreads();
    mx=sm[0];
    #pragma unroll
    for (int w=1;w<8;w++) mx=fmaxf(mx,sm[w]);
    float s=0.f;
    for (int j=t; j<NP1; j+=256) s += __expf(row[j]+vv[j]-mx);
    #pragma unroll
    for (int o=16;o>0;o>>=1) s+=__shfl_xor_sync(0xffffffffu,s,o);
    __syncthreads();
    if ((t&31)==0) sm[t>>5]=s;
    __syncthreads();
    s=0.f;
    #pragma unroll
    for (int w=0;w<8;w++) s+=sm[w];
    if (t==0) u[i] = ((i<NN)?NORMC:(LOGN+NORMC)) - (mx + logf(s));
}
__global__ void v_part_kernel(const float* __restrict__ C, const float* __restrict__ u,
                              float* __restrict__ pm, float* __restrict__ ps) {
    int j = blockIdx.x*256 + threadIdx.x;
    if (j >= NP1) return;
    int rc = blockIdx.y, i0 = rc*129, i1 = min(i0+129, NP1);
    float m=-1e30f, s=0.f;
    for (int i=i0; i<i1; i++) {
        float x = C[(size_t)i*NP1+j] + u[i];
        if (x>m) { s=s*__expf(m-x)+1.f; m=x; } else s+=__expf(x-m);
    }
    pm[rc*NP1+j]=m; ps[rc*NP1+j]=s;
}
__global__ void v_combine_kernel(const float* __restrict__ pm, const float* __restrict__ ps,
                                 float* __restrict__ vv) {
    int j = blockIdx.x*256 + threadIdx.x;
    if (j >= NP1) return;
    float M=-1e30f;
    #pragma unroll
    for (int rc=0;rc<16;rc++) M=fmaxf(M, pm[rc*NP1+j]);
    float S=0.f;
    #pragma unroll
    for (int rc=0;rc<16;rc++) S+=ps[rc*NP1+j]*__expf(pm[rc*NP1+j]-M);
    vv[j] = ((j<NN)?NORMC:(LOGN+NORMC)) - (M + logf(S));
}
__global__ void final_add_kernel(float* __restrict__ C, const float* __restrict__ u,
                                 const float* __restrict__ vv) {
    int idx = blockIdx.x*256 + threadIdx.x;
    if (idx >= NP1*NP1) return;
    C[idx] += u[idx/NP1] + vv[idx%NP1] + LOG4096;
}

// ---------- host ----------
#define GSA(p,s) cudaGetSymbolAddress((void**)&(p), s)
extern "C" void kernel_launch(void* const* d_in, const int* in_sizes, int n_in,
                              void* d_out, int out_size) {
    (void)in_sizes; (void)n_in; (void)out_size;
    const float *desc0=(const float*)d_in[0], *desc1=(const float*)d_in[1];
    const float *kpts0=(const float*)d_in[2], *kpts1=(const float*)d_in[3];
    const float *Wr=(const float*)d_in[4], *proj_w=(const float*)d_in[5];
    const float *proj_b=(const float*)d_in[6];
    const float *merge_w=(const float*)d_in[7], *merge_b=(const float*)d_in[8];
    const float *mlp_w1=(const float*)d_in[9], *mlp_b1=(const float*)d_in[10];
    const float *bn_g=(const float*)d_in[11], *bn_b=(const float*)d_in[12];
    const float *mlp_w2=(const float*)d_in[13], *mlp_b2=(const float*)d_in[14];
    const float *fp_w=(const float*)d_in[15], *fp_b=(const float*)d_in[16];
    const float *binsc=(const float*)d_in[17];
    float* C = (float*)d_out;

    cudaFuncSetAttribute(mma_gemm<4>, cudaFuncAttributeMaxDynamicSharedMemorySize, SMEMB4);
    cudaFuncSetAttribute(mma_gemm<2>, cudaFuncAttributeMaxDynamicSharedMemorySize, SMEMB2);

    float *xF,*qf,*kf,*hf,*pbp,*cs,*pu,*pvv,*ppm,*pps,*S;
    bf *yh,*yl,*qh,*ql,*kh,*kl,*vh,*vl,*aoh,*aol,*hh,*hl,*ph,*pl;
    bf *wqh,*wql,*wmh,*wml,*w1h,*w1l,*w2h,*w2l,*fph,*fpl;
    GSA(xF,g_xF); GSA(qf,g_qf); GSA(kf,g_kf); GSA(hf,g_hf);
    GSA(yh,g_yh); GSA(yl,g_yl); GSA(qh,g_qh); GSA(ql,g_ql);
    GSA(kh,g_kh); GSA(kl,g_kl); GSA(vh,g_vh); GSA(vl,g_vl);
    GSA(aoh,g_aoh); GSA(aol,g_aol); GSA(hh,g_hh); GSA(hl,g_hl);
    GSA(S,g_S); GSA(ph,g_ph); GSA(pl,g_pl);
    GSA(wqh,g_wqh); GSA(wql,g_wql); GSA(wmh,g_wmh); GSA(wml,g_wml);
    GSA(w1h,g_w1h); GSA(w1l,g_w1l); GSA(w2h,g_w2h); GSA(w2l,g_w2l);
    GSA(fph,g_fph); GSA(fpl,g_fpl); GSA(pbp,g_pbp); GSA(cs,g_cs);
    GSA(pu,g_u); GSA(pvv,g_vv); GSA(ppm,g_pm); GSA(pps,g_ps);
    float *c0=cs, *s0=cs+NN*32, *c1=cs+2*NN*32, *s1=cs+3*NN*32;

    wconv<<<30*65536/256,256>>>(proj_w, wqh, wql, 1, (size_t)30*65536);
    wconv<<<10*65536/256,256>>>(merge_w, wmh, wml, 2, (size_t)10*65536);
    wconv<<<10*262144/256,256>>>(mlp_w1, w1h, w1l, 0, (size_t)10*262144);
    wconv<<<10*131072/256,256>>>(mlp_w2, w2h, w2l, 0, (size_t)10*131072);
    wconv<<<65536/256,256>>>(fp_w, fph, fpl, 0, 65536);
    bias_perm<<<30,256>>>(proj_b, pbp);
    posenc_kernel<<<NN*32/256,256>>>(kpts0, Wr, c0, s0);
    posenc_kernel<<<NN*32/256,256>>>(kpts1, Wr, c1, s1);
    TArgs ta;
    ta.in[0]=desc0; ta.in[1]=desc1;
    for (int s=0;s<2;s++){ ta.xF[s]=xF+s*SZ; ta.yh[s]=yh+s*HSZ; ta.yl[s]=yl+s*HSZ; }
    transpose_split<<<dim3(64,8,2),256>>>(ta);

    for (int l=0; l<10; l++) {
        int even = !(l&1);
        int src[2] = { even?0:1, even?1:0 };
        const float* mb  = merge_b + l*256;
        const float* b1  = mlp_b1 + l*512;
        const float* b2  = mlp_b2 + l*256;

        // q,k projections (fp32 out for RoPE): z={q0,k0,q1,k1}
        MArgs mq = {};
        mq.lda=512; mq.ldb=256; mq.ldo=256; mq.ldh=256; mq.K=256; mq.Nc=256; mq.scale=1.f;
        for (int s=0;s<2;s++) {
            MZ* zq=&mq.z[s*2], *zk=&mq.z[s*2+1];
            zq->Ah=yh+s*HSZ; zq->Al=yl+s*HSZ;
            zq->Bh=wqh+(size_t)(l*3)*65536; zq->Bl=wql+(size_t)(l*3)*65536;
            zq->bias=pbp+(l*3)*256; zq->outF=qf+s*SZ;
            zk->Ah=yh+src[s]*HSZ; zk->Al=yl+src[s]*HSZ;
            zk->Bh=wqh+(size_t)(l*3+1)*65536; zk->Bl=wql+(size_t)(l*3+1)*65536;
            zk->bias=pbp+(l*3+1)*256; zk->outF=kf+s*SZ;
        }
        mma_gemm<4><<<dim3(16,2,4),256,SMEMB4>>>(mq);

        // v projection, output transposed [c][m] as hi/lo
        MArgs mv = {};
        mv.lda=256; mv.ldb=512; mv.ldo=2048; mv.ldh=2048; mv.K=256; mv.Nc=2048;
        mv.scale=1.f; mv.bias_rows=1;
        for (int s=0;s<2;s++) {
            MZ* zv=&mv.z[s];
            zv->Ah=wqh+(size_t)(l*3+2)*65536; zv->Al=wql+(size_t)(l*3+2)*65536;
            zv->Bh=yh+src[s]*HSZ; zv->Bl=yl+src[s]*HSZ;
            zv->bias=pbp+(l*3+2)*256; zv->oh=vh+s*SZ; zv->ol=vl+s*SZ;
        }
        mma_gemm<4><<<dim3(2,16,2),256,SMEMB4>>>(mv);

        // rope (even) or plain split (odd)
        RArgs ra;
        ra.f[0]=qf; ra.f[1]=kf; ra.f[2]=qf+SZ; ra.f[3]=kf+SZ;
        ra.oh[0]=qh; ra.ol[0]=ql; ra.oh[1]=kh; ra.ol[1]=kl;
        ra.oh[2]=qh+SZ; ra.ol[2]=ql+SZ; ra.oh[3]=kh+SZ; ra.ol[3]=kl+SZ;
        ra.cs[0]=c0; ra.sn[0]=s0; ra.cs[1]=c0; ra.sn[1]=s0;
        ra.cs[2]=c1; ra.sn[2]=s1; ra.cs[3]=c1; ra.sn[3]=s1;
        rope_split<<<dim3(1024,4),256>>>(ra, even);

        // scores (per head-stream slice)
        MArgs ms = {};
        ms.lda=256; ms.ldb=256; ms.ldo=2048; ms.K=64; ms.Nc=2048; ms.scale=0.125f;
        for (int s=0;s<2;s++) for (int h=0;h<4;h++) {
            MZ* zz=&ms.z[s*4+h];
            zz->Ah=qh+s*SZ+h*64; zz->Al=ql+s*SZ+h*64;
            zz->Bh=kh+s*SZ+h*64; zz->Bl=kl+s*SZ+h*64;
            zz->outF=S+(size_t)(s*4+h)*PSZ;
        }
        mma_gemm<4><<<dim3(16,16,8),256,SMEMB4>>>(ms);
        softmax_split<<<8*NN,256>>>(S, ph, pl);

        // attn out: rows n, cols hd (64), K=2048 — JT=2 tile, no wasted MMA
        MArgs mo = {};
        mo.lda=2048; mo.ldb=2048; mo.ldh=256; mo.K=2048; mo.Nc=64; mo.scale=1.f;
        for (int s=0;s<2;s++) for (int h=0;h<4;h++) {
            MZ* zz=&mo.z[s*4+h];
            zz->Ah=ph+(size_t)(s*4+h)*PSZ; zz->Al=pl+(size_t)(s*4+h)*PSZ;
            zz->Bh=vh+s*SZ+(size_t)(h*64)*2048; zz->Bl=vl+s*SZ+(size_t)(h*64)*2048;
            zz->oh=aoh+s*SZ+h*64; zz->ol=aol+s*SZ+h*64;
        }
        mma_gemm<2><<<dim3(16,1,8),256,SMEMB2>>>(mo);

        // merge -> y cols 256:511
        MArgs mm = {};
        mm.lda=256; mm.ldb=256; mm.ldh=512; mm.K=256; mm.Nc=256; mm.scale=1.f;
        for (int s=0;s<2;s++) {
            MZ* zz=&mm.z[s];
            zz->Ah=aoh+s*SZ; zz->Al=aol+s*SZ;
            zz->Bh=wmh+(size_t)l*65536; zz->Bl=wml+(size_t)l*65536;
            zz->bias=mb; zz->oh=yh+s*HSZ+256; zz->ol=yl+s*HSZ+256;
        }
        mma_gemm<4><<<dim3(16,2,2),256,SMEMB4>>>(mm);

        // mlp1 -> h fp32
        MArgs m1 = {};
        m1.lda=512; m1.ldb=512; m1.ldo=512; m1.K=512; m1.Nc=512; m1.scale=1.f;
        for (int s=0;s<2;s++) {
            MZ* zz=&m1.z[s];
            zz->Ah=yh+s*HSZ; zz->Al=yl+s*HSZ;
            zz->Bh=w1h+(size_t)l*262144; zz->Bl=w1l+(size_t)l*262144;
            zz->bias=b1; zz->outF=hf+s*HSZ;
        }
        mma_gemm<4><<<dim3(16,4,2),256,SMEMB4>>>(m1);
        bn_split<<<dim3(8,2),256>>>(hf, bn_g+l*512, bn_b+l*512, hh, hl);

        // mlp2 + residual -> xF + y cols 0:255
        MArgs m2 = {};
        m2.lda=512; m2.ldb=512; m2.ldo=256; m2.ldh=512; m2.K=512; m2.Nc=256; m2.scale=1.f;
        for (int s=0;s<2;s++) {
            MZ* zz=&m2.z[s];
            zz->Ah=hh+s*HSZ; zz->Al=hl+s*HSZ;
            zz->Bh=w2h+(size_t)l*131072; zz->Bl=w2l+(size_t)l*131072;
            zz->bias=b2; zz->res=xF+s*SZ; zz->outF=xF+s*SZ;
            zz->oh=yh+s*HSZ; zz->ol=yl+s*HSZ;
        }
        mma_gemm<4><<<dim3(16,2,2),256,SMEMB4>>>(m2);
    }

    // final projection
    MArgs mf = {};
    mf.lda=512; mf.ldb=256; mf.ldh=256; mf.K=256; mf.Nc=256; mf.scale=1.f;
    for (int s=0;s<2;s++) {
        MZ* zz=&mf.z[s];
        zz->Ah=yh+s*HSZ; zz->Al=yl+s*HSZ;
        zz->Bh=fph; zz->Bl=fpl;
        zz->bias=fp_b; zz->oh=qh+s*SZ; zz->ol=ql+s*SZ;
    }
    mma_gemm<4><<<dim3(16,2,2),256,SMEMB4>>>(mf);

    // final match scores into C (ld 2049)
    MArgs mc = {};
    mc.lda=256; mc.ldb=256; mc.ldo=NP1; mc.K=256; mc.Nc=2048; mc.scale=0.0625f;
    mc.z[0].Ah=qh; mc.z[0].Al=ql; mc.z[0].Bh=qh+SZ; mc.z[0].Bl=ql+SZ;
    mc.z[0].outF=C;
    mma_gemm<4><<<dim3(16,16,1),256,SMEMB4>>>(mc);
    bins_kernel<<<(NP1+255)/256,256>>>(C, binsc);

    zero_kernel<<<(NP1+255)/256,256>>>(pvv, NP1);
    for (int t=0; t<20; t++) {
        u_update_kernel<<<NP1,256>>>(C, pvv, pu);
        v_part_kernel<<<dim3((NP1+255)/256,16),256>>>(C, pu, ppm, pps);
        v_combine_kernel<<<(NP1+255)/256,256>>>(ppm, pps, pvv);
    }
    final_add_kernel<<<(NP1*NP1+255)/256,256>>>(C, pu, pvv);
}

// round 7
// speedup vs baseline: 2.6088x; 1.3256x over previous
#include <cuda_runtime.h>
#include <cuda_bf16.h>
#include <math.h>
#include <stdint.h>

#define NN 2048
#define DM 256
#define NP1 2049
#define NORMC (-8.317766166719343f)
#define LOGN (7.624618986159398f)
#define LOG4096 (8.317766166719343f)
#define SZ ((size_t)NN*DM)
#define HSZ ((size_t)NN*512)
typedef __nv_bfloat16 bf;

// ---------- static scratch ----------
__device__ float g_xF[2*SZ], g_qf[2*SZ], g_kf[2*SZ], g_hf[2*HSZ];
__device__ bf g_yh[2*HSZ], g_yl[2*HSZ];
__device__ bf g_qh[2*SZ], g_ql[2*SZ], g_kh[2*SZ], g_kl[2*SZ];
__device__ bf g_vh[2*SZ], g_vl[2*SZ], g_aoh[2*SZ], g_aol[2*SZ];
__device__ bf g_hh[2*HSZ], g_hl[2*HSZ];
__device__ bf g_wqh[30*65536], g_wql[30*65536], g_wmh[10*65536], g_wml[10*65536];
__device__ bf g_w1h[10*262144], g_w1l[10*262144], g_w2h[10*131072], g_w2l[10*131072];
__device__ bf g_fph[65536], g_fpl[65536];
__device__ float g_pbp[30*256];
__device__ float g_cs[4*NN*32];
__device__ float g_u[NP1], g_vv[NP1], g_pm[16*NP1], g_ps[16*NP1];

// ---------- HMMA m16n8k16 bf16 ----------
__device__ __forceinline__ void mma16816(float* c, const uint32_t* a, const uint32_t* b) {
    asm volatile("mma.sync.aligned.m16n8k16.row.col.f32.bf16.bf16.f32 "
        "{%0,%1,%2,%3}, {%4,%5,%6,%7}, {%8,%9}, {%0,%1,%2,%3};"
        : "+f"(c[0]), "+f"(c[1]), "+f"(c[2]), "+f"(c[3])
        : "r"(a[0]), "r"(a[1]), "r"(a[2]), "r"(a[3]), "r"(b[0]), "r"(b[1]));
}
#define CP16(dst, src) asm volatile("cp.async.ca.shared.global [%0], [%1], 16;" :: "r"(dst), "l"(src))

__device__ __forceinline__ uint32_t pkbf(float x, float y) {
    __nv_bfloat162 t = __floats2bfloat162_rn(x, y);
    return *(uint32_t*)&t;
}
__device__ __forceinline__ void split2(float x, float y, uint32_t& hi, uint32_t& lo) {
    bf hx = __float2bfloat16(x), hy = __float2bfloat16(y);
    __nv_bfloat162 hp; hp.x = hx; hp.y = hy;
    hi = *(uint32_t*)&hp;
    lo = pkbf(x - __bfloat162float(hx), y - __bfloat162float(hy));
}

// ---------- generic split-bf16 HMMA GEMM, cp.async double-buffered ----------
struct MZ { const bf *Ah,*Al,*Bh,*Bl; const float *bias,*res; float *outF; bf *oh,*ol; };
struct MArgs { MZ z[8]; int lda,ldb,ldo,ldh,K,Nc,bias_rows; float scale; };

#define APAD 72
#define AST (128*APAD)

template<int JT>
__global__ void __launch_bounds__(256) mma_gemm(MArgs a) {
    constexpr int CTAC = 32*JT;
    constexpr int BST = CTAC*APAD;
    constexpr int STAGE = 2*AST + 2*BST;
    extern __shared__ bf smem[];
    MZ z = a.z[blockIdx.z];
    int t = threadIdx.x, w = t>>5, lane = t&31;
    int wm = w & 1, wn = w >> 1;
    int row0 = blockIdx.x*128, col0 = blockIdx.y*CTAC;
    uint32_t smb = (uint32_t)__cvta_generic_to_shared(smem);
    int lr = t >> 3, lc = (t & 7) * 8;
    int nch = a.K >> 6;

    auto issue = [&](int ch, int st) {
        uint32_t base = smb + (uint32_t)(st*STAGE*2);
        const bf* Agh = z.Ah + (size_t)(row0+lr)*a.lda + ch*64 + lc;
        const bf* Agl = z.Al + (size_t)(row0+lr)*a.lda + ch*64 + lc;
        #pragma unroll
        for (int it=0; it<4; it++) {
            uint32_t d = base + (uint32_t)(((lr+it*32)*APAD + lc)*2);
            CP16(d,           Agh + (size_t)it*32*a.lda);
            CP16(d + AST*2,   Agl + (size_t)it*32*a.lda);
        }
        uint32_t bb = base + 2*AST*2;
        #pragma unroll
        for (int it=0; it<JT; it++) {
            int r = lr + it*32;
            if (col0 + r < a.Nc) {
                uint32_t d = bb + (uint32_t)((r*APAD + lc)*2);
                CP16(d,         z.Bh + (size_t)(col0+r)*a.ldb + ch*64 + lc);
                CP16(d + BST*2, z.Bl + (size_t)(col0+r)*a.ldb + ch*64 + lc);
            }
        }
        asm volatile("cp.async.commit_group;");
    };

    float acc[4][JT][4] = {};
    issue(0, 0);
    for (int ch = 0; ch < nch; ch++) {
        int st = ch & 1;
        if (ch + 1 < nch) {
            issue(ch+1, st^1);
            asm volatile("cp.async.wait_group 1;");
        } else {
            asm volatile("cp.async.wait_group 0;");
        }
        __syncthreads();
        bf* Ash = smem + st*STAGE;
        bf* Asl = Ash + AST;
        bf* Bsh = Asl + AST;
        bf* Bsl = Bsh + BST;
        #pragma unroll
        for (int ks = 0; ks < 4; ks++) {
            int ak = ks*16 + (lane & 3)*2;
            int ar = wm*64 + (lane >> 2);
            uint32_t Afh[4][4], Afl[4][4], Bfh[JT][2], Bfl[JT][2];
            #pragma unroll
            for (int i = 0; i < 4; i++) {
                int base = (ar + i*16)*APAD + ak;
                Afh[i][0] = *(const uint32_t*)&Ash[base];
                Afh[i][1] = *(const uint32_t*)&Ash[base + 8*APAD];
                Afh[i][2] = *(const uint32_t*)&Ash[base + 8];
                Afh[i][3] = *(const uint32_t*)&Ash[base + 8*APAD + 8];
                Afl[i][0] = *(const uint32_t*)&Asl[base];
                Afl[i][1] = *(const uint32_t*)&Asl[base + 8*APAD];
                Afl[i][2] = *(const uint32_t*)&Asl[base + 8];
                Afl[i][3] = *(const uint32_t*)&Asl[base + 8*APAD + 8];
            }
            int bc = wn*8*JT + (lane >> 2);
            #pragma unroll
            for (int j = 0; j < JT; j++) {
                int base = (bc + j*8)*APAD + ak;
                Bfh[j][0] = *(const uint32_t*)&Bsh[base];
                Bfh[j][1] = *(const uint32_t*)&Bsh[base + 8];
                Bfl[j][0] = *(const uint32_t*)&Bsl[base];
                Bfl[j][1] = *(const uint32_t*)&Bsl[base + 8];
            }
            #pragma unroll
            for (int i = 0; i < 4; i++)
                #pragma unroll
                for (int j = 0; j < JT; j++) {
                    mma16816(acc[i][j], Afh[i], Bfh[j]);
                    mma16816(acc[i][j], Afh[i], Bfl[j]);
                    mma16816(acc[i][j], Afl[i], Bfh[j]);
                }
        }
        __syncthreads();
    }
    #pragma unroll
    for (int i = 0; i < 4; i++) {
        #pragma unroll
        for (int j = 0; j < JT; j++) {
            int gr0 = row0 + wm*64 + i*16 + (lane >> 2);
            int gc  = col0 + wn*8*JT + j*8 + (lane & 3)*2;
            if (gc >= a.Nc) continue;
            #pragma unroll
            for (int h2 = 0; h2 < 2; h2++) {
                int gr = gr0 + h2*8;
                float v0 = acc[i][j][h2*2+0]*a.scale;
                float v1 = acc[i][j][h2*2+1]*a.scale;
                if (z.bias) {
                    if (a.bias_rows) { float bb=z.bias[gr]; v0+=bb; v1+=bb; }
                    else { v0+=z.bias[gc]; v1+=z.bias[gc+1]; }
                }
                if (z.res) {
                    v0 += z.res[(size_t)gr*a.ldo + gc];
                    v1 += z.res[(size_t)gr*a.ldo + gc + 1];
                }
                if (z.outF) {
                    z.outF[(size_t)gr*a.ldo + gc]   = v0;
                    z.outF[(size_t)gr*a.ldo + gc+1] = v1;
                }
                if (z.oh) {
                    bf h0=__float2bfloat16(v0), h1=__float2bfloat16(v1);
                    size_t o = (size_t)gr*a.ldh + gc;
                    z.oh[o]=h0;   z.oh[o+1]=h1;
                    z.ol[o]  =__float2bfloat16(v0-__bfloat162float(h0));
                    z.ol[o+1]=__float2bfloat16(v1-__bfloat162float(h1));
                }
            }
        }
    }
}
#define SMEMB4 ((2*(2*AST+2*128*APAD))*2)

// ---------- flash attention: scores + online softmax + P*V fused ----------
#define KP 72
#define VP 136
#define FK_L (128*KP)               /* elem offset of K-lo  */
#define FV_H (2*128*KP)             /* elem offset of V-hi  */
#define FV_L (2*128*KP + 64*VP)     /* elem offset of V-lo  */
#define FSTAGE (2*128*KP + 2*64*VP) /* elems per stage      */
#define FSMEM_B (2*FSTAGE*2)        /* bytes total          */

__global__ void __launch_bounds__(256)
flash_attn(const bf* __restrict__ qh_, const bf* __restrict__ ql_,
           const bf* __restrict__ kh_, const bf* __restrict__ kl_,
           const bf* __restrict__ vh_, const bf* __restrict__ vl_,
           bf* __restrict__ aoh_, bf* __restrict__ aol_) {
    extern __shared__ bf fsm[];
    int slice = blockIdx.y;
    int s = slice >> 2, h = slice & 3;
    const bf* qgh = qh_ + (size_t)s*SZ;
    const bf* qgl = ql_ + (size_t)s*SZ;
    const bf* kgh = kh_ + (size_t)s*SZ;
    const bf* kgl = kl_ + (size_t)s*SZ;
    const bf* vgh = vh_ + (size_t)s*SZ + (size_t)(h*64)*2048;
    const bf* vgl = vl_ + (size_t)s*SZ + (size_t)(h*64)*2048;
    bf* outh = aoh_ + (size_t)s*SZ;
    bf* outl = aol_ + (size_t)s*SZ;
    int hcol = h*64;
    int t = threadIdx.x, w = t>>5, lane = t&31;
    int qrow = blockIdx.x*128 + w*16 + (lane>>2);
    uint32_t smb = (uint32_t)__cvta_generic_to_shared(fsm);

    // preload Q fragments (rows qrow, qrow+8; cols hcol + ks*16 ...)
    uint32_t Aqh[4][4], Aql[4][4];
    #pragma unroll
    for (int ks=0; ks<4; ks++) {
        int cb = hcol + ks*16 + (lane&3)*2;
        Aqh[ks][0] = *(const uint32_t*)&qgh[(size_t)qrow*256 + cb];
        Aqh[ks][1] = *(const uint32_t*)&qgh[(size_t)(qrow+8)*256 + cb];
        Aqh[ks][2] = *(const uint32_t*)&qgh[(size_t)qrow*256 + cb + 8];
        Aqh[ks][3] = *(const uint32_t*)&qgh[(size_t)(qrow+8)*256 + cb + 8];
        Aql[ks][0] = *(const uint32_t*)&qgl[(size_t)qrow*256 + cb];
        Aql[ks][1] = *(const uint32_t*)&qgl[(size_t)(qrow+8)*256 + cb];
        Aql[ks][2] = *(const uint32_t*)&qgl[(size_t)qrow*256 + cb + 8];
        Aql[ks][3] = *(const uint32_t*)&qgl[(size_t)(qrow+8)*256 + cb + 8];
    }

    auto issue = [&](int ch, int st) {
        uint32_t base = smb + (uint32_t)(st*FSTAGE*2);
        int key0 = ch*128;
        int kr = t>>1, kc = (t&1)*32;
        const bf* skh = kgh + (size_t)(key0+kr)*256 + hcol + kc;
        const bf* skl = kgl + (size_t)(key0+kr)*256 + hcol + kc;
        #pragma unroll
        for (int i=0;i<4;i++) {
            uint32_t d = base + (uint32_t)((kr*KP + kc + i*8)*2);
            CP16(d,           skh + i*8);
            CP16(d + FK_L*2,  skl + i*8);
        }
        int vr = t>>2, vc = (t&3)*32;
        const bf* svh = vgh + (size_t)vr*2048 + key0 + vc;
        const bf* svl = vgl + (size_t)vr*2048 + key0 + vc;
        #pragma unroll
        for (int i=0;i<4;i++) {
            uint32_t d = base + (uint32_t)((FV_H + vr*VP + vc + i*8)*2);
            CP16(d,                 svh + i*8);
            CP16(d + (FV_L-FV_H)*2, svl + i*8);
        }
        asm volatile("cp.async.commit_group;");
    };

    float m_run[2] = {-1e30f, -1e30f};
    float s_run[2] = {0.f, 0.f};
    float oacc[8][4] = {};

    issue(0, 0);
    for (int ch = 0; ch < 16; ch++) {
        int st = ch & 1;
        if (ch + 1 < 16) { issue(ch+1, st^1); asm volatile("cp.async.wait_group 1;"); }
        else             { asm volatile("cp.async.wait_group 0;"); }
        __syncthreads();
        bf* Kh = fsm + st*FSTAGE;
        bf* Kl = Kh + FK_L;
        bf* Vh = fsm + st*FSTAGE + FV_H;
        bf* Vl = fsm + st*FSTAGE + FV_L;

        // S = Q K^T chunk (16 j-tiles of 8 keys)
        float sacc[16][4] = {};
        #pragma unroll
        for (int ks = 0; ks < 4; ks++) {
            int ak = ks*16 + (lane&3)*2;
            #pragma unroll
            for (int j = 0; j < 16; j++) {
                int base = (j*8 + (lane>>2))*KP + ak;
                uint32_t Bh[2] = { *(const uint32_t*)&Kh[base], *(const uint32_t*)&Kh[base+8] };
                uint32_t Bl[2] = { *(const uint32_t*)&Kl[base], *(const uint32_t*)&Kl[base+8] };
                mma16816(sacc[j], Aqh[ks], Bh);
                mma16816(sacc[j], Aqh[ks], Bl);
                mma16816(sacc[j], Aql[ks], Bh);
            }
        }
        // scale + online softmax
        float mx0 = -1e30f, mx1 = -1e30f;
        #pragma unroll
        for (int j = 0; j < 16; j++) {
            sacc[j][0]*=0.125f; sacc[j][1]*=0.125f; sacc[j][2]*=0.125f; sacc[j][3]*=0.125f;
            mx0 = fmaxf(mx0, fmaxf(sacc[j][0], sacc[j][1]));
            mx1 = fmaxf(mx1, fmaxf(sacc[j][2], sacc[j][3]));
        }
        mx0 = fmaxf(mx0, __shfl_xor_sync(0xffffffffu, mx0, 1));
        mx0 = fmaxf(mx0, __shfl_xor_sync(0xffffffffu, mx0, 2));
        mx1 = fmaxf(mx1, __shfl_xor_sync(0xffffffffu, mx1, 1));
        mx1 = fmaxf(mx1, __shfl_xor_sync(0xffffffffu, mx1, 2));
        float nm0 = fmaxf(m_run[0], mx0), nm1 = fmaxf(m_run[1], mx1);
        float al0 = __expf(m_run[0]-nm0), al1 = __expf(m_run[1]-nm1);
        float cs0 = 0.f, cs1 = 0.f;
        #pragma unroll
        for (int j = 0; j < 16; j++) {
            float p0=__expf(sacc[j][0]-nm0), p1=__expf(sacc[j][1]-nm0);
            float p2=__expf(sacc[j][2]-nm1), p3=__expf(sacc[j][3]-nm1);
            sacc[j][0]=p0; sacc[j][1]=p1; sacc[j][2]=p2; sacc[j][3]=p3;
            cs0 += p0+p1; cs1 += p2+p3;
        }
        cs0 += __shfl_xor_sync(0xffffffffu, cs0, 1);
        cs0 += __shfl_xor_sync(0xffffffffu, cs0, 2);
        cs1 += __shfl_xor_sync(0xffffffffu, cs1, 1);
        cs1 += __shfl_xor_sync(0xffffffffu, cs1, 2);
        s_run[0] = s_run[0]*al0 + cs0;
        s_run[1] = s_run[1]*al1 + cs1;
        m_run[0] = nm0; m_run[1] = nm1;
        #pragma unroll
        for (int j2 = 0; j2 < 8; j2++) {
            oacc[j2][0]*=al0; oacc[j2][1]*=al0; oacc[j2][2]*=al1; oacc[j2][3]*=al1;
        }
        // O += P V  (P from registers: C-frag -> A-frag identity)
        #pragma unroll
        for (int kk = 0; kk < 8; kk++) {
            uint32_t Pah[4], Pal[4];
            split2(sacc[2*kk  ][0], sacc[2*kk  ][1], Pah[0], Pal[0]);
            split2(sacc[2*kk  ][2], sacc[2*kk  ][3], Pah[1], Pal[1]);
            split2(sacc[2*kk+1][0], sacc[2*kk+1][1], Pah[2], Pal[2]);
            split2(sacc[2*kk+1][2], sacc[2*kk+1][3], Pah[3], Pal[3]);
            int vk = kk*16 + (lane&3)*2;
            #pragma unroll
            for (int j2 = 0; j2 < 8; j2++) {
                int base = (j2*8 + (lane>>2))*VP + vk;
                uint32_t Bh[2] = { *(const uint32_t*)&Vh[base], *(const uint32_t*)&Vh[base+8] };
                uint32_t Bl[2] = { *(const uint32_t*)&Vl[base], *(const uint32_t*)&Vl[base+8] };
                mma16816(oacc[j2], Pah, Bh);
                mma16816(oacc[j2], Pah, Bl);
                mma16816(oacc[j2], Pal, Bh);
            }
        }
        __syncthreads();
    }
    // normalize + write hi/lo
    float inv0 = 1.0f/s_run[0], inv1 = 1.0f/s_run[1];
    #pragma unroll
    for (int j2 = 0; j2 < 8; j2++) {
        int col = hcol + j2*8 + (lane&3)*2;
        uint32_t hi, lo;
        split2(oacc[j2][0]*inv0, oacc[j2][1]*inv0, hi, lo);
        *(uint32_t*)&outh[(size_t)qrow*256 + col] = hi;
        *(uint32_t*)&outl[(size_t)qrow*256 + col] = lo;
        split2(oacc[j2][2]*inv1, oacc[j2][3]*inv1, hi, lo);
        *(uint32_t*)&outh[(size_t)(qrow+8)*256 + col] = hi;
        *(uint32_t*)&outl[(size_t)(qrow+8)*256 + col] = lo;
    }
}

// ---------- conversions ----------
__global__ void wconv(const float* __restrict__ w, bf* __restrict__ oh, bf* __restrict__ ol,
                      int mode, size_t total) {
    size_t idx = (size_t)blockIdx.x*256 + threadIdx.x;
    if (idx >= total) return;
    size_t src = idx;
    if (mode==1) { int op=(idx>>8)&255; int o=(op&63)*4+(op>>6); src = (idx & ~(size_t)0xFF00) | ((size_t)o<<8); }
    else if (mode==2) { int cp=idx&255; int c=(cp&63)*4+(cp>>6); src = (idx & ~(size_t)0xFF) | (size_t)c; }
    float v = w[src];
    bf h = __float2bfloat16(v);
    oh[idx]=h; ol[idx]=__float2bfloat16(v-__bfloat162float(h));
}
__global__ void bias_perm(const float* __restrict__ pb, float* __restrict__ out) {
    int idx = blockIdx.x*256 + threadIdx.x;
    int op = idx & 255;
    out[idx] = pb[(idx & ~255) | ((op&63)*4 + (op>>6))];
}
struct TArgs { const float* in[2]; float* xF[2]; bf *yh[2], *yl[2]; };
__global__ void transpose_split(TArgs a) {
    __shared__ float tl[32][33];
    int zz = blockIdx.z, n0 = blockIdx.x*32, c0 = blockIdx.y*32;
    int tx = threadIdx.x&31, ty = threadIdx.x>>5;
    const float* in = a.in[zz];
    #pragma unroll
    for (int r=0;r<4;r++) tl[ty+r*8][tx] = in[(size_t)(c0+ty+r*8)*NN + n0+tx];
    __syncthreads();
    #pragma unroll
    for (int r=0;r<4;r++) {
        int n=n0+ty+r*8, c=c0+tx;
        float v = tl[tx][ty+r*8];
        a.xF[zz][(size_t)n*256+c]=v;
        bf h=__float2bfloat16(v);
        a.yh[zz][(size_t)n*512+c]=h;
        a.yl[zz][(size_t)n*512+c]=__float2bfloat16(v-__bfloat162float(h));
    }
}
__global__ void posenc_kernel(const float* __restrict__ kpts, const float* __restrict__ Wr,
                              float* __restrict__ cosv, float* __restrict__ sinv) {
    int idx = blockIdx.x*256 + threadIdx.x;
    if (idx >= NN*32) return;
    int p = idx & 31, n = idx >> 5;
    float kx = (kpts[2*n+0]-512.0f)*(1.0f/716.8f);
    float ky = (kpts[2*n+1]-384.0f)*(1.0f/716.8f);
    float pr = kx*Wr[2*p+0] + ky*Wr[2*p+1];
    cosv[idx] = cosf(pr); sinv[idx] = sinf(pr);
}
struct RArgs { const float* f[4]; bf *oh[4], *ol[4]; const float *cs[4], *sn[4]; };
__global__ void rope_split(RArgs a, int dorope) {
    int zz = blockIdx.y;
    int idx = blockIdx.x*256 + threadIdx.x;
    int pair = idx & 127, n = idx >> 7;
    int c = (pair>>5)*64 + 2*(pair&31);
    const float* f = a.f[zz];
    float x0 = f[(size_t)n*256+c], x1 = f[(size_t)n*256+c+1];
    if (dorope) {
        int p = pair&31;
        float cv = a.cs[zz][n*32+p], sv = a.sn[zz][n*32+p];
        float r0 = x0*cv - x1*sv, r1 = x1*cv + x0*sv;
        x0=r0; x1=r1;
    }
    bf h0=__float2bfloat16(x0), h1=__float2bfloat16(x1);
    a.oh[zz][(size_t)n*256+c]=h0;   a.oh[zz][(size_t)n*256+c+1]=h1;
    a.ol[zz][(size_t)n*256+c]=__float2bfloat16(x0-__bfloat162float(h0));
    a.ol[zz][(size_t)n*256+c+1]=__float2bfloat16(x1-__bfloat162float(h1));
}
__global__ void __launch_bounds__(256)
bn_split(const float* __restrict__ hf, const float* __restrict__ g, const float* __restrict__ b,
         bf* __restrict__ oh, bf* __restrict__ ol) {
    __shared__ float ssum[4][64], ssq[4][64], sc[64], sh[64];
    size_t base = (size_t)blockIdx.y * HSZ;
    int l = threadIdx.x & 63, r0 = threadIdx.x >> 6;
    int c = blockIdx.x*64 + l;
    float su=0.f, sq=0.f;
    for (int n=r0; n<NN; n+=4) { float x = hf[base+(size_t)n*512+c]; su+=x; sq+=x*x; }
    ssum[r0][l]=su; ssq[r0][l]=sq;
    __syncthreads();
    if (r0==0) {
        float S=0,Q=0;
        #pragma unroll
        for (int i=0;i<4;i++){ S+=ssum[i][l]; Q+=ssq[i][l]; }
        float mean=S*(1.0f/NN), var=Q*(1.0f/NN)-mean*mean;
        float s1=g[c]*rsqrtf(var+1e-5f);
        sc[l]=s1; sh[l]=b[c]-mean*s1;
    }
    __syncthreads();
    float s1=sc[l], s2=sh[l];
    for (int n=r0; n<NN; n+=4) {
        float v=fmaxf(hf[base+(size_t)n*512+c]*s1+s2, 0.0f);
        bf h=__float2bfloat16(v);
        oh[base+(size_t)n*512+c]=h;
        ol[base+(size_t)n*512+c]=__float2bfloat16(v-__bfloat162float(h));
    }
}
// ---------- Sinkhorn ----------
__global__ void bins_kernel(float* __restrict__ C, const float* __restrict__ a) {
    int i = blockIdx.x*256 + threadIdx.x;
    if (i >= NP1) return;
    float v = a[0];
    C[(size_t)i*NP1 + NN] = v;
    C[(size_t)NN*NP1 + i] = v;
}
__global__ void zero_kernel(float* p, int n) { int i=blockIdx.x*256+threadIdx.x; if(i<n) p[i]=0.f; }
__global__ void __launch_bounds__(256)
u_update_kernel(const float* __restrict__ C, const float* __restrict__ vv, float* __restrict__ u) {
    __shared__ float sm[8];
    int i = blockIdx.x;
    const float* row = C + (size_t)i*NP1;
    int t = threadIdx.x;
    float mx = -1e30f;
    for (int j=t; j<NP1; j+=256) mx = fmaxf(mx, row[j]+vv[j]);
    #pragma unroll
    for (int o=16;o>0;o>>=1) mx=fmaxf(mx,__shfl_xor_sync(0xffffffffu,mx,o));
    if ((t&31)==0) sm[t>>5]=mx;
    __syncthreads();
    mx=sm[0];
    #pragma unroll
    for (int w=1;w<8;w++) mx=fmaxf(mx,sm[w]);
    float s=0.f;
    for (int j=t; j<NP1; j+=256) s += __expf(row[j]+vv[j]-mx);
    #pragma unroll
    for (int o=16;o>0;o>>=1) s+=__shfl_xor_sync(0xffffffffu,s,o);
    __syncthreads();
    if ((t&31)==0) sm[t>>5]=s;
    __syncthreads();
    s=0.f;
    #pragma unroll
    for (int w=0;w<8;w++) s+=sm[w];
    if (t==0) u[i] = ((i<NN)?NORMC:(LOGN+NORMC)) - (mx + logf(s));
}
__global__ void v_part_kernel(const float* __restrict__ C, const float* __restrict__ u,
                              float* __restrict__ pm, float* __restrict__ ps) {
    int j = blockIdx.x*256 + threadIdx.x;
    if (j >= NP1) return;
    int rc = blockIdx.y, i0 = rc*129, i1 = min(i0+129, NP1);
    float m=-1e30f, s=0.f;
    for (int i=i0; i<i1; i++) {
        float x = C[(size_t)i*NP1+j] + u[i];
        if (x>m) { s=s*__expf(m-x)+1.f; m=x; } else s+=__expf(x-m);
    }
    pm[rc*NP1+j]=m; ps[rc*NP1+j]=s;
}
__global__ void v_combine_kernel(const float* __restrict__ pm, const float* __restrict__ ps,
                                 float* __restrict__ vv) {
    int j = blockIdx.x*256 + threadIdx.x;
    if (j >= NP1) return;
    float M=-1e30f;
    #pragma unroll
    for (int rc=0;rc<16;rc++) M=fmaxf(M, pm[rc*NP1+j]);
    float S=0.f;
    #pragma unroll
    for (int rc=0;rc<16;rc++) S+=ps[rc*NP1+j]*__expf(pm[rc*NP1+j]-M);
    vv[j] = ((j<NN)?NORMC:(LOGN+NORMC)) - (M + logf(S));
}
__global__ void final_add_kernel(float* __restrict__ C, const float* __restrict__ u,
                                 const float* __restrict__ vv) {
    int idx = blockIdx.x*256 + threadIdx.x;
    if (idx >= NP1*NP1) return;
    C[idx] += u[idx/NP1] + vv[idx%NP1] + LOG4096;
}

// ---------- host ----------
#define GSA(p,s) cudaGetSymbolAddress((void**)&(p), s)
extern "C" void kernel_launch(void* const* d_in, const int* in_sizes, int n_in,
                              void* d_out, int out_size) {
    (void)in_sizes; (void)n_in; (void)out_size;
    const float *desc0=(const float*)d_in[0], *desc1=(const float*)d_in[1];
    const float *kpts0=(const float*)d_in[2], *kpts1=(const float*)d_in[3];
    const float *Wr=(const float*)d_in[4], *proj_w=(const float*)d_in[5];
    const float *proj_b=(const float*)d_in[6];
    const float *merge_w=(const float*)d_in[7], *merge_b=(const float*)d_in[8];
    const float *mlp_w1=(const float*)d_in[9], *mlp_b1=(const float*)d_in[10];
    const float *bn_g=(const float*)d_in[11], *bn_b=(const float*)d_in[12];
    const float *mlp_w2=(const float*)d_in[13], *mlp_b2=(const float*)d_in[14];
    const float *fp_w=(const float*)d_in[15], *fp_b=(const float*)d_in[16];
    const float *binsc=(const float*)d_in[17];
    float* C = (float*)d_out;

    cudaFuncSetAttribute(mma_gemm<4>, cudaFuncAttributeMaxDynamicSharedMemorySize, SMEMB4);
    cudaFuncSetAttribute(flash_attn, cudaFuncAttributeMaxDynamicSharedMemorySize, FSMEM_B);

    float *xF,*qf,*kf,*hf,*pbp,*cs,*pu,*pvv,*ppm,*pps;
    bf *yh,*yl,*qh,*ql,*kh,*kl,*vh,*vl,*aoh,*aol,*hh,*hl;
    bf *wqh,*wql,*wmh,*wml,*w1h,*w1l,*w2h,*w2l,*fph,*fpl;
    GSA(xF,g_xF); GSA(qf,g_qf); GSA(kf,g_kf); GSA(hf,g_hf);
    GSA(yh,g_yh); GSA(yl,g_yl); GSA(qh,g_qh); GSA(ql,g_ql);
    GSA(kh,g_kh); GSA(kl,g_kl); GSA(vh,g_vh); GSA(vl,g_vl);
    GSA(aoh,g_aoh); GSA(aol,g_aol); GSA(hh,g_hh); GSA(hl,g_hl);
    GSA(wqh,g_wqh); GSA(wql,g_wql); GSA(wmh,g_wmh); GSA(wml,g_wml);
    GSA(w1h,g_w1h); GSA(w1l,g_w1l); GSA(w2h,g_w2h); GSA(w2l,g_w2l);
    GSA(fph,g_fph); GSA(fpl,g_fpl); GSA(pbp,g_pbp); GSA(cs,g_cs);
    GSA(pu,g_u); GSA(pvv,g_vv); GSA(ppm,g_pm); GSA(pps,g_ps);
    float *c0=cs, *s0=cs+NN*32, *c1=cs+2*NN*32, *s1=cs+3*NN*32;

    wconv<<<30*65536/256,256>>>(proj_w, wqh, wql, 1, (size_t)30*65536);
    wconv<<<10*65536/256,256>>>(merge_w, wmh, wml, 2, (size_t)10*65536);
    wconv<<<10*262144/256,256>>>(mlp_w1, w1h, w1l, 0, (size_t)10*262144);
    wconv<<<10*131072/256,256>>>(mlp_w2, w2h, w2l, 0, (size_t)10*131072);
    wconv<<<65536/256,256>>>(fp_w, fph, fpl, 0, 65536);
    bias_perm<<<30,256>>>(proj_b, pbp);
    posenc_kernel<<<NN*32/256,256>>>(kpts0, Wr, c0, s0);
    posenc_kernel<<<NN*32/256,256>>>(kpts1, Wr, c1, s1);
    TArgs ta;
    ta.in[0]=desc0; ta.in[1]=desc1;
    for (int s=0;s<2;s++){ ta.xF[s]=xF+s*SZ; ta.yh[s]=yh+s*HSZ; ta.yl[s]=yl+s*HSZ; }
    transpose_split<<<dim3(64,8,2),256>>>(ta);

    for (int l=0; l<10; l++) {
        int even = !(l&1);
        int src[2] = { even?0:1, even?1:0 };
        const float* mb  = merge_b + l*256;
        const float* b1  = mlp_b1 + l*512;
        const float* b2  = mlp_b2 + l*256;

        // q,k projections (fp32 out for RoPE): z={q0,k0,q1,k1}
        MArgs mq = {};
        mq.lda=512; mq.ldb=256; mq.ldo=256; mq.ldh=256; mq.K=256; mq.Nc=256; mq.scale=1.f;
        for (int s=0;s<2;s++) {
            MZ* zq=&mq.z[s*2], *zk=&mq.z[s*2+1];
            zq->Ah=yh+s*HSZ; zq->Al=yl+s*HSZ;
            zq->Bh=wqh+(size_t)(l*3)*65536; zq->Bl=wql+(size_t)(l*3)*65536;
            zq->bias=pbp+(l*3)*256; zq->outF=qf+s*SZ;
            zk->Ah=yh+src[s]*HSZ; zk->Al=yl+src[s]*HSZ;
            zk->Bh=wqh+(size_t)(l*3+1)*65536; zk->Bl=wql+(size_t)(l*3+1)*65536;
            zk->bias=pbp+(l*3+1)*256; zk->outF=kf+s*SZ;
        }
        mma_gemm<4><<<dim3(16,2,4),256,SMEMB4>>>(mq);

        // v projection, output transposed [c][m] as hi/lo
        MArgs mv = {};
        mv.lda=256; mv.ldb=512; mv.ldo=2048; mv.ldh=2048; mv.K=256; mv.Nc=2048;
        mv.scale=1.f; mv.bias_rows=1;
        for (int s=0;s<2;s++) {
            MZ* zv=&mv.z[s];
            zv->Ah=wqh+(size_t)(l*3+2)*65536; zv->Al=wql+(size_t)(l*3+2)*65536;
            zv->Bh=yh+src[s]*HSZ; zv->Bl=yl+src[s]*HSZ;
            zv->bias=pbp+(l*3+2)*256; zv->oh=vh+s*SZ; zv->ol=vl+s*SZ;
        }
        mma_gemm<4><<<dim3(2,16,2),256,SMEMB4>>>(mv);

        // rope (even) or plain split (odd)
        RArgs ra;
        ra.f[0]=qf; ra.f[1]=kf; ra.f[2]=qf+SZ; ra.f[3]=kf+SZ;
        ra.oh[0]=qh; ra.ol[0]=ql; ra.oh[1]=kh; ra.ol[1]=kl;
        ra.oh[2]=qh+SZ; ra.ol[2]=ql+SZ; ra.oh[3]=kh+SZ; ra.ol[3]=kl+SZ;
        ra.cs[0]=c0; ra.sn[0]=s0; ra.cs[1]=c0; ra.sn[1]=s0;
        ra.cs[2]=c1; ra.sn[2]=s1; ra.cs[3]=c1; ra.sn[3]=s1;
        rope_split<<<dim3(1024,4),256>>>(ra, even);

        // fused attention: scores + softmax + P*V
        flash_attn<<<dim3(16,8),256,FSMEM_B>>>(qh,ql,kh,kl,vh,vl,aoh,aol);

        // merge -> y cols 256:511
        MArgs mm = {};
        mm.lda=256; mm.ldb=256; mm.ldh=512; mm.K=256; mm.Nc=256; mm.scale=1.f;
        for (int s=0;s<2;s++) {
            MZ* zz=&mm.z[s];
            zz->Ah=aoh+s*SZ; zz->Al=aol+s*SZ;
            zz->Bh=wmh+(size_t)l*65536; zz->Bl=wml+(size_t)l*65536;
            zz->bias=mb; zz->oh=yh+s*HSZ+256; zz->ol=yl+s*HSZ+256;
        }
        mma_gemm<4><<<dim3(16,2,2),256,SMEMB4>>>(mm);

        // mlp1 -> h fp32
        MArgs m1 = {};
        m1.lda=512; m1.ldb=512; m1.ldo=512; m1.K=512; m1.Nc=512; m1.scale=1.f;
        for (int s=0;s<2;s++) {
            MZ* zz=&m1.z[s];
            zz->Ah=yh+s*HSZ; zz->Al=yl+s*HSZ;
            zz->Bh=w1h+(size_t)l*262144; zz->Bl=w1l+(size_t)l*262144;
            zz->bias=b1; zz->outF=hf+s*HSZ;
        }
        mma_gemm<4><<<dim3(16,4,2),256,SMEMB4>>>(m1);
        bn_split<<<dim3(8,2),256>>>(hf, bn_g+l*512, bn_b+l*512, hh, hl);

        // mlp2 + residual -> xF + y cols 0:255
        MArgs m2 = {};
        m2.lda=512; m2.ldb=512; m2.ldo=256; m2.ldh=512; m2.K=512; m2.Nc=256; m2.scale=1.f;
        for (int s=0;s<2;s++) {
            MZ* zz=&m2.z[s];
            zz->Ah=hh+s*HSZ; zz->Al=hl+s*HSZ;
            zz->Bh=w2h+(size_t)l*131072; zz->Bl=w2l+(size_t)l*131072;
            zz->bias=b2; zz->res=xF+s*SZ; zz->outF=xF+s*SZ;
            zz->oh=yh+s*HSZ; zz->ol=yl+s*HSZ;
        }
        mma_gemm<4><<<dim3(16,2,2),256,SMEMB4>>>(m2);
    }

    // final projection
    MArgs mf = {};
    mf.lda=512; mf.ldb=256; mf.ldh=256; mf.K=256; mf.Nc=256; mf.scale=1.f;
    for (int s=0;s<2;s++) {
        MZ* zz=&mf.z[s];
        zz->Ah=yh+s*HSZ; zz->Al=yl+s*HSZ;
        zz->Bh=fph; zz->Bl=fpl;
        zz->bias=fp_b; zz->oh=qh+s*SZ; zz->ol=ql+s*SZ;
    }
    mma_gemm<4><<<dim3(16,2,2),256,SMEMB4>>>(mf);

    // final match scores into C (ld 2049)
    MArgs mc = {};
    mc.lda=256; mc.ldb=256; mc.ldo=NP1; mc.K=256; mc.Nc=2048; mc.scale=0.0625f;
    mc.z[0].Ah=qh; mc.z[0].Al=ql; mc.z[0].Bh=qh+SZ; mc.z[0].Bl=ql+SZ;
    mc.z[0].outF=C;
    mma_gemm<4><<<dim3(16,16,1),256,SMEMB4>>>(mc);
    bins_kernel<<<(NP1+255)/256,256>>>(C, binsc);

    zero_kernel<<<(NP1+255)/256,256>>>(pvv, NP1);
    for (int t=0; t<20; t++) {
        u_update_kernel<<<NP1,256>>>(C, pvv, pu);
        v_part_kernel<<<dim3((NP1+255)/256,16),256>>>(C, pu, ppm, pps);
        v_combine_kernel<<<(NP1+255)/256,256>>>(ppm, pps, pvv);
    }
    final_add_kernel<<<(NP1*NP1+255)/256,256>>>(C, pu, pvv);
}

// round 8
// speedup vs baseline: 3.1463x; 1.2060x over previous
#include <cuda_runtime.h>
#include <cuda_bf16.h>
#include <math.h>
#include <stdint.h>

#define NN 2048
#define DM 256
#define NP1 2049
#define NORMC (-8.317766166719343f)
#define LOGN (7.624618986159398f)
#define LOG4096 (8.317766166719343f)
#define SZ ((size_t)NN*DM)
#define HSZ ((size_t)NN*512)
typedef __nv_bfloat16 bf;

// ---------- static scratch ----------
__device__ float g_xF[2*SZ], g_hf[2*HSZ];
__device__ bf g_yh[2*HSZ], g_yl[2*HSZ];
__device__ bf g_qh[2*SZ], g_ql[2*SZ], g_kh[2*SZ], g_kl[2*SZ];
__device__ bf g_vh[2*SZ], g_vl[2*SZ], g_aoh[2*SZ], g_aol[2*SZ];
__device__ bf g_hh[2*HSZ], g_hl[2*HSZ];
__device__ bf g_wqh[30*65536], g_wql[30*65536], g_wmh[10*65536], g_wml[10*65536];
__device__ bf g_w1h[10*262144], g_w1l[10*262144], g_w2h[10*131072], g_w2l[10*131072];
__device__ bf g_fph[65536], g_fpl[65536];
__device__ float g_pbp[30*256];
__device__ float g_cs[4*NN*32];
__device__ float g_bnS[2*16*512], g_bnQ[2*16*512];
__device__ float g_u[NP1], g_vv[NP1], g_pm[16*NP1], g_ps[16*NP1];

// ---------- HMMA m16n8k16 bf16 ----------
__device__ __forceinline__ void mma16816(float* c, const uint32_t* a, const uint32_t* b) {
    asm volatile("mma.sync.aligned.m16n8k16.row.col.f32.bf16.bf16.f32 "
        "{%0,%1,%2,%3}, {%4,%5,%6,%7}, {%8,%9}, {%0,%1,%2,%3};"
        : "+f"(c[0]), "+f"(c[1]), "+f"(c[2]), "+f"(c[3])
        : "r"(a[0]), "r"(a[1]), "r"(a[2]), "r"(a[3]), "r"(b[0]), "r"(b[1]));
}
#define CP16(dst, src) asm volatile("cp.async.ca.shared.global [%0], [%1], 16;" :: "r"(dst), "l"(src))

__device__ __forceinline__ uint32_t pkbf(float x, float y) {
    __nv_bfloat162 t = __floats2bfloat162_rn(x, y);
    return *(uint32_t*)&t;
}
__device__ __forceinline__ void split2(float x, float y, uint32_t& hi, uint32_t& lo) {
    bf hx = __float2bfloat16(x), hy = __float2bfloat16(y);
    __nv_bfloat162 hp; hp.x = hx; hp.y = hy;
    hi = *(uint32_t*)&hp;
    lo = pkbf(x - __bfloat162float(hx), y - __bfloat162float(hy));
}

// ---------- generic split-bf16 HMMA GEMM, cp.async double-buffered ----------
// RoPE fused in epilogue when cosv != null (pairs = (gc, gc+1), gc even)
struct MZ { const bf *Ah,*Al,*Bh,*Bl; const float *bias,*res; float *outF; bf *oh,*ol;
            const float *cosv,*sinv; };
struct MArgs { MZ z[8]; int lda,ldb,ldo,ldh,K,Nc,bias_rows; float scale; };

#define APAD 72
#define AST (128*APAD)

template<int JT>
__global__ void __launch_bounds__(256) mma_gemm(MArgs a) {
    constexpr int CTAC = 32*JT;
    constexpr int BST = CTAC*APAD;
    constexpr int STAGE = 2*AST + 2*BST;
    extern __shared__ bf smem[];
    MZ z = a.z[blockIdx.z];
    int t = threadIdx.x, w = t>>5, lane = t&31;
    int wm = w & 1, wn = w >> 1;
    int row0 = blockIdx.x*128, col0 = blockIdx.y*CTAC;
    uint32_t smb = (uint32_t)__cvta_generic_to_shared(smem);
    int lr = t >> 3, lc = (t & 7) * 8;
    int nch = a.K >> 6;

    auto issue = [&](int ch, int st) {
        uint32_t base = smb + (uint32_t)(st*STAGE*2);
        const bf* Agh = z.Ah + (size_t)(row0+lr)*a.lda + ch*64 + lc;
        const bf* Agl = z.Al + (size_t)(row0+lr)*a.lda + ch*64 + lc;
        #pragma unroll
        for (int it=0; it<4; it++) {
            uint32_t d = base + (uint32_t)(((lr+it*32)*APAD + lc)*2);
            CP16(d,           Agh + (size_t)it*32*a.lda);
            CP16(d + AST*2,   Agl + (size_t)it*32*a.lda);
        }
        uint32_t bb = base + 2*AST*2;
        #pragma unroll
        for (int it=0; it<JT; it++) {
            int r = lr + it*32;
            if (col0 + r < a.Nc) {
                uint32_t d = bb + (uint32_t)((r*APAD + lc)*2);
                CP16(d,         z.Bh + (size_t)(col0+r)*a.ldb + ch*64 + lc);
                CP16(d + BST*2, z.Bl + (size_t)(col0+r)*a.ldb + ch*64 + lc);
            }
        }
        asm volatile("cp.async.commit_group;");
    };

    float acc[4][JT][4] = {};
    issue(0, 0);
    for (int ch = 0; ch < nch; ch++) {
        int st = ch & 1;
        if (ch + 1 < nch) {
            issue(ch+1, st^1);
            asm volatile("cp.async.wait_group 1;");
        } else {
            asm volatile("cp.async.wait_group 0;");
        }
        __syncthreads();
        bf* Ash = smem + st*STAGE;
        bf* Asl = Ash + AST;
        bf* Bsh = Asl + AST;
        bf* Bsl = Bsh + BST;
        #pragma unroll
        for (int ks = 0; ks < 4; ks++) {
            int ak = ks*16 + (lane & 3)*2;
            int ar = wm*64 + (lane >> 2);
            uint32_t Afh[4][4], Afl[4][4], Bfh[JT][2], Bfl[JT][2];
            #pragma unroll
            for (int i = 0; i < 4; i++) {
                int base = (ar + i*16)*APAD + ak;
                Afh[i][0] = *(const uint32_t*)&Ash[base];
                Afh[i][1] = *(const uint32_t*)&Ash[base + 8*APAD];
                Afh[i][2] = *(const uint32_t*)&Ash[base + 8];
                Afh[i][3] = *(const uint32_t*)&Ash[base + 8*APAD + 8];
                Afl[i][0] = *(const uint32_t*)&Asl[base];
                Afl[i][1] = *(const uint32_t*)&Asl[base + 8*APAD];
                Afl[i][2] = *(const uint32_t*)&Asl[base + 8];
                Afl[i][3] = *(const uint32_t*)&Asl[base + 8*APAD + 8];
            }
            int bc = wn*8*JT + (lane >> 2);
            #pragma unroll
            for (int j = 0; j < JT; j++) {
                int base = (bc + j*8)*APAD + ak;
                Bfh[j][0] = *(const uint32_t*)&Bsh[base];
                Bfh[j][1] = *(const uint32_t*)&Bsh[base + 8];
                Bfl[j][0] = *(const uint32_t*)&Bsl[base];
                Bfl[j][1] = *(const uint32_t*)&Bsl[base + 8];
            }
            #pragma unroll
            for (int i = 0; i < 4; i++)
                #pragma unroll
                for (int j = 0; j < JT; j++) {
                    mma16816(acc[i][j], Afh[i], Bfh[j]);
                    mma16816(acc[i][j], Afh[i], Bfl[j]);
                    mma16816(acc[i][j], Afl[i], Bfh[j]);
                }
        }
        __syncthreads();
    }
    #pragma unroll
    for (int i = 0; i < 4; i++) {
        #pragma unroll
        for (int j = 0; j < JT; j++) {
            int gr0 = row0 + wm*64 + i*16 + (lane >> 2);
            int gc  = col0 + wn*8*JT + j*8 + (lane & 3)*2;
            if (gc >= a.Nc) continue;
            #pragma unroll
            for (int h2 = 0; h2 < 2; h2++) {
                int gr = gr0 + h2*8;
                float v0 = acc[i][j][h2*2+0]*a.scale;
                float v1 = acc[i][j][h2*2+1]*a.scale;
                if (z.bias) {
                    if (a.bias_rows) { float bb=z.bias[gr]; v0+=bb; v1+=bb; }
                    else { v0+=z.bias[gc]; v1+=z.bias[gc+1]; }
                }
                if (z.res) {
                    v0 += z.res[(size_t)gr*a.ldo + gc];
                    v1 += z.res[(size_t)gr*a.ldo + gc + 1];
                }
                if (z.outF) {
                    z.outF[(size_t)gr*a.ldo + gc]   = v0;
                    z.outF[(size_t)gr*a.ldo + gc+1] = v1;
                }
                if (z.oh) {
                    if (z.cosv) {   // fused RoPE: (gc, gc+1) is a rotation pair
                        int p = (gc & 63) >> 1;
                        float cv = z.cosv[gr*32+p], sv = z.sinv[gr*32+p];
                        float r0 = v0*cv - v1*sv;
                        float r1 = v1*cv + v0*sv;
                        v0 = r0; v1 = r1;
                    }
                    uint32_t hi, lo;
                    split2(v0, v1, hi, lo);
                    size_t o = (size_t)gr*a.ldh + gc;
                    *(uint32_t*)&z.oh[o] = hi;
                    *(uint32_t*)&z.ol[o] = lo;
                }
            }
        }
    }
}
#define SMEMB4 ((2*(2*AST+2*128*APAD))*2)

// ---------- flash attention: scores + online softmax + P*V fused ----------
#define KP 72
#define VP 136
#define FK_L (128*KP)
#define FV_H (2*128*KP)
#define FV_L (2*128*KP + 64*VP)
#define FSTAGE (2*128*KP + 2*64*VP)
#define FSMEM_B (2*FSTAGE*2)

__global__ void __launch_bounds__(256)
flash_attn(const bf* __restrict__ qh_, const bf* __restrict__ ql_,
           const bf* __restrict__ kh_, const bf* __restrict__ kl_,
           const bf* __restrict__ vh_, const bf* __restrict__ vl_,
           bf* __restrict__ aoh_, bf* __restrict__ aol_) {
    extern __shared__ bf fsm[];
    int slice = blockIdx.y;
    int s = slice >> 2, h = slice & 3;
    const bf* qgh = qh_ + (size_t)s*SZ;
    const bf* qgl = ql_ + (size_t)s*SZ;
    const bf* kgh = kh_ + (size_t)s*SZ;
    const bf* kgl = kl_ + (size_t)s*SZ;
    const bf* vgh = vh_ + (size_t)s*SZ + (size_t)(h*64)*2048;
    const bf* vgl = vl_ + (size_t)s*SZ + (size_t)(h*64)*2048;
    bf* outh = aoh_ + (size_t)s*SZ;
    bf* outl = aol_ + (size_t)s*SZ;
    int hcol = h*64;
    int t = threadIdx.x, w = t>>5, lane = t&31;
    int qrow = blockIdx.x*128 + w*16 + (lane>>2);
    uint32_t smb = (uint32_t)__cvta_generic_to_shared(fsm);

    uint32_t Aqh[4][4], Aql[4][4];
    #pragma unroll
    for (int ks=0; ks<4; ks++) {
        int cb = hcol + ks*16 + (lane&3)*2;
        Aqh[ks][0] = *(const uint32_t*)&qgh[(size_t)qrow*256 + cb];
        Aqh[ks][1] = *(const uint32_t*)&qgh[(size_t)(qrow+8)*256 + cb];
        Aqh[ks][2] = *(const uint32_t*)&qgh[(size_t)qrow*256 + cb + 8];
        Aqh[ks][3] = *(const uint32_t*)&qgh[(size_t)(qrow+8)*256 + cb + 8];
        Aql[ks][0] = *(const uint32_t*)&qgl[(size_t)qrow*256 + cb];
        Aql[ks][1] = *(const uint32_t*)&qgl[(size_t)(qrow+8)*256 + cb];
        Aql[ks][2] = *(const uint32_t*)&qgl[(size_t)qrow*256 + cb + 8];
        Aql[ks][3] = *(const uint32_t*)&qgl[(size_t)(qrow+8)*256 + cb + 8];
    }

    auto issue = [&](int ch, int st) {
        uint32_t base = smb + (uint32_t)(st*FSTAGE*2);
        int key0 = ch*128;
        int kr = t>>1, kc = (t&1)*32;
        const bf* skh = kgh + (size_t)(key0+kr)*256 + hcol + kc;
        const bf* skl = kgl + (size_t)(key0+kr)*256 + hcol + kc;
        #pragma unroll
        for (int i=0;i<4;i++) {
            uint32_t d = base + (uint32_t)((kr*KP + kc + i*8)*2);
            CP16(d,           skh + i*8);
            CP16(d + FK_L*2,  skl + i*8);
        }
        int vr = t>>2, vc = (t&3)*32;
        const bf* svh = vgh + (size_t)vr*2048 + key0 + vc;
        const bf* svl = vgl + (size_t)vr*2048 + key0 + vc;
        #pragma unroll
        for (int i=0;i<4;i++) {
            uint32_t d = base + (uint32_t)((FV_H + vr*VP + vc + i*8)*2);
            CP16(d,                 svh + i*8);
            CP16(d + (FV_L-FV_H)*2, svl + i*8);
        }
        asm volatile("cp.async.commit_group;");
    };

    float m_run[2] = {-1e30f, -1e30f};
    float s_run[2] = {0.f, 0.f};
    float oacc[8][4] = {};

    issue(0, 0);
    for (int ch = 0; ch < 16; ch++) {
        int st = ch & 1;
        if (ch + 1 < 16) { issue(ch+1, st^1); asm volatile("cp.async.wait_group 1;"); }
        else             { asm volatile("cp.async.wait_group 0;"); }
        __syncthreads();
        bf* Kh = fsm + st*FSTAGE;
        bf* Kl = Kh + FK_L;
        bf* Vh = fsm + st*FSTAGE + FV_H;
        bf* Vl = fsm + st*FSTAGE + FV_L;

        float sacc[16][4] = {};
        #pragma unroll
        for (int ks = 0; ks < 4; ks++) {
            int ak = ks*16 + (lane&3)*2;
            #pragma unroll
            for (int j = 0; j < 16; j++) {
                int base = (j*8 + (lane>>2))*KP + ak;
                uint32_t Bh[2] = { *(const uint32_t*)&Kh[base], *(const uint32_t*)&Kh[base+8] };
                uint32_t Bl[2] = { *(const uint32_t*)&Kl[base], *(const uint32_t*)&Kl[base+8] };
                mma16816(sacc[j], Aqh[ks], Bh);
                mma16816(sacc[j], Aqh[ks], Bl);
                mma16816(sacc[j], Aql[ks], Bh);
            }
        }
        float mx0 = -1e30f, mx1 = -1e30f;
        #pragma unroll
        for (int j = 0; j < 16; j++) {
            sacc[j][0]*=0.125f; sacc[j][1]*=0.125f; sacc[j][2]*=0.125f; sacc[j][3]*=0.125f;
            mx0 = fmaxf(mx0, fmaxf(sacc[j][0], sacc[j][1]));
            mx1 = fmaxf(mx1, fmaxf(sacc[j][2], sacc[j][3]));
        }
        mx0 = fmaxf(mx0, __shfl_xor_sync(0xffffffffu, mx0, 1));
        mx0 = fmaxf(mx0, __shfl_xor_sync(0xffffffffu, mx0, 2));
        mx1 = fmaxf(mx1, __shfl_xor_sync(0xffffffffu, mx1, 1));
        mx1 = fmaxf(mx1, __shfl_xor_sync(0xffffffffu, mx1, 2));
        float nm0 = fmaxf(m_run[0], mx0), nm1 = fmaxf(m_run[1], mx1);
        float al0 = __expf(m_run[0]-nm0), al1 = __expf(m_run[1]-nm1);
        float cs0 = 0.f, cs1 = 0.f;
        #pragma unroll
        for (int j = 0; j < 16; j++) {
            float p0=__expf(sacc[j][0]-nm0), p1=__expf(sacc[j][1]-nm0);
            float p2=__expf(sacc[j][2]-nm1), p3=__expf(sacc[j][3]-nm1);
            sacc[j][0]=p0; sacc[j][1]=p1; sacc[j][2]=p2; sacc[j][3]=p3;
            cs0 += p0+p1; cs1 += p2+p3;
        }
        cs0 += __shfl_xor_sync(0xffffffffu, cs0, 1);
        cs0 += __shfl_xor_sync(0xffffffffu, cs0, 2);
        cs1 += __shfl_xor_sync(0xffffffffu, cs1, 1);
        cs1 += __shfl_xor_sync(0xffffffffu, cs1, 2);
        s_run[0] = s_run[0]*al0 + cs0;
        s_run[1] = s_run[1]*al1 + cs1;
        m_run[0] = nm0; m_run[1] = nm1;
        #pragma unroll
        for (int j2 = 0; j2 < 8; j2++) {
            oacc[j2][0]*=al0; oacc[j2][1]*=al0; oacc[j2][2]*=al1; oacc[j2][3]*=al1;
        }
        #pragma unroll
        for (int kk = 0; kk < 8; kk++) {
            uint32_t Pah[4], Pal[4];
            split2(sacc[2*kk  ][0], sacc[2*kk  ][1], Pah[0], Pal[0]);
            split2(sacc[2*kk  ][2], sacc[2*kk  ][3], Pah[1], Pal[1]);
            split2(sacc[2*kk+1][0], sacc[2*kk+1][1], Pah[2], Pal[2]);
            split2(sacc[2*kk+1][2], sacc[2*kk+1][3], Pah[3], Pal[3]);
            int vk = kk*16 + (lane&3)*2;
            #pragma unroll
            for (int j2 = 0; j2 < 8; j2++) {
                int base = (j2*8 + (lane>>2))*VP + vk;
                uint32_t Bh[2] = { *(const uint32_t*)&Vh[base], *(const uint32_t*)&Vh[base+8] };
                uint32_t Bl[2] = { *(const uint32_t*)&Vl[base], *(const uint32_t*)&Vl[base+8] };
                mma16816(oacc[j2], Pah, Bh);
                mma16816(oacc[j2], Pah, Bl);
                mma16816(oacc[j2], Pal, Bh);
            }
        }
        __syncthreads();
    }
    float inv0 = 1.0f/s_run[0], inv1 = 1.0f/s_run[1];
    #pragma unroll
    for (int j2 = 0; j2 < 8; j2++) {
        int col = hcol + j2*8 + (lane&3)*2;
        uint32_t hi, lo;
        split2(oacc[j2][0]*inv0, oacc[j2][1]*inv0, hi, lo);
        *(uint32_t*)&outh[(size_t)qrow*256 + col] = hi;
        *(uint32_t*)&outl[(size_t)qrow*256 + col] = lo;
        split2(oacc[j2][2]*inv1, oacc[j2][3]*inv1, hi, lo);
        *(uint32_t*)&outh[(size_t)(qrow+8)*256 + col] = hi;
        *(uint32_t*)&outl[(size_t)(qrow+8)*256 + col] = lo;
    }
}

// ---------- conversions ----------
__global__ void wconv(const float* __restrict__ w, bf* __restrict__ oh, bf* __restrict__ ol,
                      int mode, size_t total) {
    size_t idx = (size_t)blockIdx.x*256 + threadIdx.x;
    if (idx >= total) return;
    size_t src = idx;
    if (mode==1) { int op=(idx>>8)&255; int o=(op&63)*4+(op>>6); src = (idx & ~(size_t)0xFF00) | ((size_t)o<<8); }
    else if (mode==2) { int cp=idx&255; int c=(cp&63)*4+(cp>>6); src = (idx & ~(size_t)0xFF) | (size_t)c; }
    float v = w[src];
    bf h = __float2bfloat16(v);
    oh[idx]=h; ol[idx]=__float2bfloat16(v-__bfloat162float(h));
}
__global__ void bias_perm(const float* __restrict__ pb, float* __restrict__ out) {
    int idx = blockIdx.x*256 + threadIdx.x;
    int op = idx & 255;
    out[idx] = pb[(idx & ~255) | ((op&63)*4 + (op>>6))];
}
struct TArgs { const float* in[2]; float* xF[2]; bf *yh[2], *yl[2]; };
__global__ void transpose_split(TArgs a) {
    __shared__ float tl[32][33];
    int zz = blockIdx.z, n0 = blockIdx.x*32, c0 = blockIdx.y*32;
    int tx = threadIdx.x&31, ty = threadIdx.x>>5;
    const float* in = a.in[zz];
    #pragma unroll
    for (int r=0;r<4;r++) tl[ty+r*8][tx] = in[(size_t)(c0+ty+r*8)*NN + n0+tx];
    __syncthreads();
    #pragma unroll
    for (int r=0;r<4;r++) {
        int n=n0+ty+r*8, c=c0+tx;
        float v = tl[tx][ty+r*8];
        a.xF[zz][(size_t)n*256+c]=v;
        bf h=__float2bfloat16(v);
        a.yh[zz][(size_t)n*512+c]=h;
        a.yl[zz][(size_t)n*512+c]=__float2bfloat16(v-__bfloat162float(h));
    }
}
__global__ void posenc_kernel(const float* __restrict__ kpts, const float* __restrict__ Wr,
                              float* __restrict__ cosv, float* __restrict__ sinv) {
    int idx = blockIdx.x*256 + threadIdx.x;
    if (idx >= NN*32) return;
    int p = idx & 31, n = idx >> 5;
    float kx = (kpts[2*n+0]-512.0f)*(1.0f/716.8f);
    float ky = (kpts[2*n+1]-384.0f)*(1.0f/716.8f);
    float pr = kx*Wr[2*p+0] + ky*Wr[2*p+1];
    cosv[idx] = cosf(pr); sinv[idx] = sinf(pr);
}
// ---------- batchnorm: full-grid two-pass ----------
__global__ void __launch_bounds__(256)
bn_stats(const float* __restrict__ hf, float* __restrict__ pS, float* __restrict__ pQ) {
    // grid (8, 16, 2)
    int z = blockIdx.z;
    size_t base = (size_t)z * HSZ;
    int l = threadIdx.x & 63, rr = threadIdx.x >> 6;
    int c = blockIdx.x*64 + l;
    int r0 = blockIdx.y*128;
    float su=0.f, sq=0.f;
    for (int n = r0+rr; n < r0+128; n += 4) {
        float x = hf[base + (size_t)n*512 + c];
        su += x; sq += x*x;
    }
    __shared__ float sS[4][64], sQ[4][64];
    sS[rr][l]=su; sQ[rr][l]=sq;
    __syncthreads();
    if (rr==0) {
        float S=0.f, Q=0.f;
        #pragma unroll
        for (int i=0;i<4;i++){ S+=sS[i][l]; Q+=sQ[i][l]; }
        int o = (z*16 + blockIdx.y)*512 + c;
        pS[o]=S; pQ[o]=Q;
    }
}
__global__ void __launch_bounds__(256)
bn_apply(const float* __restrict__ hf, const float* __restrict__ pS, const float* __restrict__ pQ,
         const float* __restrict__ g, const float* __restrict__ b,
         bf* __restrict__ oh, bf* __restrict__ ol) {
    // grid (8, 16, 2)
    int z = blockIdx.z;
    size_t base = (size_t)z * HSZ;
    __shared__ float sc[64], sh[64];
    int l = threadIdx.x & 63;
    if (threadIdx.x < 64) {
        int c = blockIdx.x*64 + threadIdx.x;
        float S=0.f, Q=0.f;
        #pragma unroll
        for (int k=0;k<16;k++){ S+=pS[(z*16+k)*512+c]; Q+=pQ[(z*16+k)*512+c]; }
        float mean=S*(1.0f/NN), var=Q*(1.0f/NN)-mean*mean;
        float s1=g[c]*rsqrtf(var+1e-5f);
        sc[threadIdx.x]=s1; sh[threadIdx.x]=b[c]-mean*s1;
    }
    __syncthreads();
    int c = blockIdx.x*64 + l;
    int rr = threadIdx.x >> 6, r0 = blockIdx.y*128;
    float s1=sc[l], s2=sh[l];
    for (int n = r0+rr; n < r0+128; n += 4) {
        float v=fmaxf(hf[base+(size_t)n*512+c]*s1+s2, 0.0f);
        bf h=__float2bfloat16(v);
        oh[base+(size_t)n*512+c]=h;
        ol[base+(size_t)n*512+c]=__float2bfloat16(v-__bfloat162float(h));
    }
}
// ---------- Sinkhorn ----------
__global__ void bins_kernel(float* __restrict__ C, const float* __restrict__ a) {
    int i = blockIdx.x*256 + threadIdx.x;
    if (i >= NP1) return;
    float v = a[0];
    C[(size_t)i*NP1 + NN] = v;
    C[(size_t)NN*NP1 + i] = v;
}
__global__ void zero_kernel(float* p, int n) { int i=blockIdx.x*256+threadIdx.x; if(i<n) p[i]=0.f; }
__global__ void __launch_bounds__(256)
u_update_kernel(const float* __restrict__ C, const float* __restrict__ vv, float* __restrict__ u) {
    __shared__ float sm[8];
    int i = blockIdx.x;
    const float* row = C + (size_t)i*NP1;
    int t = threadIdx.x;
    float mx = -1e30f;
    for (int j=t; j<NP1; j+=256) mx = fmaxf(mx, row[j]+vv[j]);
    #pragma unroll
    for (int o=16;o>0;o>>=1) mx=fmaxf(mx,__shfl_xor_sync(0xffffffffu,mx,o));
    if ((t&31)==0) sm[t>>5]=mx;
    __syncthreads();
    mx=sm[0];
    #pragma unroll
    for (int w=1;w<8;w++) mx=fmaxf(mx,sm[w]);
    float s=0.f;
    for (int j=t; j<NP1; j+=256) s += __expf(row[j]+vv[j]-mx);
    #pragma unroll
    for (int o=16;o>0;o>>=1) s+=__shfl_xor_sync(0xffffffffu,s,o);
    __syncthreads();
    if ((t&31)==0) sm[t>>5]=s;
    __syncthreads();
    s=0.f;
    #pragma unroll
    for (int w=0;w<8;w++) s+=sm[w];
    if (t==0) u[i] = ((i<NN)?NORMC:(LOGN+NORMC)) - (mx + logf(s));
}
__global__ void v_part_kernel(const float* __restrict__ C, const float* __restrict__ u,
                              float* __restrict__ pm, float* __restrict__ ps) {
    int j = blockIdx.x*256 + threadIdx.x;
    if (j >= NP1) return;
    int rc = blockIdx.y, i0 = rc*129, i1 = min(i0+129, NP1);
    float m=-1e30f, s=0.f;
    for (int i=i0; i<i1; i++) {
        float x = C[(size_t)i*NP1+j] + u[i];
        if (x>m) { s=s*__expf(m-x)+1.f; m=x; } else s+=__expf(x-m);
    }
    pm[rc*NP1+j]=m; ps[rc*NP1+j]=s;
}
__global__ void v_combine_kernel(const float* __restrict__ pm, const float* __restrict__ ps,
                                 float* __restrict__ vv) {
    int j = blockIdx.x*256 + threadIdx.x;
    if (j >= NP1) return;
    float M=-1e30f;
    #pragma unroll
    for (int rc=0;rc<16;rc++) M=fmaxf(M, pm[rc*NP1+j]);
    float S=0.f;
    #pragma unroll
    for (int rc=0;rc<16;rc++) S+=ps[rc*NP1+j]*__expf(pm[rc*NP1+j]-M);
    vv[j] = ((j<NN)?NORMC:(LOGN+NORMC)) - (M + logf(S));
}
__global__ void final_add_kernel(float* __restrict__ C, const float* __restrict__ u,
                                 const float* __restrict__ vv) {
    int idx = blockIdx.x*256 + threadIdx.x;
    if (idx >= NP1*NP1) return;
    C[idx] += u[idx/NP1] + vv[idx%NP1] + LOG4096;
}

// ---------- host ----------
#define GSA(p,s) cudaGetSymbolAddress((void**)&(p), s)
extern "C" void kernel_launch(void* const* d_in, const int* in_sizes, int n_in,
                              void* d_out, int out_size) {
    (void)in_sizes; (void)n_in; (void)out_size;
    const float *desc0=(const float*)d_in[0], *desc1=(const float*)d_in[1];
    const float *kpts0=(const float*)d_in[2], *kpts1=(const float*)d_in[3];
    const float *Wr=(const float*)d_in[4], *proj_w=(const float*)d_in[5];
    const float *proj_b=(const float*)d_in[6];
    const float *merge_w=(const float*)d_in[7], *merge_b=(const float*)d_in[8];
    const float *mlp_w1=(const float*)d_in[9], *mlp_b1=(const float*)d_in[10];
    const float *bn_g=(const float*)d_in[11], *bn_b=(const float*)d_in[12];
    const float *mlp_w2=(const float*)d_in[13], *mlp_b2=(const float*)d_in[14];
    const float *fp_w=(const float*)d_in[15], *fp_b=(const float*)d_in[16];
    const float *binsc=(const float*)d_in[17];
    float* C = (float*)d_out;

    cudaFuncSetAttribute(mma_gemm<4>, cudaFuncAttributeMaxDynamicSharedMemorySize, SMEMB4);
    cudaFuncSetAttribute(flash_attn, cudaFuncAttributeMaxDynamicSharedMemorySize, FSMEM_B);

    float *xF,*hf,*pbp,*cs,*pu,*pvv,*ppm,*pps,*bnS,*bnQ;
    bf *yh,*yl,*qh,*ql,*kh,*kl,*vh,*vl,*aoh,*aol,*hh,*hl;
    bf *wqh,*wql,*wmh,*wml,*w1h,*w1l,*w2h,*w2l,*fph,*fpl;
    GSA(xF,g_xF); GSA(hf,g_hf);
    GSA(yh,g_yh); GSA(yl,g_yl); GSA(qh,g_qh); GSA(ql,g_ql);
    GSA(kh,g_kh); GSA(kl,g_kl); GSA(vh,g_vh); GSA(vl,g_vl);
    GSA(aoh,g_aoh); GSA(aol,g_aol); GSA(hh,g_hh); GSA(hl,g_hl);
    GSA(wqh,g_wqh); GSA(wql,g_wql); GSA(wmh,g_wmh); GSA(wml,g_wml);
    GSA(w1h,g_w1h); GSA(w1l,g_w1l); GSA(w2h,g_w2h); GSA(w2l,g_w2l);
    GSA(fph,g_fph); GSA(fpl,g_fpl); GSA(pbp,g_pbp); GSA(cs,g_cs);
    GSA(bnS,g_bnS); GSA(bnQ,g_bnQ);
    GSA(pu,g_u); GSA(pvv,g_vv); GSA(ppm,g_pm); GSA(pps,g_ps);
    float *c0=cs, *s0=cs+NN*32, *c1=cs+2*NN*32, *s1=cs+3*NN*32;

    wconv<<<30*65536/256,256>>>(proj_w, wqh, wql, 1, (size_t)30*65536);
    wconv<<<10*65536/256,256>>>(merge_w, wmh, wml, 2, (size_t)10*65536);
    wconv<<<10*262144/256,256>>>(mlp_w1, w1h, w1l, 0, (size_t)10*262144);
    wconv<<<10*131072/256,256>>>(mlp_w2, w2h, w2l, 0, (size_t)10*131072);
    wconv<<<65536/256,256>>>(fp_w, fph, fpl, 0, 65536);
    bias_perm<<<30,256>>>(proj_b, pbp);
    posenc_kernel<<<NN*32/256,256>>>(kpts0, Wr, c0, s0);
    posenc_kernel<<<NN*32/256,256>>>(kpts1, Wr, c1, s1);
    TArgs ta;
    ta.in[0]=desc0; ta.in[1]=desc1;
    for (int s=0;s<2;s++){ ta.xF[s]=xF+s*SZ; ta.yh[s]=yh+s*HSZ; ta.yl[s]=yl+s*HSZ; }
    transpose_split<<<dim3(64,8,2),256>>>(ta);

    for (int l=0; l<10; l++) {
        int even = !(l&1);
        int src[2] = { even?0:1, even?1:0 };
        const float* mb  = merge_b + l*256;
        const float* b1  = mlp_b1 + l*512;
        const float* b2  = mlp_b2 + l*256;
        const float* csv[2] = { c0, c1 };
        const float* snv[2] = { s0, s1 };

        // q,k projections with fused RoPE+split: z={q0,k0,q1,k1}
        MArgs mq = {};
        mq.lda=512; mq.ldb=256; mq.ldo=256; mq.ldh=256; mq.K=256; mq.Nc=256; mq.scale=1.f;
        for (int s=0;s<2;s++) {
            MZ* zq=&mq.z[s*2], *zk=&mq.z[s*2+1];
            zq->Ah=yh+s*HSZ; zq->Al=yl+s*HSZ;
            zq->Bh=wqh+(size_t)(l*3)*65536; zq->Bl=wql+(size_t)(l*3)*65536;
            zq->bias=pbp+(l*3)*256; zq->oh=qh+s*SZ; zq->ol=ql+s*SZ;
            zk->Ah=yh+src[s]*HSZ; zk->Al=yl+src[s]*HSZ;
            zk->Bh=wqh+(size_t)(l*3+1)*65536; zk->Bl=wql+(size_t)(l*3+1)*65536;
            zk->bias=pbp+(l*3+1)*256; zk->oh=kh+s*SZ; zk->ol=kl+s*SZ;
            if (even) {
                zq->cosv=csv[s]; zq->sinv=snv[s];
                zk->cosv=csv[s]; zk->sinv=snv[s];
            }
        }
        mma_gemm<4><<<dim3(16,2,4),256,SMEMB4>>>(mq);

        // v projection, output transposed [c][m] as hi/lo
        MArgs mv = {};
        mv.lda=256; mv.ldb=512; mv.ldo=2048; mv.ldh=2048; mv.K=256; mv.Nc=2048;
        mv.scale=1.f; mv.bias_rows=1;
        for (int s=0;s<2;s++) {
            MZ* zv=&mv.z[s];
            zv->Ah=wqh+(size_t)(l*3+2)*65536; zv->Al=wql+(size_t)(l*3+2)*65536;
            zv->Bh=yh+src[s]*HSZ; zv->Bl=yl+src[s]*HSZ;
            zv->bias=pbp+(l*3+2)*256; zv->oh=vh+s*SZ; zv->ol=vl+s*SZ;
        }
        mma_gemm<4><<<dim3(2,16,2),256,SMEMB4>>>(mv);

        // fused attention: scores + softmax + P*V
        flash_attn<<<dim3(16,8),256,FSMEM_B>>>(qh,ql,kh,kl,vh,vl,aoh,aol);

        // merge -> y cols 256:511
        MArgs mm = {};
        mm.lda=256; mm.ldb=256; mm.ldh=512; mm.K=256; mm.Nc=256; mm.scale=1.f;
        for (int s=0;s<2;s++) {
            MZ* zz=&mm.z[s];
            zz->Ah=aoh+s*SZ; zz->Al=aol+s*SZ;
            zz->Bh=wmh+(size_t)l*65536; zz->Bl=wml+(size_t)l*65536;
            zz->bias=mb; zz->oh=yh+s*HSZ+256; zz->ol=yl+s*HSZ+256;
        }
        mma_gemm<4><<<dim3(16,2,2),256,SMEMB4>>>(mm);

        // mlp1 -> h fp32
        MArgs m1 = {};
        m1.lda=512; m1.ldb=512; m1.ldo=512; m1.K=512; m1.Nc=512; m1.scale=1.f;
        for (int s=0;s<2;s++) {
            MZ* zz=&m1.z[s];
            zz->Ah=yh+s*HSZ; zz->Al=yl+s*HSZ;
            zz->Bh=w1h+(size_t)l*262144; zz->Bl=w1l+(size_t)l*262144;
            zz->bias=b1; zz->outF=hf+s*HSZ;
        }
        mma_gemm<4><<<dim3(16,4,2),256,SMEMB4>>>(m1);
        bn_stats<<<dim3(8,16,2),256>>>(hf, bnS, bnQ);
        bn_apply<<<dim3(8,16,2),256>>>(hf, bnS, bnQ, bn_g+l*512, bn_b+l*512, hh, hl);

        // mlp2 + residual -> xF + y cols 0:255
        MArgs m2 = {};
        m2.lda=512; m2.ldb=512; m2.ldo=256; m2.ldh=512; m2.K=512; m2.Nc=256; m2.scale=1.f;
        for (int s=0;s<2;s++) {
            MZ* zz=&m2.z[s];
            zz->Ah=hh+s*HSZ; zz->Al=hl+s*HSZ;
            zz->Bh=w2h+(size_t)l*131072; zz->Bl=w2l+(size_t)l*131072;
            zz->bias=b2; zz->res=xF+s*SZ; zz->outF=xF+s*SZ;
            zz->oh=yh+s*HSZ; zz->ol=yl+s*HSZ;
        }
        mma_gemm<4><<<dim3(16,2,2),256,SMEMB4>>>(m2);
    }

    // final projection (reuse qh/ql as mdesc buffers)
    MArgs mf = {};
    mf.lda=512; mf.ldb=256; mf.ldh=256; mf.K=256; mf.Nc=256; mf.scale=1.f;
    for (int s=0;s<2;s++) {
        MZ* zz=&mf.z[s];
        zz->Ah=yh+s*HSZ; zz->Al=yl+s*HSZ;
        zz->Bh=fph; zz->Bl=fpl;
        zz->bias=fp_b; zz->oh=qh+s*SZ; zz->ol=ql+s*SZ;
    }
    mma_gemm<4><<<dim3(16,2,2),256,SMEMB4>>>(mf);

    // final match scores into C (ld 2049)
    MArgs mc = {};
    mc.lda=256; mc.ldb=256; mc.ldo=NP1; mc.K=256; mc.Nc=2048; mc.scale=0.0625f;
    mc.z[0].Ah=qh; mc.z[0].Al=ql; mc.z[0].Bh=qh+SZ; mc.z[0].Bl=ql+SZ;
    mc.z[0].outF=C;
    mma_gemm<4><<<dim3(16,16,1),256,SMEMB4>>>(mc);
    bins_kernel<<<(NP1+255)/256,256>>>(C, binsc);

    zero_kernel<<<(NP1+255)/256,256>>>(pvv, NP1);
    for (int t=0; t<20; t++) {
        u_update_kernel<<<NP1,256>>>(C, pvv, pu);
        v_part_kernel<<<dim3((NP1+255)/256,16),256>>>(C, pu, ppm, pps);
        v_combine_kernel<<<(NP1+255)/256,256>>>(ppm, pps, pvv);
    }
    final_add_kernel<<<(NP1*NP1+255)/256,256>>>(C, pu, pvv);
}

// round 9
// speedup vs baseline: 3.3629x; 1.0689x over previous
#include <cuda_runtime.h>
#include <cuda_bf16.h>
#include <math.h>
#include <stdint.h>

#define NN 2048
#define DM 256
#define NP1 2049
#define NORMC (-8.317766166719343f)
#define LOGN (7.624618986159398f)
#define LOG4096 (8.317766166719343f)
#define SZ ((size_t)NN*DM)
#define HSZ ((size_t)NN*512)
typedef __nv_bfloat16 bf;

// ---------- static scratch ----------
__device__ float g_xF[2*SZ], g_hf[2*HSZ];
__device__ bf g_yh[2*HSZ], g_yl[2*HSZ];
__device__ bf g_qh[2*SZ], g_ql[2*SZ], g_kh[2*SZ], g_kl[2*SZ];
__device__ bf g_vh[2*SZ], g_vl[2*SZ], g_aoh[2*SZ], g_aol[2*SZ];
__device__ bf g_hh[2*HSZ], g_hl[2*HSZ];
__device__ bf g_wqh[30*65536], g_wql[30*65536], g_wmh[10*65536], g_wml[10*65536];
__device__ bf g_w1h[10*262144], g_w1l[10*262144], g_w2h[10*131072], g_w2l[10*131072];
__device__ bf g_fph[65536], g_fpl[65536];
__device__ float g_pbp[30*256];
__device__ float g_cs[4*NN*32];
__device__ float g_bnS[2*16*512], g_bnQ[2*16*512];
__device__ float g_u[NP1], g_vv[NP1], g_pm[16*NP1], g_ps[16*NP1];

// ---------- HMMA m16n8k16 bf16 + ldmatrix ----------
__device__ __forceinline__ void mma16816(float* c, const uint32_t* a, const uint32_t* b) {
    asm volatile("mma.sync.aligned.m16n8k16.row.col.f32.bf16.bf16.f32 "
        "{%0,%1,%2,%3}, {%4,%5,%6,%7}, {%8,%9}, {%0,%1,%2,%3};"
        : "+f"(c[0]), "+f"(c[1]), "+f"(c[2]), "+f"(c[3])
        : "r"(a[0]), "r"(a[1]), "r"(a[2]), "r"(a[3]), "r"(b[0]), "r"(b[1]));
}
__device__ __forceinline__ void ldsm4(uint32_t& r0, uint32_t& r1, uint32_t& r2, uint32_t& r3,
                                      uint32_t addr) {
    asm volatile("ldmatrix.sync.aligned.m8n8.x4.shared.b16 {%0,%1,%2,%3}, [%4];"
        : "=r"(r0), "=r"(r1), "=r"(r2), "=r"(r3) : "r"(addr));
}
#define CP16(dst, src) asm volatile("cp.async.ca.shared.global [%0], [%1], 16;" :: "r"(dst), "l"(src))

__device__ __forceinline__ uint32_t pkbf(float x, float y) {
    __nv_bfloat162 t = __floats2bfloat162_rn(x, y);
    return *(uint32_t*)&t;
}
__device__ __forceinline__ void split2(float x, float y, uint32_t& hi, uint32_t& lo) {
    bf hx = __float2bfloat16(x), hy = __float2bfloat16(y);
    __nv_bfloat162 hp; hp.x = hx; hp.y = hy;
    hi = *(uint32_t*)&hp;
    lo = pkbf(x - __bfloat162float(hx), y - __bfloat162float(hy));
}

// ---------- generic split-bf16 HMMA GEMM ----------
struct MZ { const bf *Ah,*Al,*Bh,*Bl; const float *bias,*res; float *outF; bf *oh,*ol;
            const float *cosv,*sinv; };
struct MArgs { MZ z[8]; int lda,ldb,ldo,ldh,K,Nc,bias_rows; float scale; };

#define APAD 72
#define AST (128*APAD)

template<int JT>
__global__ void __launch_bounds__(256) mma_gemm(MArgs a) {
    constexpr int CTAC = 32*JT;
    constexpr int BST = CTAC*APAD;
    constexpr int STAGE = 2*AST + 2*BST;
    extern __shared__ bf smem[];
    MZ z = a.z[blockIdx.z];
    int t = threadIdx.x, w = t>>5, lane = t&31;
    int wm = w & 1, wn = w >> 1;
    int row0 = blockIdx.x*128, col0 = blockIdx.y*CTAC;
    uint32_t smb = (uint32_t)__cvta_generic_to_shared(smem);
    int lr = t >> 3, lc = (t & 7) * 8;
    int nch = a.K >> 6;

    auto issue = [&](int ch, int st) {
        uint32_t base = smb + (uint32_t)(st*STAGE*2);
        const bf* Agh = z.Ah + (size_t)(row0+lr)*a.lda + ch*64 + lc;
        const bf* Agl = z.Al + (size_t)(row0+lr)*a.lda + ch*64 + lc;
        #pragma unroll
        for (int it=0; it<4; it++) {
            uint32_t d = base + (uint32_t)(((lr+it*32)*APAD + lc)*2);
            CP16(d,           Agh + (size_t)it*32*a.lda);
            CP16(d + AST*2,   Agl + (size_t)it*32*a.lda);
        }
        uint32_t bb = base + 2*AST*2;
        #pragma unroll
        for (int it=0; it<JT; it++) {
            int r = lr + it*32;
            if (col0 + r < a.Nc) {
                uint32_t d = bb + (uint32_t)((r*APAD + lc)*2);
                CP16(d,         z.Bh + (size_t)(col0+r)*a.ldb + ch*64 + lc);
                CP16(d + BST*2, z.Bl + (size_t)(col0+r)*a.ldb + ch*64 + lc);
            }
        }
        asm volatile("cp.async.commit_group;");
    };

    float acc[4][JT][4] = {};
    issue(0, 0);
    for (int ch = 0; ch < nch; ch++) {
        int st = ch & 1;
        if (ch + 1 < nch) {
            issue(ch+1, st^1);
            asm volatile("cp.async.wait_group 1;");
        } else {
            asm volatile("cp.async.wait_group 0;");
        }
        __syncthreads();
        uint32_t bAh = smb + (uint32_t)(st*STAGE*2);
        uint32_t bAl = bAh + AST*2;
        uint32_t bBh = bAh + 2*AST*2;
        uint32_t bBl = bBh + BST*2;
        int l15 = lane & 15, lhi = (lane >> 4)*8;
        #pragma unroll
        for (int ks = 0; ks < 4; ks++) {
            uint32_t Afh[4][4], Afl[4][4], Bfh[JT][2], Bfl[JT][2];
            uint32_t aoff = (uint32_t)(((wm*64 + l15)*APAD + ks*16 + lhi)*2);
            #pragma unroll
            for (int i = 0; i < 4; i++) {
                ldsm4(Afh[i][0],Afh[i][1],Afh[i][2],Afh[i][3], bAh + aoff + (uint32_t)(i*16*APAD*2));
                ldsm4(Afl[i][0],Afl[i][1],Afl[i][2],Afl[i][3], bAl + aoff + (uint32_t)(i*16*APAD*2));
            }
            #pragma unroll
            for (int j = 0; j < JT; j += 2) {
                uint32_t boff = (uint32_t)(((wn*8*JT + j*8 + l15)*APAD + ks*16 + lhi)*2);
                ldsm4(Bfh[j][0],Bfh[j+1][0],Bfh[j][1],Bfh[j+1][1], bBh + boff);
                ldsm4(Bfl[j][0],Bfl[j+1][0],Bfl[j][1],Bfl[j+1][1], bBl + boff);
            }
            #pragma unroll
            for (int i = 0; i < 4; i++)
                #pragma unroll
                for (int j = 0; j < JT; j++) {
                    mma16816(acc[i][j], Afh[i], Bfh[j]);
                    mma16816(acc[i][j], Afh[i], Bfl[j]);
                    mma16816(acc[i][j], Afl[i], Bfh[j]);
                }
        }
        __syncthreads();
    }
    #pragma unroll
    for (int i = 0; i < 4; i++) {
        #pragma unroll
        for (int j = 0; j < JT; j++) {
            int gr0 = row0 + wm*64 + i*16 + (lane >> 2);
            int gc  = col0 + wn*8*JT + j*8 + (lane & 3)*2;
            if (gc >= a.Nc) continue;
            #pragma unroll
            for (int h2 = 0; h2 < 2; h2++) {
                int gr = gr0 + h2*8;
                float v0 = acc[i][j][h2*2+0]*a.scale;
                float v1 = acc[i][j][h2*2+1]*a.scale;
                if (z.bias) {
                    if (a.bias_rows) { float bb=z.bias[gr]; v0+=bb; v1+=bb; }
                    else { v0+=z.bias[gc]; v1+=z.bias[gc+1]; }
                }
                if (z.res) {
                    v0 += z.res[(size_t)gr*a.ldo + gc];
                    v1 += z.res[(size_t)gr*a.ldo + gc + 1];
                }
                if (z.outF) {
                    z.outF[(size_t)gr*a.ldo + gc]   = v0;
                    z.outF[(size_t)gr*a.ldo + gc+1] = v1;
                }
                if (z.oh) {
                    if (z.cosv) {
                        int p = (gc & 63) >> 1;
                        float cv = z.cosv[gr*32+p], sv = z.sinv[gr*32+p];
                        float r0 = v0*cv - v1*sv;
                        float r1 = v1*cv + v0*sv;
                        v0 = r0; v1 = r1;
                    }
                    uint32_t hi, lo;
                    split2(v0, v1, hi, lo);
                    size_t o = (size_t)gr*a.ldh + gc;
                    *(uint32_t*)&z.oh[o] = hi;
                    *(uint32_t*)&z.ol[o] = lo;
                }
            }
        }
    }
}
#define SMEMB4 ((2*(2*AST+2*128*APAD))*2)
#define SMEMB2 ((2*(2*AST+2*64*APAD))*2)

// ---------- flash attention ----------
#define KP 72
#define VP 136
#define FK_L (128*KP)
#define FV_H (2*128*KP)
#define FV_L (2*128*KP + 64*VP)
#define FSTAGE (2*128*KP + 2*64*VP)
#define FSMEM_B (2*FSTAGE*2)
#define SC2 (0.125f*1.44269504088896f)   /* scale * log2(e) */

__global__ void __launch_bounds__(256)
flash_attn(const bf* __restrict__ qh_, const bf* __restrict__ ql_,
           const bf* __restrict__ kh_, const bf* __restrict__ kl_,
           const bf* __restrict__ vh_, const bf* __restrict__ vl_,
           bf* __restrict__ aoh_, bf* __restrict__ aol_) {
    extern __shared__ bf fsm[];
    int slice = blockIdx.y;
    int s = slice >> 2, h = slice & 3;
    const bf* qgh = qh_ + (size_t)s*SZ;
    const bf* qgl = ql_ + (size_t)s*SZ;
    const bf* kgh = kh_ + (size_t)s*SZ;
    const bf* kgl = kl_ + (size_t)s*SZ;
    const bf* vgh = vh_ + (size_t)s*SZ + (size_t)(h*64)*2048;
    const bf* vgl = vl_ + (size_t)s*SZ + (size_t)(h*64)*2048;
    bf* outh = aoh_ + (size_t)s*SZ;
    bf* outl = aol_ + (size_t)s*SZ;
    int hcol = h*64;
    int t = threadIdx.x, w = t>>5, lane = t&31;
    int qrow = blockIdx.x*128 + w*16 + (lane>>2);
    uint32_t smb = (uint32_t)__cvta_generic_to_shared(fsm);

    uint32_t Aqh[4][4], Aql[4][4];
    #pragma unroll
    for (int ks=0; ks<4; ks++) {
        int cb = hcol + ks*16 + (lane&3)*2;
        Aqh[ks][0] = *(const uint32_t*)&qgh[(size_t)qrow*256 + cb];
        Aqh[ks][1] = *(const uint32_t*)&qgh[(size_t)(qrow+8)*256 + cb];
        Aqh[ks][2] = *(const uint32_t*)&qgh[(size_t)qrow*256 + cb + 8];
        Aqh[ks][3] = *(const uint32_t*)&qgh[(size_t)(qrow+8)*256 + cb + 8];
        Aql[ks][0] = *(const uint32_t*)&qgl[(size_t)qrow*256 + cb];
        Aql[ks][1] = *(const uint32_t*)&qgl[(size_t)(qrow+8)*256 + cb];
        Aql[ks][2] = *(const uint32_t*)&qgl[(size_t)qrow*256 + cb + 8];
        Aql[ks][3] = *(const uint32_t*)&qgl[(size_t)(qrow+8)*256 + cb + 8];
    }

    auto issue = [&](int ch, int st) {
        uint32_t base = smb + (uint32_t)(st*FSTAGE*2);
        int key0 = ch*128;
        int kr = t>>1, kc = (t&1)*32;
        const bf* skh = kgh + (size_t)(key0+kr)*256 + hcol + kc;
        const bf* skl = kgl + (size_t)(key0+kr)*256 + hcol + kc;
        #pragma unroll
        for (int i=0;i<4;i++) {
            uint32_t d = base + (uint32_t)((kr*KP + kc + i*8)*2);
            CP16(d,           skh + i*8);
            CP16(d + FK_L*2,  skl + i*8);
        }
        int vr = t>>2, vc = (t&3)*32;
        const bf* svh = vgh + (size_t)vr*2048 + key0 + vc;
        const bf* svl = vgl + (size_t)vr*2048 + key0 + vc;
        #pragma unroll
        for (int i=0;i<4;i++) {
            uint32_t d = base + (uint32_t)((FV_H + vr*VP + vc + i*8)*2);
            CP16(d,                 svh + i*8);
            CP16(d + (FV_L-FV_H)*2, svl + i*8);
        }
        asm volatile("cp.async.commit_group;");
    };

    float m_run[2] = {-1e30f, -1e30f};
    float s_run[2] = {0.f, 0.f};
    float oacc[8][4] = {};
    int l15 = lane & 15, lhi = (lane >> 4)*8;

    issue(0, 0);
    for (int ch = 0; ch < 16; ch++) {
        int st = ch & 1;
        if (ch + 1 < 16) { issue(ch+1, st^1); asm volatile("cp.async.wait_group 1;"); }
        else             { asm volatile("cp.async.wait_group 0;"); }
        __syncthreads();
        uint32_t bKh = smb + (uint32_t)(st*FSTAGE*2);
        uint32_t bKl = bKh + FK_L*2;
        uint32_t bVh = bKh + FV_H*2;
        uint32_t bVl = bKh + FV_L*2;

        float sacc[16][4] = {};
        #pragma unroll
        for (int ks = 0; ks < 4; ks++) {
            #pragma unroll
            for (int j = 0; j < 16; j += 2) {
                uint32_t koff = (uint32_t)(((j*8 + l15)*KP + ks*16 + lhi)*2);
                uint32_t Bh[2][2], Bl[2][2];
                ldsm4(Bh[0][0],Bh[1][0],Bh[0][1],Bh[1][1], bKh + koff);
                ldsm4(Bl[0][0],Bl[1][0],Bl[0][1],Bl[1][1], bKl + koff);
                mma16816(sacc[j],   Aqh[ks], Bh[0]);
                mma16816(sacc[j],   Aqh[ks], Bl[0]);
                mma16816(sacc[j],   Aql[ks], Bh[0]);
                mma16816(sacc[j+1], Aqh[ks], Bh[1]);
                mma16816(sacc[j+1], Aqh[ks], Bl[1]);
                mma16816(sacc[j+1], Aql[ks], Bh[1]);
            }
        }
        float mx0 = -1e30f, mx1 = -1e30f;
        #pragma unroll
        for (int j = 0; j < 16; j++) {
            sacc[j][0]*=SC2; sacc[j][1]*=SC2; sacc[j][2]*=SC2; sacc[j][3]*=SC2;
            mx0 = fmaxf(mx0, fmaxf(sacc[j][0], sacc[j][1]));
            mx1 = fmaxf(mx1, fmaxf(sacc[j][2], sacc[j][3]));
        }
        mx0 = fmaxf(mx0, __shfl_xor_sync(0xffffffffu, mx0, 1));
        mx0 = fmaxf(mx0, __shfl_xor_sync(0xffffffffu, mx0, 2));
        mx1 = fmaxf(mx1, __shfl_xor_sync(0xffffffffu, mx1, 1));
        mx1 = fmaxf(mx1, __shfl_xor_sync(0xffffffffu, mx1, 2));
        float nm0 = fmaxf(m_run[0], mx0), nm1 = fmaxf(m_run[1], mx1);
        float al0 = exp2f(m_run[0]-nm0), al1 = exp2f(m_run[1]-nm1);
        float cs0 = 0.f, cs1 = 0.f;
        #pragma unroll
        for (int j = 0; j < 16; j++) {
            float p0=exp2f(sacc[j][0]-nm0), p1=exp2f(sacc[j][1]-nm0);
            float p2=exp2f(sacc[j][2]-nm1), p3=exp2f(sacc[j][3]-nm1);
            sacc[j][0]=p0; sacc[j][1]=p1; sacc[j][2]=p2; sacc[j][3]=p3;
            cs0 += p0+p1; cs1 += p2+p3;
        }
        cs0 += __shfl_xor_sync(0xffffffffu, cs0, 1);
        cs0 += __shfl_xor_sync(0xffffffffu, cs0, 2);
        cs1 += __shfl_xor_sync(0xffffffffu, cs1, 1);
        cs1 += __shfl_xor_sync(0xffffffffu, cs1, 2);
        s_run[0] = s_run[0]*al0 + cs0;
        s_run[1] = s_run[1]*al1 + cs1;
        m_run[0] = nm0; m_run[1] = nm1;
        #pragma unroll
        for (int j2 = 0; j2 < 8; j2++) {
            oacc[j2][0]*=al0; oacc[j2][1]*=al0; oacc[j2][2]*=al1; oacc[j2][3]*=al1;
        }
        #pragma unroll
        for (int kk = 0; kk < 8; kk++) {
            uint32_t Pah[4], Pal[4];
            split2(sacc[2*kk  ][0], sacc[2*kk  ][1], Pah[0], Pal[0]);
            split2(sacc[2*kk  ][2], sacc[2*kk  ][3], Pah[1], Pal[1]);
            split2(sacc[2*kk+1][0], sacc[2*kk+1][1], Pah[2], Pal[2]);
            split2(sacc[2*kk+1][2], sacc[2*kk+1][3], Pah[3], Pal[3]);
            #pragma unroll
            for (int j2 = 0; j2 < 8; j2 += 2) {
                uint32_t voff = (uint32_t)(((j2*8 + l15)*VP + kk*16 + lhi)*2);
                uint32_t Bh[2][2], Bl[2][2];
                ldsm4(Bh[0][0],Bh[1][0],Bh[0][1],Bh[1][1], bVh + voff);
                ldsm4(Bl[0][0],Bl[1][0],Bl[0][1],Bl[1][1], bVl + voff);
                mma16816(oacc[j2],   Pah, Bh[0]);
                mma16816(oacc[j2],   Pah, Bl[0]);
                mma16816(oacc[j2],   Pal, Bh[0]);
                mma16816(oacc[j2+1], Pah, Bh[1]);
                mma16816(oacc[j2+1], Pah, Bl[1]);
                mma16816(oacc[j2+1], Pal, Bh[1]);
            }
        }
        __syncthreads();
    }
    float inv0 = 1.0f/s_run[0], inv1 = 1.0f/s_run[1];
    #pragma unroll
    for (int j2 = 0; j2 < 8; j2++) {
        int col = hcol + j2*8 + (lane&3)*2;
        uint32_t hi, lo;
        split2(oacc[j2][0]*inv0, oacc[j2][1]*inv0, hi, lo);
        *(uint32_t*)&outh[(size_t)qrow*256 + col] = hi;
        *(uint32_t*)&outl[(size_t)qrow*256 + col] = lo;
        split2(oacc[j2][2]*inv1, oacc[j2][3]*inv1, hi, lo);
        *(uint32_t*)&outh[(size_t)(qrow+8)*256 + col] = hi;
        *(uint32_t*)&outl[(size_t)(qrow+8)*256 + col] = lo;
    }
}

// ---------- conversions ----------
__global__ void wconv(const float* __restrict__ w, bf* __restrict__ oh, bf* __restrict__ ol,
                      int mode, size_t total) {
    size_t idx = (size_t)blockIdx.x*256 + threadIdx.x;
    if (idx >= total) return;
    size_t src = idx;
    if (mode==1) { int op=(idx>>8)&255; int o=(op&63)*4+(op>>6); src = (idx & ~(size_t)0xFF00) | ((size_t)o<<8); }
    else if (mode==2) { int cp=idx&255; int c=(cp&63)*4+(cp>>6); src = (idx & ~(size_t)0xFF) | (size_t)c; }
    float v = w[src];
    bf h = __float2bfloat16(v);
    oh[idx]=h; ol[idx]=__float2bfloat16(v-__bfloat162float(h));
}
__global__ void bias_perm(const float* __restrict__ pb, float* __restrict__ out) {
    int idx = blockIdx.x*256 + threadIdx.x;
    int op = idx & 255;
    out[idx] = pb[(idx & ~255) | ((op&63)*4 + (op>>6))];
}
struct TArgs { const float* in[2]; float* xF[2]; bf *yh[2], *yl[2]; };
__global__ void transpose_split(TArgs a) {
    __shared__ float tl[32][33];
    int zz = blockIdx.z, n0 = blockIdx.x*32, c0 = blockIdx.y*32;
    int tx = threadIdx.x&31, ty = threadIdx.x>>5;
    const float* in = a.in[zz];
    #pragma unroll
    for (int r=0;r<4;r++) tl[ty+r*8][tx] = in[(size_t)(c0+ty+r*8)*NN + n0+tx];
    __syncthreads();
    #pragma unroll
    for (int r=0;r<4;r++) {
        int n=n0+ty+r*8, c=c0+tx;
        float v = tl[tx][ty+r*8];
        a.xF[zz][(size_t)n*256+c]=v;
        bf h=__float2bfloat16(v);
        a.yh[zz][(size_t)n*512+c]=h;
        a.yl[zz][(size_t)n*512+c]=__float2bfloat16(v-__bfloat162float(h));
    }
}
__global__ void posenc_kernel(const float* __restrict__ kpts, const float* __restrict__ Wr,
                              float* __restrict__ cosv, float* __restrict__ sinv) {
    int idx = blockIdx.x*256 + threadIdx.x;
    if (idx >= NN*32) return;
    int p = idx & 31, n = idx >> 5;
    float kx = (kpts[2*n+0]-512.0f)*(1.0f/716.8f);
    float ky = (kpts[2*n+1]-384.0f)*(1.0f/716.8f);
    float pr = kx*Wr[2*p+0] + ky*Wr[2*p+1];
    cosv[idx] = cosf(pr); sinv[idx] = sinf(pr);
}
// ---------- batchnorm: full-grid two-pass ----------
__global__ void __launch_bounds__(256)
bn_stats(const float* __restrict__ hf, float* __restrict__ pS, float* __restrict__ pQ) {
    int z = blockIdx.z;
    size_t base = (size_t)z * HSZ;
    int l = threadIdx.x & 63, rr = threadIdx.x >> 6;
    int c = blockIdx.x*64 + l;
    int r0 = blockIdx.y*128;
    float su=0.f, sq=0.f;
    for (int n = r0+rr; n < r0+128; n += 4) {
        float x = hf[base + (size_t)n*512 + c];
        su += x; sq += x*x;
    }
    __shared__ float sS[4][64], sQ[4][64];
    sS[rr][l]=su; sQ[rr][l]=sq;
    __syncthreads();
    if (rr==0) {
        float S=0.f, Q=0.f;
        #pragma unroll
        for (int i=0;i<4;i++){ S+=sS[i][l]; Q+=sQ[i][l]; }
        int o = (z*16 + blockIdx.y)*512 + c;
        pS[o]=S; pQ[o]=Q;
    }
}
__global__ void __launch_bounds__(256)
bn_apply(const float* __restrict__ hf, const float* __restrict__ pS, const float* __restrict__ pQ,
         const float* __restrict__ g, const float* __restrict__ b,
         bf* __restrict__ oh, bf* __restrict__ ol) {
    int z = blockIdx.z;
    size_t base = (size_t)z * HSZ;
    __shared__ float sc[64], sh[64];
    int l = threadIdx.x & 63;
    if (threadIdx.x < 64) {
        int c = blockIdx.x*64 + threadIdx.x;
        float S=0.f, Q=0.f;
        #pragma unroll
        for (int k=0;k<16;k++){ S+=pS[(z*16+k)*512+c]; Q+=pQ[(z*16+k)*512+c]; }
        float mean=S*(1.0f/NN), var=Q*(1.0f/NN)-mean*mean;
        float s1=g[c]*rsqrtf(var+1e-5f);
        sc[threadIdx.x]=s1; sh[threadIdx.x]=b[c]-mean*s1;
    }
    __syncthreads();
    int c = blockIdx.x*64 + l;
    int rr = threadIdx.x >> 6, r0 = blockIdx.y*128;
    float s1=sc[l], s2=sh[l];
    for (int n = r0+rr; n < r0+128; n += 4) {
        float v=fmaxf(hf[base+(size_t)n*512+c]*s1+s2, 0.0f);
        bf h=__float2bfloat16(v);
        oh[base+(size_t)n*512+c]=h;
        ol[base+(size_t)n*512+c]=__float2bfloat16(v-__bfloat162float(h));
    }
}
// ---------- Sinkhorn ----------
__global__ void bins_kernel(float* __restrict__ C, const float* __restrict__ a) {
    int i = blockIdx.x*256 + threadIdx.x;
    if (i >= NP1) return;
    float v = a[0];
    C[(size_t)i*NP1 + NN] = v;
    C[(size_t)NN*NP1 + i] = v;
}
__global__ void zero_kernel(float* p, int n) { int i=blockIdx.x*256+threadIdx.x; if(i<n) p[i]=0.f; }
__global__ void __launch_bounds__(256)
u_update_kernel(const float* __restrict__ C, const float* __restrict__ vv, float* __restrict__ u) {
    __shared__ float sm[8];
    int i = blockIdx.x;
    const float* row = C + (size_t)i*NP1;
    int t = threadIdx.x;
    float mx = -1e30f;
    for (int j=t; j<NP1; j+=256) mx = fmaxf(mx, row[j]+vv[j]);
    #pragma unroll
    for (int o=16;o>0;o>>=1) mx=fmaxf(mx,__shfl_xor_sync(0xffffffffu,mx,o));
    if ((t&31)==0) sm[t>>5]=mx;
    __syncthreads();
    mx=sm[0];
    #pragma unroll
    for (int w=1;w<8;w++) mx=fmaxf(mx,sm[w]);
    float s=0.f;
    for (int j=t; j<NP1; j+=256) s += __expf(row[j]+vv[j]-mx);
    #pragma unroll
    for (int o=16;o>0;o>>=1) s+=__shfl_xor_sync(0xffffffffu,s,o);
    __syncthreads();
    if ((t&31)==0) sm[t>>5]=s;
    __syncthreads();
    s=0.f;
    #pragma unroll
    for (int w=0;w<8;w++) s+=sm[w];
    if (t==0) u[i] = ((i<NN)?NORMC:(LOGN+NORMC)) - (mx + logf(s));
}
__global__ void v_part_kernel(const float* __restrict__ C, const float* __restrict__ u,
                              float* __restrict__ pm, float* __restrict__ ps) {
    int j = blockIdx.x*256 + threadIdx.x;
    if (j >= NP1) return;
    int rc = blockIdx.y, i0 = rc*129, i1 = min(i0+129, NP1);
    float m=-1e30f, s=0.f;
    for (int i=i0; i<i1; i++) {
        float x = C[(size_t)i*NP1+j] + u[i];
        if (x>m) { s=s*__expf(m-x)+1.f; m=x; } else s+=__expf(x-m);
    }
    pm[rc*NP1+j]=m; ps[rc*NP1+j]=s;
}
__global__ void v_combine_kernel(const float* __restrict__ pm, const float* __restrict__ ps,
                                 float* __restrict__ vv) {
    int j = blockIdx.x*256 + threadIdx.x;
    if (j >= NP1) return;
    float M=-1e30f;
    #pragma unroll
    for (int rc=0;rc<16;rc++) M=fmaxf(M, pm[rc*NP1+j]);
    float S=0.f;
    #pragma unroll
    for (int rc=0;rc<16;rc++) S+=ps[rc*NP1+j]*__expf(pm[rc*NP1+j]-M);
    vv[j] = ((j<NN)?NORMC:(LOGN+NORMC)) - (M + logf(S));
}
__global__ void final_add_kernel(float* __restrict__ C, const float* __restrict__ u,
                                 const float* __restrict__ vv) {
    int idx = blockIdx.x*256 + threadIdx.x;
    if (idx >= NP1*NP1) return;
    C[idx] += u[idx/NP1] + vv[idx%NP1] + LOG4096;
}

// ---------- host ----------
#define GSA(p,s) cudaGetSymbolAddress((void**)&(p), s)
extern "C" void kernel_launch(void* const* d_in, const int* in_sizes, int n_in,
                              void* d_out, int out_size) {
    (void)in_sizes; (void)n_in; (void)out_size;
    const float *desc0=(const float*)d_in[0], *desc1=(const float*)d_in[1];
    const float *kpts0=(const float*)d_in[2], *kpts1=(const float*)d_in[3];
    const float *Wr=(const float*)d_in[4], *proj_w=(const float*)d_in[5];
    const float *proj_b=(const float*)d_in[6];
    const float *merge_w=(const float*)d_in[7], *merge_b=(const float*)d_in[8];
    const float *mlp_w1=(const float*)d_in[9], *mlp_b1=(const float*)d_in[10];
    const float *bn_g=(const float*)d_in[11], *bn_b=(const float*)d_in[12];
    const float *mlp_w2=(const float*)d_in[13], *mlp_b2=(const float*)d_in[14];
    const float *fp_w=(const float*)d_in[15], *fp_b=(const float*)d_in[16];
    const float *binsc=(const float*)d_in[17];
    float* C = (float*)d_out;

    cudaFuncSetAttribute(mma_gemm<4>, cudaFuncAttributeMaxDynamicSharedMemorySize, SMEMB4);
    cudaFuncSetAttribute(mma_gemm<2>, cudaFuncAttributeMaxDynamicSharedMemorySize, SMEMB2);
    cudaFuncSetAttribute(flash_attn, cudaFuncAttributeMaxDynamicSharedMemorySize, FSMEM_B);

    float *xF,*hf,*pbp,*cs,*pu,*pvv,*ppm,*pps,*bnS,*bnQ;
    bf *yh,*yl,*qh,*ql,*kh,*kl,*vh,*vl,*aoh,*aol,*hh,*hl;
    bf *wqh,*wql,*wmh,*wml,*w1h,*w1l,*w2h,*w2l,*fph,*fpl;
    GSA(xF,g_xF); GSA(hf,g_hf);
    GSA(yh,g_yh); GSA(yl,g_yl); GSA(qh,g_qh); GSA(ql,g_ql);
    GSA(kh,g_kh); GSA(kl,g_kl); GSA(vh,g_vh); GSA(vl,g_vl);
    GSA(aoh,g_aoh); GSA(aol,g_aol); GSA(hh,g_hh); GSA(hl,g_hl);
    GSA(wqh,g_wqh); GSA(wql,g_wql); GSA(wmh,g_wmh); GSA(wml,g_wml);
    GSA(w1h,g_w1h); GSA(w1l,g_w1l); GSA(w2h,g_w2h); GSA(w2l,g_w2l);
    GSA(fph,g_fph); GSA(fpl,g_fpl); GSA(pbp,g_pbp); GSA(cs,g_cs);
    GSA(bnS,g_bnS); GSA(bnQ,g_bnQ);
    GSA(pu,g_u); GSA(pvv,g_vv); GSA(ppm,g_pm); GSA(pps,g_ps);
    float *c0=cs, *s0=cs+NN*32, *c1=cs+2*NN*32, *s1=cs+3*NN*32;

    wconv<<<30*65536/256,256>>>(proj_w, wqh, wql, 1, (size_t)30*65536);
    wconv<<<10*65536/256,256>>>(merge_w, wmh, wml, 2, (size_t)10*65536);
    wconv<<<10*262144/256,256>>>(mlp_w1, w1h, w1l, 0, (size_t)10*262144);
    wconv<<<10*131072/256,256>>>(mlp_w2, w2h, w2l, 0, (size_t)10*131072);
    wconv<<<65536/256,256>>>(fp_w, fph, fpl, 0, 65536);
    bias_perm<<<30,256>>>(proj_b, pbp);
    posenc_kernel<<<NN*32/256,256>>>(kpts0, Wr, c0, s0);
    posenc_kernel<<<NN*32/256,256>>>(kpts1, Wr, c1, s1);
    TArgs ta;
    ta.in[0]=desc0; ta.in[1]=desc1;
    for (int s=0;s<2;s++){ ta.xF[s]=xF+s*SZ; ta.yh[s]=yh+s*HSZ; ta.yl[s]=yl+s*HSZ; }
    transpose_split<<<dim3(64,8,2),256>>>(ta);

    for (int l=0; l<10; l++) {
        int even = !(l&1);
        int src[2] = { even?0:1, even?1:0 };
        const float* mb  = merge_b + l*256;
        const float* b1  = mlp_b1 + l*512;
        const float* b2  = mlp_b2 + l*256;
        const float* csv[2] = { c0, c1 };
        const float* snv[2] = { s0, s1 };

        // q,k projections with fused RoPE+split
        MArgs mq = {};
        mq.lda=512; mq.ldb=256; mq.ldo=256; mq.ldh=256; mq.K=256; mq.Nc=256; mq.scale=1.f;
        for (int s=0;s<2;s++) {
            MZ* zq=&mq.z[s*2], *zk=&mq.z[s*2+1];
            zq->Ah=yh+s*HSZ; zq->Al=yl+s*HSZ;
            zq->Bh=wqh+(size_t)(l*3)*65536; zq->Bl=wql+(size_t)(l*3)*65536;
            zq->bias=pbp+(l*3)*256; zq->oh=qh+s*SZ; zq->ol=ql+s*SZ;
            zk->Ah=yh+src[s]*HSZ; zk->Al=yl+src[s]*HSZ;
            zk->Bh=wqh+(size_t)(l*3+1)*65536; zk->Bl=wql+(size_t)(l*3+1)*65536;
            zk->bias=pbp+(l*3+1)*256; zk->oh=kh+s*SZ; zk->ol=kl+s*SZ;
            if (even) {
                zq->cosv=csv[s]; zq->sinv=snv[s];
                zk->cosv=csv[s]; zk->sinv=snv[s];
            }
        }
        mma_gemm<4><<<dim3(16,2,4),256,SMEMB4>>>(mq);

        // v projection (transposed out) — JT=2 for full-grid occupancy
        MArgs mv = {};
        mv.lda=256; mv.ldb=512; mv.ldo=2048; mv.ldh=2048; mv.K=256; mv.Nc=2048;
        mv.scale=1.f; mv.bias_rows=1;
        for (int s=0;s<2;s++) {
            MZ* zv=&mv.z[s];
            zv->Ah=wqh+(size_t)(l*3+2)*65536; zv->Al=wql+(size_t)(l*3+2)*65536;
            zv->Bh=yh+src[s]*HSZ; zv->Bl=yl+src[s]*HSZ;
            zv->bias=pbp+(l*3+2)*256; zv->oh=vh+s*SZ; zv->ol=vl+s*SZ;
        }
        mma_gemm<2><<<dim3(2,32,2),256,SMEMB2>>>(mv);

        // fused attention
        flash_attn<<<dim3(16,8),256,FSMEM_B>>>(qh,ql,kh,kl,vh,vl,aoh,aol);

        // merge -> y cols 256:511 — JT=2
        MArgs mm = {};
        mm.lda=256; mm.ldb=256; mm.ldh=512; mm.K=256; mm.Nc=256; mm.scale=1.f;
        for (int s=0;s<2;s++) {
            MZ* zz=&mm.z[s];
            zz->Ah=aoh+s*SZ; zz->Al=aol+s*SZ;
            zz->Bh=wmh+(size_t)l*65536; zz->Bl=wml+(size_t)l*65536;
            zz->bias=mb; zz->oh=yh+s*HSZ+256; zz->ol=yl+s*HSZ+256;
        }
        mma_gemm<2><<<dim3(16,4,2),256,SMEMB2>>>(mm);

        // mlp1 -> h fp32
        MArgs m1 = {};
        m1.lda=512; m1.ldb=512; m1.ldo=512; m1.K=512; m1.Nc=512; m1.scale=1.f;
        for (int s=0;s<2;s++) {
            MZ* zz=&m1.z[s];
            zz->Ah=yh+s*HSZ; zz->Al=yl+s*HSZ;
            zz->Bh=w1h+(size_t)l*262144; zz->Bl=w1l+(size_t)l*262144;
            zz->bias=b1; zz->outF=hf+s*HSZ;
        }
        mma_gemm<4><<<dim3(16,4,2),256,SMEMB4>>>(m1);
        bn_stats<<<dim3(8,16,2),256>>>(hf, bnS, bnQ);
        bn_apply<<<dim3(8,16,2),256>>>(hf, bnS, bnQ, bn_g+l*512, bn_b+l*512, hh, hl);

        // mlp2 + residual — JT=2
        MArgs m2 = {};
        m2.lda=512; m2.ldb=512; m2.ldo=256; m2.ldh=512; m2.K=512; m2.Nc=256; m2.scale=1.f;
        for (int s=0;s<2;s++) {
            MZ* zz=&m2.z[s];
            zz->Ah=hh+s*HSZ; zz->Al=hl+s*HSZ;
            zz->Bh=w2h+(size_t)l*131072; zz->Bl=w2l+(size_t)l*131072;
            zz->bias=b2; zz->res=xF+s*SZ; zz->outF=xF+s*SZ;
            zz->oh=yh+s*HSZ; zz->ol=yl+s*HSZ;
        }
        mma_gemm<2><<<dim3(16,4,2),256,SMEMB2>>>(m2);
    }

    // final projection — JT=2
    MArgs mf = {};
    mf.lda=512; mf.ldb=256; mf.ldh=256; mf.K=256; mf.Nc=256; mf.scale=1.f;
    for (int s=0;s<2;s++) {
        MZ* zz=&mf.z[s];
        zz->Ah=yh+s*HSZ; zz->Al=yl+s*HSZ;
        zz->Bh=fph; zz->Bl=fpl;
        zz->bias=fp_b; zz->oh=qh+s*SZ; zz->ol=ql+s*SZ;
    }
    mma_gemm<2><<<dim3(16,4,2),256,SMEMB2>>>(mf);

    // final match scores into C (ld 2049)
    MArgs mc = {};
    mc.lda=256; mc.ldb=256; mc.ldo=NP1; mc.K=256; mc.Nc=2048; mc.scale=0.0625f;
    mc.z[0].Ah=qh; mc.z[0].Al=ql; mc.z[0].Bh=qh+SZ; mc.z[0].Bl=ql+SZ;
    mc.z[0].outF=C;
    mma_gemm<4><<<dim3(16,16,1),256,SMEMB4>>>(mc);
    bins_kernel<<<(NP1+255)/256,256>>>(C, binsc);

    zero_kernel<<<(NP1+255)/256,256>>>(pvv, NP1);
    for (int t=0; t<20; t++) {
        u_update_kernel<<<NP1,256>>>(C, pvv, pu);
        v_part_kernel<<<dim3((NP1+255)/256,16),256>>>(C, pu, ppm, pps);
        v_combine_kernel<<<(NP1+255)/256,256>>>(ppm, pps, pvv);
    }
    final_add_kernel<<<(NP1*NP1+255)/256,256>>>(C, pu, pvv);
}

// round 10
// speedup vs baseline: 3.8432x; 1.1428x over previous
#include <cuda_runtime.h>
#include <cuda_bf16.h>
#include <math.h>
#include <stdint.h>

#define NN 2048
#define DM 256
#define NP1 2049
#define NORMC (-8.317766166719343f)
#define LOGN (7.624618986159398f)
#define LOG4096 (8.317766166719343f)
#define SZ ((size_t)NN*DM)
#define HSZ ((size_t)NN*512)
typedef __nv_bfloat16 bf;

// ---------- static scratch ----------
__device__ float g_xF[2*SZ], g_hf[2*HSZ];
__device__ bf g_yh[2*HSZ], g_yl[2*HSZ];
__device__ bf g_qh[2*SZ], g_ql[2*SZ], g_kh[2*SZ], g_kl[2*SZ];
__device__ bf g_vh[2*SZ], g_vl[2*SZ], g_aoh[2*SZ], g_aol[2*SZ];
__device__ bf g_hh[2*HSZ], g_hl[2*HSZ];
__device__ bf g_wqh[30*65536], g_wql[30*65536], g_wmh[10*65536], g_wml[10*65536];
__device__ bf g_w1h[10*262144], g_w1l[10*262144], g_w2h[10*131072], g_w2l[10*131072];
__device__ bf g_fph[65536], g_fpl[65536];
__device__ float g_pbp[30*256];
__device__ float g_cs[4*NN*32];
__device__ float g_bnS[2*16*512], g_bnQ[2*16*512];
__device__ float g_u[NP1], g_vv[NP1], g_pm[16*NP1], g_ps[16*NP1];

// ---------- HMMA m16n8k16 bf16 + ldmatrix ----------
__device__ __forceinline__ void mma16816(float* c, const uint32_t* a, const uint32_t* b) {
    asm volatile("mma.sync.aligned.m16n8k16.row.col.f32.bf16.bf16.f32 "
        "{%0,%1,%2,%3}, {%4,%5,%6,%7}, {%8,%9}, {%0,%1,%2,%3};"
        : "+f"(c[0]), "+f"(c[1]), "+f"(c[2]), "+f"(c[3])
        : "r"(a[0]), "r"(a[1]), "r"(a[2]), "r"(a[3]), "r"(b[0]), "r"(b[1]));
}
__device__ __forceinline__ void ldsm4(uint32_t& r0, uint32_t& r1, uint32_t& r2, uint32_t& r3,
                                      uint32_t addr) {
    asm volatile("ldmatrix.sync.aligned.m8n8.x4.shared.b16 {%0,%1,%2,%3}, [%4];"
        : "=r"(r0), "=r"(r1), "=r"(r2), "=r"(r3) : "r"(addr));
}
#define CP16(dst, src) asm volatile("cp.async.ca.shared.global [%0], [%1], 16;" :: "r"(dst), "l"(src))

__device__ __forceinline__ uint32_t pkbf(float x, float y) {
    __nv_bfloat162 t = __floats2bfloat162_rn(x, y);
    return *(uint32_t*)&t;
}
__device__ __forceinline__ void split2(float x, float y, uint32_t& hi, uint32_t& lo) {
    bf hx = __float2bfloat16(x), hy = __float2bfloat16(y);
    __nv_bfloat162 hp; hp.x = hx; hp.y = hy;
    hi = *(uint32_t*)&hp;
    lo = pkbf(x - __bfloat162float(hx), y - __bfloat162float(hy));
}

// ---------- generic split-bf16 HMMA GEMM ----------
struct MZ { const bf *Ah,*Al,*Bh,*Bl; const float *bias,*res; float *outF; bf *oh,*ol;
            const float *cosv,*sinv; };
struct MArgs { MZ z[8]; int lda,ldb,ldo,ldh,K,Nc,bias_rows; float scale; };

#define APAD 72
#define AST (128*APAD)

template<int JT>
__global__ void __launch_bounds__(256) mma_gemm(MArgs a) {
    constexpr int CTAC = 32*JT;
    constexpr int BST = CTAC*APAD;
    constexpr int STAGE = 2*AST + 2*BST;
    extern __shared__ bf smem[];
    MZ z = a.z[blockIdx.z];
    int t = threadIdx.x, w = t>>5, lane = t&31;
    int wm = w & 1, wn = w >> 1;
    int row0 = blockIdx.x*128, col0 = blockIdx.y*CTAC;
    uint32_t smb = (uint32_t)__cvta_generic_to_shared(smem);
    int lr = t >> 3, lc = (t & 7) * 8;
    int nch = a.K >> 6;

    auto issue = [&](int ch, int st) {
        uint32_t base = smb + (uint32_t)(st*STAGE*2);
        const bf* Agh = z.Ah + (size_t)(row0+lr)*a.lda + ch*64 + lc;
        const bf* Agl = z.Al + (size_t)(row0+lr)*a.lda + ch*64 + lc;
        #pragma unroll
        for (int it=0; it<4; it++) {
            uint32_t d = base + (uint32_t)(((lr+it*32)*APAD + lc)*2);
            CP16(d,           Agh + (size_t)it*32*a.lda);
            CP16(d + AST*2,   Agl + (size_t)it*32*a.lda);
        }
        uint32_t bb = base + 2*AST*2;
        #pragma unroll
        for (int it=0; it<JT; it++) {
            int r = lr + it*32;
            if (col0 + r < a.Nc) {
                uint32_t d = bb + (uint32_t)((r*APAD + lc)*2);
                CP16(d,         z.Bh + (size_t)(col0+r)*a.ldb + ch*64 + lc);
                CP16(d + BST*2, z.Bl + (size_t)(col0+r)*a.ldb + ch*64 + lc);
            }
        }
        asm volatile("cp.async.commit_group;");
    };

    float acc[4][JT][4] = {};
    issue(0, 0);
    for (int ch = 0; ch < nch; ch++) {
        int st = ch & 1;
        if (ch + 1 < nch) {
            issue(ch+1, st^1);
            asm volatile("cp.async.wait_group 1;");
        } else {
            asm volatile("cp.async.wait_group 0;");
        }
        __syncthreads();
        uint32_t bAh = smb + (uint32_t)(st*STAGE*2);
        uint32_t bAl = bAh + AST*2;
        uint32_t bBh = bAh + 2*AST*2;
        uint32_t bBl = bBh + BST*2;
        int l15 = lane & 15, lhi = (lane >> 4)*8;
        #pragma unroll
        for (int ks = 0; ks < 4; ks++) {
            uint32_t Afh[4][4], Afl[4][4], Bfh[JT][2], Bfl[JT][2];
            uint32_t aoff = (uint32_t)(((wm*64 + l15)*APAD + ks*16 + lhi)*2);
            #pragma unroll
            for (int i = 0; i < 4; i++) {
                ldsm4(Afh[i][0],Afh[i][1],Afh[i][2],Afh[i][3], bAh + aoff + (uint32_t)(i*16*APAD*2));
                ldsm4(Afl[i][0],Afl[i][1],Afl[i][2],Afl[i][3], bAl + aoff + (uint32_t)(i*16*APAD*2));
            }
            #pragma unroll
            for (int j = 0; j < JT; j += 2) {
                uint32_t boff = (uint32_t)(((wn*8*JT + j*8 + l15)*APAD + ks*16 + lhi)*2);
                ldsm4(Bfh[j][0],Bfh[j+1][0],Bfh[j][1],Bfh[j+1][1], bBh + boff);
                ldsm4(Bfl[j][0],Bfl[j+1][0],Bfl[j][1],Bfl[j+1][1], bBl + boff);
            }
            #pragma unroll
            for (int i = 0; i < 4; i++)
                #pragma unroll
                for (int j = 0; j < JT; j++) {
                    mma16816(acc[i][j], Afh[i], Bfh[j]);
                    mma16816(acc[i][j], Afh[i], Bfl[j]);
                    mma16816(acc[i][j], Afl[i], Bfh[j]);
                }
        }
        __syncthreads();
    }
    #pragma unroll
    for (int i = 0; i < 4; i++) {
        #pragma unroll
        for (int j = 0; j < JT; j++) {
            int gr0 = row0 + wm*64 + i*16 + (lane >> 2);
            int gc  = col0 + wn*8*JT + j*8 + (lane & 3)*2;
            if (gc >= a.Nc) continue;
            #pragma unroll
            for (int h2 = 0; h2 < 2; h2++) {
                int gr = gr0 + h2*8;
                float v0 = acc[i][j][h2*2+0]*a.scale;
                float v1 = acc[i][j][h2*2+1]*a.scale;
                if (z.bias) {
                    if (a.bias_rows) { float bb=z.bias[gr]; v0+=bb; v1+=bb; }
                    else { v0+=z.bias[gc]; v1+=z.bias[gc+1]; }
                }
                if (z.res) {
                    v0 += z.res[(size_t)gr*a.ldo + gc];
                    v1 += z.res[(size_t)gr*a.ldo + gc + 1];
                }
                if (z.outF) {
                    z.outF[(size_t)gr*a.ldo + gc]   = v0;
                    z.outF[(size_t)gr*a.ldo + gc+1] = v1;
                }
                if (z.oh) {
                    if (z.cosv) {
                        int p = (gc & 63) >> 1;
                        float cv = z.cosv[gr*32+p], sv = z.sinv[gr*32+p];
                        float r0 = v0*cv - v1*sv;
                        float r1 = v1*cv + v0*sv;
                        v0 = r0; v1 = r1;
                    }
                    uint32_t hi, lo;
                    split2(v0, v1, hi, lo);
                    size_t o = (size_t)gr*a.ldh + gc;
                    *(uint32_t*)&z.oh[o] = hi;
                    *(uint32_t*)&z.ol[o] = lo;
                }
            }
        }
    }
}
#define SMEMB4 ((2*(2*AST+2*128*APAD))*2)
#define SMEMB2 ((2*(2*AST+2*64*APAD))*2)

// ---------- flash attention (PV single-term: O = Ph*Vh; S stays 3-term) ----------
#define KP 72
#define VP 136
#define FK_L (128*KP)
#define FV_H (2*128*KP)
#define FSTAGE (2*128*KP + 64*VP)
#define FSMEM_B (2*FSTAGE*2)
#define SC2 (0.125f*1.44269504088896f)   /* scale * log2(e) */

__global__ void __launch_bounds__(256)
flash_attn(const bf* __restrict__ qh_, const bf* __restrict__ ql_,
           const bf* __restrict__ kh_, const bf* __restrict__ kl_,
           const bf* __restrict__ vh_,
           bf* __restrict__ aoh_, bf* __restrict__ aol_) {
    extern __shared__ bf fsm[];
    int slice = blockIdx.y;
    int s = slice >> 2, h = slice & 3;
    const bf* qgh = qh_ + (size_t)s*SZ;
    const bf* qgl = ql_ + (size_t)s*SZ;
    const bf* kgh = kh_ + (size_t)s*SZ;
    const bf* kgl = kl_ + (size_t)s*SZ;
    const bf* vgh = vh_ + (size_t)s*SZ + (size_t)(h*64)*2048;
    bf* outh = aoh_ + (size_t)s*SZ;
    bf* outl = aol_ + (size_t)s*SZ;
    int hcol = h*64;
    int t = threadIdx.x, w = t>>5, lane = t&31;
    int qrow = blockIdx.x*128 + w*16 + (lane>>2);
    uint32_t smb = (uint32_t)__cvta_generic_to_shared(fsm);

    uint32_t Aqh[4][4], Aql[4][4];
    #pragma unroll
    for (int ks=0; ks<4; ks++) {
        int cb = hcol + ks*16 + (lane&3)*2;
        Aqh[ks][0] = *(const uint32_t*)&qgh[(size_t)qrow*256 + cb];
        Aqh[ks][1] = *(const uint32_t*)&qgh[(size_t)(qrow+8)*256 + cb];
        Aqh[ks][2] = *(const uint32_t*)&qgh[(size_t)qrow*256 + cb + 8];
        Aqh[ks][3] = *(const uint32_t*)&qgh[(size_t)(qrow+8)*256 + cb + 8];
        Aql[ks][0] = *(const uint32_t*)&qgl[(size_t)qrow*256 + cb];
        Aql[ks][1] = *(const uint32_t*)&qgl[(size_t)(qrow+8)*256 + cb];
        Aql[ks][2] = *(const uint32_t*)&qgl[(size_t)qrow*256 + cb + 8];
        Aql[ks][3] = *(const uint32_t*)&qgl[(size_t)(qrow+8)*256 + cb + 8];
    }

    auto issue = [&](int ch, int st) {
        uint32_t base = smb + (uint32_t)(st*FSTAGE*2);
        int key0 = ch*128;
        int kr = t>>1, kc = (t&1)*32;
        const bf* skh = kgh + (size_t)(key0+kr)*256 + hcol + kc;
        const bf* skl = kgl + (size_t)(key0+kr)*256 + hcol + kc;
        #pragma unroll
        for (int i=0;i<4;i++) {
            uint32_t d = base + (uint32_t)((kr*KP + kc + i*8)*2);
            CP16(d,           skh + i*8);
            CP16(d + FK_L*2,  skl + i*8);
        }
        int vr = t>>2, vc = (t&3)*32;
        const bf* svh = vgh + (size_t)vr*2048 + key0 + vc;
        #pragma unroll
        for (int i=0;i<4;i++) {
            uint32_t d = base + (uint32_t)((FV_H + vr*VP + vc + i*8)*2);
            CP16(d, svh + i*8);
        }
        asm volatile("cp.async.commit_group;");
    };

    float m_run[2] = {-1e30f, -1e30f};
    float s_run[2] = {0.f, 0.f};
    float oacc[8][4] = {};
    int l15 = lane & 15, lhi = (lane >> 4)*8;

    issue(0, 0);
    for (int ch = 0; ch < 16; ch++) {
        int st = ch & 1;
        if (ch + 1 < 16) { issue(ch+1, st^1); asm volatile("cp.async.wait_group 1;"); }
        else             { asm volatile("cp.async.wait_group 0;"); }
        __syncthreads();
        uint32_t bKh = smb + (uint32_t)(st*FSTAGE*2);
        uint32_t bKl = bKh + FK_L*2;
        uint32_t bVh = bKh + FV_H*2;

        float sacc[16][4] = {};
        #pragma unroll
        for (int ks = 0; ks < 4; ks++) {
            #pragma unroll
            for (int j = 0; j < 16; j += 2) {
                uint32_t koff = (uint32_t)(((j*8 + l15)*KP + ks*16 + lhi)*2);
                uint32_t Bh[2][2], Bl[2][2];
                ldsm4(Bh[0][0],Bh[1][0],Bh[0][1],Bh[1][1], bKh + koff);
                ldsm4(Bl[0][0],Bl[1][0],Bl[0][1],Bl[1][1], bKl + koff);
                mma16816(sacc[j],   Aqh[ks], Bh[0]);
                mma16816(sacc[j],   Aqh[ks], Bl[0]);
                mma16816(sacc[j],   Aql[ks], Bh[0]);
                mma16816(sacc[j+1], Aqh[ks], Bh[1]);
                mma16816(sacc[j+1], Aqh[ks], Bl[1]);
                mma16816(sacc[j+1], Aql[ks], Bh[1]);
            }
        }
        float mx0 = -1e30f, mx1 = -1e30f;
        #pragma unroll
        for (int j = 0; j < 16; j++) {
            sacc[j][0]*=SC2; sacc[j][1]*=SC2; sacc[j][2]*=SC2; sacc[j][3]*=SC2;
            mx0 = fmaxf(mx0, fmaxf(sacc[j][0], sacc[j][1]));
            mx1 = fmaxf(mx1, fmaxf(sacc[j][2], sacc[j][3]));
        }
        mx0 = fmaxf(mx0, __shfl_xor_sync(0xffffffffu, mx0, 1));
        mx0 = fmaxf(mx0, __shfl_xor_sync(0xffffffffu, mx0, 2));
        mx1 = fmaxf(mx1, __shfl_xor_sync(0xffffffffu, mx1, 1));
        mx1 = fmaxf(mx1, __shfl_xor_sync(0xffffffffu, mx1, 2));
        float nm0 = fmaxf(m_run[0], mx0), nm1 = fmaxf(m_run[1], mx1);
        float al0 = exp2f(m_run[0]-nm0), al1 = exp2f(m_run[1]-nm1);
        float cs0 = 0.f, cs1 = 0.f;
        #pragma unroll
        for (int j = 0; j < 16; j++) {
            float p0=exp2f(sacc[j][0]-nm0), p1=exp2f(sacc[j][1]-nm0);
            float p2=exp2f(sacc[j][2]-nm1), p3=exp2f(sacc[j][3]-nm1);
            sacc[j][0]=p0; sacc[j][1]=p1; sacc[j][2]=p2; sacc[j][3]=p3;
            cs0 += p0+p1; cs1 += p2+p3;
        }
        cs0 += __shfl_xor_sync(0xffffffffu, cs0, 1);
        cs0 += __shfl_xor_sync(0xffffffffu, cs0, 2);
        cs1 += __shfl_xor_sync(0xffffffffu, cs1, 1);
        cs1 += __shfl_xor_sync(0xffffffffu, cs1, 2);
        s_run[0] = s_run[0]*al0 + cs0;
        s_run[1] = s_run[1]*al1 + cs1;
        m_run[0] = nm0; m_run[1] = nm1;
        #pragma unroll
        for (int j2 = 0; j2 < 8; j2++) {
            oacc[j2][0]*=al0; oacc[j2][1]*=al0; oacc[j2][2]*=al1; oacc[j2][3]*=al1;
        }
        // O += Ph * Vh (single-term: P,V truncation errors are value-space, ~2^-9 rel with cancellation)
        #pragma unroll
        for (int kk = 0; kk < 8; kk++) {
            uint32_t Pah[4];
            Pah[0] = pkbf(sacc[2*kk  ][0], sacc[2*kk  ][1]);
            Pah[1] = pkbf(sacc[2*kk  ][2], sacc[2*kk  ][3]);
            Pah[2] = pkbf(sacc[2*kk+1][0], sacc[2*kk+1][1]);
            Pah[3] = pkbf(sacc[2*kk+1][2], sacc[2*kk+1][3]);
            #pragma unroll
            for (int j2 = 0; j2 < 8; j2 += 2) {
                uint32_t voff = (uint32_t)(((j2*8 + l15)*VP + kk*16 + lhi)*2);
                uint32_t Bh[2][2];
                ldsm4(Bh[0][0],Bh[1][0],Bh[0][1],Bh[1][1], bVh + voff);
                mma16816(oacc[j2],   Pah, Bh[0]);
                mma16816(oacc[j2+1], Pah, Bh[1]);
            }
        }
        __syncthreads();
    }
    float inv0 = 1.0f/s_run[0], inv1 = 1.0f/s_run[1];
    #pragma unroll
    for (int j2 = 0; j2 < 8; j2++) {
        int col = hcol + j2*8 + (lane&3)*2;
        uint32_t hi, lo;
        split2(oacc[j2][0]*inv0, oacc[j2][1]*inv0, hi, lo);
        *(uint32_t*)&outh[(size_t)qrow*256 + col] = hi;
        *(uint32_t*)&outl[(size_t)qrow*256 + col] = lo;
        split2(oacc[j2][2]*inv1, oacc[j2][3]*inv1, hi, lo);
        *(uint32_t*)&outh[(size_t)(qrow+8)*256 + col] = hi;
        *(uint32_t*)&outl[(size_t)(qrow+8)*256 + col] = lo;
    }
}

// ---------- conversions ----------
__global__ void wconv(const float* __restrict__ w, bf* __restrict__ oh, bf* __restrict__ ol,
                      int mode, size_t total) {
    size_t idx = (size_t)blockIdx.x*256 + threadIdx.x;
    if (idx >= total) return;
    size_t src = idx;
    if (mode==1) { int op=(idx>>8)&255; int o=(op&63)*4+(op>>6); src = (idx & ~(size_t)0xFF00) | ((size_t)o<<8); }
    else if (mode==2) { int cp=idx&255; int c=(cp&63)*4+(cp>>6); src = (idx & ~(size_t)0xFF) | (size_t)c; }
    float v = w[src];
    bf h = __float2bfloat16(v);
    oh[idx]=h; ol[idx]=__float2bfloat16(v-__bfloat162float(h));
}
__global__ void bias_perm(const float* __restrict__ pb, float* __restrict__ out) {
    int idx = blockIdx.x*256 + threadIdx.x;
    int op = idx & 255;
    out[idx] = pb[(idx & ~255) | ((op&63)*4 + (op>>6))];
}
struct TArgs { const float* in[2]; float* xF[2]; bf *yh[2], *yl[2]; };
__global__ void transpose_split(TArgs a) {
    __shared__ float tl[32][33];
    int zz = blockIdx.z, n0 = blockIdx.x*32, c0 = blockIdx.y*32;
    int tx = threadIdx.x&31, ty = threadIdx.x>>5;
    const float* in = a.in[zz];
    #pragma unroll
    for (int r=0;r<4;r++) tl[ty+r*8][tx] = in[(size_t)(c0+ty+r*8)*NN + n0+tx];
    __syncthreads();
    #pragma unroll
    for (int r=0;r<4;r++) {
        int n=n0+ty+r*8, c=c0+tx;
        float v = tl[tx][ty+r*8];
        a.xF[zz][(size_t)n*256+c]=v;
        bf h=__float2bfloat16(v);
        a.yh[zz][(size_t)n*512+c]=h;
        a.yl[zz][(size_t)n*512+c]=__float2bfloat16(v-__bfloat162float(h));
    }
}
__global__ void posenc_kernel(const float* __restrict__ kpts, const float* __restrict__ Wr,
                              float* __restrict__ cosv, float* __restrict__ sinv) {
    int idx = blockIdx.x*256 + threadIdx.x;
    if (idx >= NN*32) return;
    int p = idx & 31, n = idx >> 5;
    float kx = (kpts[2*n+0]-512.0f)*(1.0f/716.8f);
    float ky = (kpts[2*n+1]-384.0f)*(1.0f/716.8f);
    float pr = kx*Wr[2*p+0] + ky*Wr[2*p+1];
    cosv[idx] = cosf(pr); sinv[idx] = sinf(pr);
}
// ---------- batchnorm: full-grid two-pass ----------
__global__ void __launch_bounds__(256)
bn_stats(const float* __restrict__ hf, float* __restrict__ pS, float* __restrict__ pQ) {
    int z = blockIdx.z;
    size_t base = (size_t)z * HSZ;
    int l = threadIdx.x & 63, rr = threadIdx.x >> 6;
    int c = blockIdx.x*64 + l;
    int r0 = blockIdx.y*128;
    float su=0.f, sq=0.f;
    for (int n = r0+rr; n < r0+128; n += 4) {
        float x = hf[base + (size_t)n*512 + c];
        su += x; sq += x*x;
    }
    __shared__ float sS[4][64], sQ[4][64];
    sS[rr][l]=su; sQ[rr][l]=sq;
    __syncthreads();
    if (rr==0) {
        float S=0.f, Q=0.f;
        #pragma unroll
        for (int i=0;i<4;i++){ S+=sS[i][l]; Q+=sQ[i][l]; }
        int o = (z*16 + blockIdx.y)*512 + c;
        pS[o]=S; pQ[o]=Q;
    }
}
__global__ void __launch_bounds__(256)
bn_apply(const float* __restrict__ hf, const float* __restrict__ pS, const float* __restrict__ pQ,
         const float* __restrict__ g, const float* __restrict__ b,
         bf* __restrict__ oh, bf* __restrict__ ol) {
    int z = blockIdx.z;
    size_t base = (size_t)z * HSZ;
    __shared__ float sc[64], sh[64];
    int l = threadIdx.x & 63;
    if (threadIdx.x < 64) {
        int c = blockIdx.x*64 + threadIdx.x;
        float S=0.f, Q=0.f;
        #pragma unroll
        for (int k=0;k<16;k++){ S+=pS[(z*16+k)*512+c]; Q+=pQ[(z*16+k)*512+c]; }
        float mean=S*(1.0f/NN), var=Q*(1.0f/NN)-mean*mean;
        float s1=g[c]*rsqrtf(var+1e-5f);
        sc[threadIdx.x]=s1; sh[threadIdx.x]=b[c]-mean*s1;
    }
    __syncthreads();
    int c = blockIdx.x*64 + l;
    int rr = threadIdx.x >> 6, r0 = blockIdx.y*128;
    float s1=sc[l], s2=sh[l];
    for (int n = r0+rr; n < r0+128; n += 4) {
        float v=fmaxf(hf[base+(size_t)n*512+c]*s1+s2, 0.0f);
        bf h=__float2bfloat16(v);
        oh[base+(size_t)n*512+c]=h;
        ol[base+(size_t)n*512+c]=__float2bfloat16(v-__bfloat162float(h));
    }
}
// ---------- Sinkhorn ----------
__global__ void bins_kernel(float* __restrict__ C, const float* __restrict__ a) {
    int i = blockIdx.x*256 + threadIdx.x;
    if (i >= NP1) return;
    float v = a[0];
    C[(size_t)i*NP1 + NN] = v;
    C[(size_t)NN*NP1 + i] = v;
}
__global__ void zero_kernel(float* p, int n) { int i=blockIdx.x*256+threadIdx.x; if(i<n) p[i]=0.f; }
__global__ void __launch_bounds__(256)
u_update_kernel(const float* __restrict__ C, const float* __restrict__ vv, float* __restrict__ u) {
    __shared__ float sm[8];
    int i = blockIdx.x;
    const float* row = C + (size_t)i*NP1;
    int t = threadIdx.x;
    float mx = -1e30f;
    for (int j=t; j<NP1; j+=256) mx = fmaxf(mx, row[j]+vv[j]);
    #pragma unroll
    for (int o=16;o>0;o>>=1) mx=fmaxf(mx,__shfl_xor_sync(0xffffffffu,mx,o));
    if ((t&31)==0) sm[t>>5]=mx;
    __syncthreads();
    mx=sm[0];
    #pragma unroll
    for (int w=1;w<8;w++) mx=fmaxf(mx,sm[w]);
    float s=0.f;
    for (int j=t; j<NP1; j+=256) s += __expf(row[j]+vv[j]-mx);
    #pragma unroll
    for (int o=16;o>0;o>>=1) s+=__shfl_xor_sync(0xffffffffu,s,o);
    __syncthreads();
    if ((t&31)==0) sm[t>>5]=s;
    __syncthreads();
    s=0.f;
    #pragma unroll
    for (int w=0;w<8;w++) s+=sm[w];
    if (t==0) u[i] = ((i<NN)?NORMC:(LOGN+NORMC)) - (mx + logf(s));
}
__global__ void v_part_kernel(const float* __restrict__ C, const float* __restrict__ u,
                              float* __restrict__ pm, float* __restrict__ ps) {
    int j = blockIdx.x*256 + threadIdx.x;
    if (j >= NP1) return;
    int rc = blockIdx.y, i0 = rc*129, i1 = min(i0+129, NP1);
    float m=-1e30f, s=0.f;
    for (int i=i0; i<i1; i++) {
        float x = C[(size_t)i*NP1+j] + u[i];
        if (x>m) { s=s*__expf(m-x)+1.f; m=x; } else s+=__expf(x-m);
    }
    pm[rc*NP1+j]=m; ps[rc*NP1+j]=s;
}
__global__ void v_combine_kernel(const float* __restrict__ pm, const float* __restrict__ ps,
                                 float* __restrict__ vv) {
    int j = blockIdx.x*256 + threadIdx.x;
    if (j >= NP1) return;
    float M=-1e30f;
    #pragma unroll
    for (int rc=0;rc<16;rc++) M=fmaxf(M, pm[rc*NP1+j]);
    float S=0.f;
    #pragma unroll
    for (int rc=0;rc<16;rc++) S+=ps[rc*NP1+j]*__expf(pm[rc*NP1+j]-M);
    vv[j] = ((j<NN)?NORMC:(LOGN+NORMC)) - (M + logf(S));
}
__global__ void final_add_kernel(float* __restrict__ C, const float* __restrict__ u,
                                 const float* __restrict__ vv) {
    int idx = blockIdx.x*256 + threadIdx.x;
    if (idx >= NP1*NP1) return;
    C[idx] += u[idx/NP1] + vv[idx%NP1] + LOG4096;
}

// ---------- host ----------
#define GSA(p,s) cudaGetSymbolAddress((void**)&(p), s)
extern "C" void kernel_launch(void* const* d_in, const int* in_sizes, int n_in,
                              void* d_out, int out_size) {
    (void)in_sizes; (void)n_in; (void)out_size;
    const float *desc0=(const float*)d_in[0], *desc1=(const float*)d_in[1];
    const float *kpts0=(const float*)d_in[2], *kpts1=(const float*)d_in[3];
    const float *Wr=(const float*)d_in[4], *proj_w=(const float*)d_in[5];
    const float *proj_b=(const float*)d_in[6];
    const float *merge_w=(const float*)d_in[7], *merge_b=(const float*)d_in[8];
    const float *mlp_w1=(const float*)d_in[9], *mlp_b1=(const float*)d_in[10];
    const float *bn_g=(const float*)d_in[11], *bn_b=(const float*)d_in[12];
    const float *mlp_w2=(const float*)d_in[13], *mlp_b2=(const float*)d_in[14];
    const float *fp_w=(const float*)d_in[15], *fp_b=(const float*)d_in[16];
    const float *binsc=(const float*)d_in[17];
    float* C = (float*)d_out;

    cudaFuncSetAttribute(mma_gemm<4>, cudaFuncAttributeMaxDynamicSharedMemorySize, SMEMB4);
    cudaFuncSetAttribute(mma_gemm<2>, cudaFuncAttributeMaxDynamicSharedMemorySize, SMEMB2);
    cudaFuncSetAttribute(flash_attn, cudaFuncAttributeMaxDynamicSharedMemorySize, FSMEM_B);

    float *xF,*hf,*pbp,*cs,*pu,*pvv,*ppm,*pps,*bnS,*bnQ;
    bf *yh,*yl,*qh,*ql,*kh,*kl,*vh,*vl,*aoh,*aol,*hh,*hl;
    bf *wqh,*wql,*wmh,*wml,*w1h,*w1l,*w2h,*w2l,*fph,*fpl;
    GSA(xF,g_xF); GSA(hf,g_hf);
    GSA(yh,g_yh); GSA(yl,g_yl); GSA(qh,g_qh); GSA(ql,g_ql);
    GSA(kh,g_kh); GSA(kl,g_kl); GSA(vh,g_vh); GSA(vl,g_vl);
    GSA(aoh,g_aoh); GSA(aol,g_aol); GSA(hh,g_hh); GSA(hl,g_hl);
    GSA(wqh,g_wqh); GSA(wql,g_wql); GSA(wmh,g_wmh); GSA(wml,g_wml);
    GSA(w1h,g_w1h); GSA(w1l,g_w1l); GSA(w2h,g_w2h); GSA(w2l,g_w2l);
    GSA(fph,g_fph); GSA(fpl,g_fpl); GSA(pbp,g_pbp); GSA(cs,g_cs);
    GSA(bnS,g_bnS); GSA(bnQ,g_bnQ);
    GSA(pu,g_u); GSA(pvv,g_vv); GSA(ppm,g_pm); GSA(pps,g_ps);
    float *c0=cs, *s0=cs+NN*32, *c1=cs+2*NN*32, *s1=cs+3*NN*32;

    wconv<<<30*65536/256,256>>>(proj_w, wqh, wql, 1, (size_t)30*65536);
    wconv<<<10*65536/256,256>>>(merge_w, wmh, wml, 2, (size_t)10*65536);
    wconv<<<10*262144/256,256>>>(mlp_w1, w1h, w1l, 0, (size_t)10*262144);
    wconv<<<10*131072/256,256>>>(mlp_w2, w2h, w2l, 0, (size_t)10*131072);
    wconv<<<65536/256,256>>>(fp_w, fph, fpl, 0, 65536);
    bias_perm<<<30,256>>>(proj_b, pbp);
    posenc_kernel<<<NN*32/256,256>>>(kpts0, Wr, c0, s0);
    posenc_kernel<<<NN*32/256,256>>>(kpts1, Wr, c1, s1);
    TArgs ta;
    ta.in[0]=desc0; ta.in[1]=desc1;
    for (int s=0;s<2;s++){ ta.xF[s]=xF+s*SZ; ta.yh[s]=yh+s*HSZ; ta.yl[s]=yl+s*HSZ; }
    transpose_split<<<dim3(64,8,2),256>>>(ta);

    for (int l=0; l<10; l++) {
        int even = !(l&1);
        int src[2] = { even?0:1, even?1:0 };
        const float* mb  = merge_b + l*256;
        const float* b1  = mlp_b1 + l*512;
        const float* b2  = mlp_b2 + l*256;
        const float* csv[2] = { c0, c1 };
        const float* snv[2] = { s0, s1 };

        // q,k projections with fused RoPE+split
        MArgs mq = {};
        mq.lda=512; mq.ldb=256; mq.ldo=256; mq.ldh=256; mq.K=256; mq.Nc=256; mq.scale=1.f;
        for (int s=0;s<2;s++) {
            MZ* zq=&mq.z[s*2], *zk=&mq.z[s*2+1];
            zq->Ah=yh+s*HSZ; zq->Al=yl+s*HSZ;
            zq->Bh=wqh+(size_t)(l*3)*65536; zq->Bl=wql+(size_t)(l*3)*65536;
            zq->bias=pbp+(l*3)*256; zq->oh=qh+s*SZ; zq->ol=ql+s*SZ;
            zk->Ah=yh+src[s]*HSZ; zk->Al=yl+src[s]*HSZ;
            zk->Bh=wqh+(size_t)(l*3+1)*65536; zk->Bl=wql+(size_t)(l*3+1)*65536;
            zk->bias=pbp+(l*3+1)*256; zk->oh=kh+s*SZ; zk->ol=kl+s*SZ;
            if (even) {
                zq->cosv=csv[s]; zq->sinv=snv[s];
                zk->cosv=csv[s]; zk->sinv=snv[s];
            }
        }
        mma_gemm<4><<<dim3(16,2,4),256,SMEMB4>>>(mq);

        // v projection (transposed out) — JT=2 full-grid
        MArgs mv = {};
        mv.lda=256; mv.ldb=512; mv.ldo=2048; mv.ldh=2048; mv.K=256; mv.Nc=2048;
        mv.scale=1.f; mv.bias_rows=1;
        for (int s=0;s<2;s++) {
            MZ* zv=&mv.z[s];
            zv->Ah=wqh+(size_t)(l*3+2)*65536; zv->Al=wql+(size_t)(l*3+2)*65536;
            zv->Bh=yh+src[s]*HSZ; zv->Bl=yl+src[s]*HSZ;
            zv->bias=pbp+(l*3+2)*256; zv->oh=vh+s*SZ; zv->ol=vl+s*SZ;
        }
        mma_gemm<2><<<dim3(2,32,2),256,SMEMB2>>>(mv);

        // fused attention (PV single-term; Vl unused)
        flash_attn<<<dim3(16,8),256,FSMEM_B>>>(qh,ql,kh,kl,vh,aoh,aol);

        // merge -> y cols 256:511 — JT=2
        MArgs mm = {};
        mm.lda=256; mm.ldb=256; mm.ldh=512; mm.K=256; mm.Nc=256; mm.scale=1.f;
        for (int s=0;s<2;s++) {
            MZ* zz=&mm.z[s];
            zz->Ah=aoh+s*SZ; zz->Al=aol+s*SZ;
            zz->Bh=wmh+(size_t)l*65536; zz->Bl=wml+(size_t)l*65536;
            zz->bias=mb; zz->oh=yh+s*HSZ+256; zz->ol=yl+s*HSZ+256;
        }
        mma_gemm<2><<<dim3(16,4,2),256,SMEMB2>>>(mm);

        // mlp1 -> h fp32
        MArgs m1 = {};
        m1.lda=512; m1.ldb=512; m1.ldo=512; m1.K=512; m1.Nc=512; m1.scale=1.f;
        for (int s=0;s<2;s++) {
            MZ* zz=&m1.z[s];
            zz->Ah=yh+s*HSZ; zz->Al=yl+s*HSZ;
            zz->Bh=w1h+(size_t)l*262144; zz->Bl=w1l+(size_t)l*262144;
            zz->bias=b1; zz->outF=hf+s*HSZ;
        }
        mma_gemm<4><<<dim3(16,4,2),256,SMEMB4>>>(m1);
        bn_stats<<<dim3(8,16,2),256>>>(hf, bnS, bnQ);
        bn_apply<<<dim3(8,16,2),256>>>(hf, bnS, bnQ, bn_g+l*512, bn_b+l*512, hh, hl);

        // mlp2 + residual — JT=2
        MArgs m2 = {};
        m2.lda=512; m2.ldb=512; m2.ldo=256; m2.ldh=512; m2.K=512; m2.Nc=256; m2.scale=1.f;
        for (int s=0;s<2;s++) {
            MZ* zz=&m2.z[s];
            zz->Ah=hh+s*HSZ; zz->Al=hl+s*HSZ;
            zz->Bh=w2h+(size_t)l*131072; zz->Bl=w2l+(size_t)l*131072;
            zz->bias=b2; zz->res=xF+s*SZ; zz->outF=xF+s*SZ;
            zz->oh=yh+s*HSZ; zz->ol=yl+s*HSZ;
        }
        mma_gemm<2><<<dim3(16,4,2),256,SMEMB2>>>(m2);
    }

    // final projection — JT=2
    MArgs mf = {};
    mf.lda=512; mf.ldb=256; mf.ldh=256; mf.K=256; mf.Nc=256; mf.scale=1.f;
    for (int s=0;s<2;s++) {
        MZ* zz=&mf.z[s];
        zz->Ah=yh+s*HSZ; zz->Al=yl+s*HSZ;
        zz->Bh=fph; zz->Bl=fpl;
        zz->bias=fp_b; zz->oh=qh+s*SZ; zz->ol=ql+s*SZ;
    }
    mma_gemm<2><<<dim3(16,4,2),256,SMEMB2>>>(mf);

    // final match scores into C (ld 2049)
    MArgs mc = {};
    mc.lda=256; mc.ldb=256; mc.ldo=NP1; mc.K=256; mc.Nc=2048; mc.scale=0.0625f;
    mc.z[0].Ah=qh; mc.z[0].Al=ql; mc.z[0].Bh=qh+SZ; mc.z[0].Bl=ql+SZ;
    mc.z[0].outF=C;
    mma_gemm<4><<<dim3(16,16,1),256,SMEMB4>>>(mc);
    bins_kernel<<<(NP1+255)/256,256>>>(C, binsc);

    zero_kernel<<<(NP1+255)/256,256>>>(pvv, NP1);
    for (int t=0; t<20; t++) {
        u_update_kernel<<<NP1,256>>>(C, pvv, pu);
        v_part_kernel<<<dim3((NP1+255)/256,16),256>>>(C, pu, ppm, pps);
        v_combine_kernel<<<(NP1+255)/256,256>>>(ppm, pps, pvv);
    }
    final_add_kernel<<<(NP1*NP1+255)/256,256>>>(C, pu, pvv);
}